// round 2
// baseline (speedup 1.0000x reference)
#include <cuda_runtime.h>

// ---------------------------------------------------------------------------
// MultiGVPConvLayer fused implementation, v2: dst-sorted edges + run-
// accumulated scatter (atomics reduced ~7x and hidden under FMA).
//   Output: concat( out_s [N,128], out_v [N,48] ) float32
// ---------------------------------------------------------------------------

#define NMAX 50000
#define EMAX 800000
#define TE 128

// scratch (static device globals: no runtime allocation allowed)
__device__ float g_agg[(size_t)NMAX * 176];   // per-node [128 scalar | 48 vector] SUM accumulators
__device__ int   g_cnti[NMAX];                // in-degree counts
__device__ int   g_off[NMAX];                 // CSR offsets
__device__ int   g_cur[NMAX];                 // scatter cursors
__device__ int   g_perm[EMAX];                // edge ids sorted by dst
__device__ float g_wesT[32 * 128];            // wes transposed  [k][out]
__device__ float g_wST[128 * 256];            // [k][ wns_out(128) | wrs_out(128) ]
__device__ float g_wVT[48 * 96];              // [k][ wnv_out(48) | wrv_out(48) ]

__device__ __forceinline__ float sigf(float x) { return 1.f / (1.f + __expf(-x)); }

__device__ __forceinline__ void red4(float* p, float4 v) {
    asm volatile("red.global.add.v4.f32 [%0], {%1,%2,%3,%4};"
                 :: "l"(p), "f"(v.x), "f"(v.y), "f"(v.z), "f"(v.w) : "memory");
}

// ---------------------------------------------------------------------------
__global__ void prep_kernel(const float* __restrict__ wes,
                            const float* __restrict__ wns, const float* __restrict__ wrs,
                            const float* __restrict__ wnv, const float* __restrict__ wrv)
{
    int t = blockIdx.x * 256 + threadIdx.x;
    if (t < 128 * 32) { int o = t >> 5, k = t & 31;  g_wesT[k * 128 + o] = wes[t]; }
    if (t < 128 * 128){ int o = t >> 7, k = t & 127; g_wST[k * 256 + o] = wns[t];
                                                     g_wST[k * 256 + 128 + o] = wrs[t]; }
    if (t < 48 * 48)  { int o = t / 48, k = t % 48;  g_wVT[k * 96 + o] = wnv[t];
                                                     g_wVT[k * 96 + 48 + o] = wrv[t]; }
}

// ---------------------------------------------------------------------------
__global__ void hist_kernel(const int* __restrict__ ei, int E)
{
    int e = blockIdx.x * 256 + threadIdx.x;
    if (e < E) atomicAdd(&g_cnti[ei[E + e]], 1);
}

// single-block exclusive scan of g_cnti -> g_off, g_cur (4 elems/thread)
__global__ __launch_bounds__(1024) void scan_kernel(int Nn)
{
    __shared__ int wsum[32];
    __shared__ int s_running;
    int t = threadIdx.x, lane = t & 31, wid = t >> 5;
    if (t == 0) s_running = 0;
    __syncthreads();

    for (int base = 0; base < Nn; base += 4096) {
        int idx = base + t * 4;
        int v[4];
#pragma unroll
        for (int i = 0; i < 4; i++) v[i] = (idx + i < Nn) ? g_cnti[idx + i] : 0;
        int tot = v[0] + v[1] + v[2] + v[3];
        int x = tot;
#pragma unroll
        for (int o = 1; o < 32; o <<= 1) {
            int y = __shfl_up_sync(0xffffffffu, x, o);
            if (lane >= o) x += y;
        }
        if (lane == 31) wsum[wid] = x;
        __syncthreads();
        if (wid == 0) {
            int w = wsum[lane];
            int xs = w;
#pragma unroll
            for (int o = 1; o < 32; o <<= 1) {
                int y = __shfl_up_sync(0xffffffffu, xs, o);
                if (lane >= o) xs += y;
            }
            wsum[lane] = xs - w;   // exclusive warp-sum prefix
        }
        __syncthreads();
        int excl = s_running + wsum[wid] + (x - tot);
        int run = excl;
#pragma unroll
        for (int i = 0; i < 4; i++) {
            if (idx + i < Nn) { g_off[idx + i] = run; g_cur[idx + i] = run; }
            run += v[i];
        }
        __syncthreads();
        if (t == 1023) s_running = excl + tot;
        __syncthreads();
    }
}

__global__ void perm_kernel(const int* __restrict__ ei, int E)
{
    int e = blockIdx.x * 256 + threadIdx.x;
    if (e < E) {
        int d = ei[E + e];
        int slot = atomicAdd(&g_cur[d], 1);
        g_perm[slot] = e;
    }
}

// ---------------------------------------------------------------------------
// Edge kernel: edge GVP on dst-sorted edges + run-accumulated scatter.
// 128 edges per block, 256 threads. Warp wg handles 16 consecutive slots.
// ---------------------------------------------------------------------------
__global__ __launch_bounds__(256) void edge_kernel(
    const float* __restrict__ edge_s, const float* __restrict__ edge_v,
    const int* __restrict__ edge_index,
    const float* __restrict__ bes, const float* __restrict__ wev,
    const float* __restrict__ bev, int E)
{
    __shared__ float4 wsh[32 * 32];        // wesT as float4 [k][32]
    __shared__ float  es_sh[TE * 32];
    __shared__ float  ev_sh[TE * 3];
    __shared__ int    eid_sh[TE];
    __shared__ int    dst_sh[TE];
    __shared__ float  gate_sh[TE * 16];
    __shared__ float  bes_sh[128];
    __shared__ float  wev_sh[144];
    __shared__ float  bev_sh[48];

    const int tid = threadIdx.x;
    const int e0  = blockIdx.x * TE;
    const int nE  = min(TE, E - e0);

    // stage 1: permuted edge ids + dst node ids; weights in parallel
    if (tid < TE) {
        int e = (tid < nE) ? g_perm[e0 + tid] : -1;
        eid_sh[tid] = e;
        dst_sh[tid] = (e >= 0) ? edge_index[E + e] : -1;
    }
    {
        const float4* w4 = (const float4*)g_wesT;
        for (int i = tid; i < 1024; i += 256) wsh[i] = w4[i];
    }
    if (tid < 128) bes_sh[tid] = bes[tid];
    if (tid < 144) wev_sh[tid] = wev[tid];
    if (tid < 48)  bev_sh[tid] = bev[tid];
    __syncthreads();

    // stage 2: gather edge features (each edge_s row = one 128B line)
    {
        const float4* s4 = (const float4*)edge_s;
        float4* d4 = (float4*)es_sh;
        for (int i = tid; i < TE * 8; i += 256) {
            int e = eid_sh[i >> 3];
            d4[i] = (e >= 0) ? s4[(size_t)e * 8 + (i & 7)]
                             : make_float4(0.f, 0.f, 0.f, 0.f);
        }
    }
    for (int i = tid; i < TE * 3; i += 256) {
        int e = eid_sh[i / 3];
        ev_sh[i] = (e >= 0) ? edge_v[(size_t)e * 3 + (i % 3)] : 0.f;
    }
    __syncthreads();

    const int tx = tid & 31;
    const int wg = tid >> 5;

    // register-blocked GEMV: 16 edges per warp, lane covers outputs 4tx..4tx+3
    float4 acc[16];
#pragma unroll
    for (int j = 0; j < 16; j++) acc[j] = make_float4(0.f, 0.f, 0.f, 0.f);

#pragma unroll 4
    for (int k = 0; k < 32; k++) {
        float4 w = wsh[k * 32 + tx];
#pragma unroll
        for (int j = 0; j < 16; j++) {
            float e = es_sh[(wg * 16 + j) * 32 + k];   // warp-uniform broadcast
            acc[j].x = fmaf(w.x, e, acc[j].x);
            acc[j].y = fmaf(w.y, e, acc[j].y);
            acc[j].z = fmaf(w.z, e, acc[j].z);
            acc[j].w = fmaf(w.w, e, acc[j].w);
        }
    }

    // epilogue: silu + gate + run-accumulated scatter (edges sorted by dst)
    {
        const float4 bb = ((const float4*)bes_sh)[tx];
        float4 racc = make_float4(0.f, 0.f, 0.f, 0.f);
        int cur = -1;
#pragma unroll
        for (int j = 0; j < 16; j++) {
            int el = wg * 16 + j;
            int node = dst_sh[el];
            if (node != cur) {
                if (cur >= 0) red4(g_agg + (size_t)cur * 176 + 4 * tx, racc);
                racc = make_float4(0.f, 0.f, 0.f, 0.f);
                cur = node;
            }
            if (node >= 0) {
                float4 s = acc[j];
                s.x += bb.x; s.y += bb.y; s.z += bb.z; s.w += bb.w;
                s.x *= sigf(s.x); s.y *= sigf(s.y);
                s.z *= sigf(s.z); s.w *= sigf(s.w);      // silu
                if (tx < 4) {                             // gate = sigmoid(silu)[0:16]
                    gate_sh[el * 16 + 4 * tx + 0] = sigf(s.x);
                    gate_sh[el * 16 + 4 * tx + 1] = sigf(s.y);
                    gate_sh[el * 16 + 4 * tx + 2] = sigf(s.z);
                    gate_sh[el * 16 + 4 * tx + 3] = sigf(s.w);
                }
                racc.x += s.x; racc.y += s.y; racc.z += s.z; racc.w += s.w;
            }
        }
        if (cur >= 0) red4(g_agg + (size_t)cur * 176 + 4 * tx, racc);
    }
    __syncthreads();

    // vector part: thread handles quad q over 8 consecutive edges (run-accum)
    if (tid < 192) {
        const int q   = tid >> 4;          // 0..11  (outputs 4q..4q+3)
        const int el0 = (tid & 15) * 8;    // 8 consecutive slots
        float w0[4], w1[4], w2[4], bq[4];
#pragma unroll
        for (int i = 0; i < 4; i++) {
            int o = 4 * q + i;
            w0[i] = wev_sh[o * 3 + 0]; w1[i] = wev_sh[o * 3 + 1];
            w2[i] = wev_sh[o * 3 + 2]; bq[i] = bev_sh[o];
        }
        float4 racc = make_float4(0.f, 0.f, 0.f, 0.f);
        int cur = -1;
#pragma unroll
        for (int j = 0; j < 8; j++) {
            int el = el0 + j;
            int node = dst_sh[el];
            if (node != cur) {
                if (cur >= 0) red4(g_agg + (size_t)cur * 176 + 128 + 4 * q, racc);
                racc = make_float4(0.f, 0.f, 0.f, 0.f);
                cur = node;
            }
            if (node >= 0) {
                float e0v = ev_sh[el * 3 + 0], e1v = ev_sh[el * 3 + 1], e2v = ev_sh[el * 3 + 2];
                float* rp = (float*)&racc;
#pragma unroll
                for (int i = 0; i < 4; i++) {
                    int o = 4 * q + i;
                    float val = fmaf(w0[i], e0v, fmaf(w1[i], e1v, fmaf(w2[i], e2v, bq[i])));
                    rp[i] += val * gate_sh[el * 16 + o / 3];
                }
            }
        }
        if (cur >= 0) red4(g_agg + (size_t)cur * 176 + 128 + 4 * q, racc);
    }
}

// ---------------------------------------------------------------------------
// Node kernel: LN + vnorm + scatter-mean consume + node GVP + residuals.
// ---------------------------------------------------------------------------
#define NODE_SMEM_FLOATS 50400

__global__ __launch_bounds__(256) void node_kernel(
    const float* __restrict__ node_s, const float* __restrict__ node_v,
    const float* __restrict__ ln_g, const float* __restrict__ ln_b,
    const float* __restrict__ bns, const float* __restrict__ brs,
    const float* __restrict__ bnv, const float* __restrict__ brv,
    float* __restrict__ out, int Nn)
{
    extern __shared__ float sm[];
    float* wST  = sm;                 // 32768
    float* wVT  = wST + 32768;        // 4608
    float* sn   = wVT + 4608;         // 4096  (raw -> s_n -> res_s)
    float* xs   = sn + 4096;          // 4096  (x_s  -> silu(out_pre))
    float* vn   = xs + 4096;          // 1536  (raw -> v_n)
    float* xv   = vn + 1536;          // 1536  (x_v)
    float* gate = xv + 1536;          // 512
    float* lng  = gate + 512;         // 128
    float* lnb  = lng + 128;          // 128
    float* bnsS = lnb + 128;          // 128
    float* brsS = bnsS + 128;         // 128
    float* bnvS = brsS + 128;         // 48
    float* brvS = bnvS + 48;          // 48

    const int tid = threadIdx.x;
    const int n0  = blockIdx.x * 32;
    const int nN  = min(32, Nn - n0);

    {
        float4* d = (float4*)wST; const float4* s = (const float4*)g_wST;
        for (int i = tid; i < 8192; i += 256) d[i] = s[i];
    }
    for (int i = tid; i < 4608; i += 256) wVT[i] = g_wVT[i];
    if (tid < 128) { lng[tid] = ln_g[tid]; lnb[tid] = ln_b[tid];
                     bnsS[tid] = bns[tid]; brsS[tid] = brs[tid]; }
    if (tid < 48)  { bnvS[tid] = bnv[tid]; brvS[tid] = brv[tid]; }
    for (int i = tid; i < 4096; i += 256)
        sn[i] = (i < nN * 128) ? node_s[(size_t)n0 * 128 + i] : 0.f;
    for (int i = tid; i < 1536; i += 256)
        vn[i] = (i < nN * 48) ? node_v[(size_t)n0 * 48 + i] : 0.f;
    __syncthreads();

    // --- LayerNorm + vector norm + aggregate consume: warp w -> nodes 4w..4w+3
    const int lane = tid & 31, w = tid >> 5;
    for (int q = 0; q < 4; q++) {
        int r = w * 4 + q;
        int n = n0 + r;
        const float* row = sn + r * 128;
        float a = row[lane] + row[lane + 32] + row[lane + 64] + row[lane + 96];
#pragma unroll
        for (int o = 16; o; o >>= 1) a += __shfl_xor_sync(0xffffffffu, a, o);
        float mu = a * (1.f / 128.f);
        float d0 = row[lane] - mu, d1 = row[lane + 32] - mu;
        float d2 = row[lane + 64] - mu, d3 = row[lane + 96] - mu;
        float vv = d0 * d0 + d1 * d1 + d2 * d2 + d3 * d3;
#pragma unroll
        for (int o = 16; o; o >>= 1) vv += __shfl_xor_sync(0xffffffffu, vv, o);
        float rs = rsqrtf(vv * (1.f / 128.f) + 1e-5f);

        const float* vrow = vn + r * 48;
        float x0 = vrow[lane];
        float x1 = (lane < 16) ? vrow[32 + lane] : 0.f;
        float sq = x0 * x0 + x1 * x1;
#pragma unroll
        for (int o = 16; o; o >>= 1) sq += __shfl_xor_sync(0xffffffffu, sq, o);
        float vr = rsqrtf(sq * (1.f / 16.f) + 1e-8f);

        float invden = 0.f;
        const float* aggr = g_agg + (size_t)n * 176;
        if (r < nN) invden = 1.f / fmaxf((float)g_cnti[n], 1.f);

#pragma unroll
        for (int jj = 0; jj < 4; jj++) {
            int c = lane + 32 * jj;
            float x = (row[c] - mu) * rs * lng[c] + lnb[c];
            sn[r * 128 + c] = x;
            float xa = x;
            if (r < nN) xa = x + aggr[c] * invden;
            xs[r * 128 + c] = xa;
        }
        {
            float x = x0 * vr;
            vn[r * 48 + lane] = x;
            float xa = x;
            if (r < nN) xa = x + aggr[128 + lane] * invden;
            xv[r * 48 + lane] = xa;
            if (lane < 16) {
                float y = x1 * vr;
                vn[r * 48 + 32 + lane] = y;
                float ya = y;
                if (r < nN) ya = y + aggr[128 + 32 + lane] * invden;
                xv[r * 48 + 32 + lane] = ya;
            }
        }
    }
    __syncthreads();

    // --- dual GEMM: [32,128] x [128,256]. og<32 -> wns(x_s), og>=32 -> wrs(s_n)
    const int og = tid & 63;
    const int ng = tid >> 6;
    const float* xin = (og < 32) ? xs : sn;
    const float4* w4 = (const float4*)wST;
    float4 acc[8];
#pragma unroll
    for (int j = 0; j < 8; j++) acc[j] = make_float4(0.f, 0.f, 0.f, 0.f);

#pragma unroll 4
    for (int k = 0; k < 128; k++) {
        float4 wv = w4[k * 64 + og];
#pragma unroll
        for (int j = 0; j < 8; j++) {
            float x = xin[(ng * 8 + j) * 128 + k];
            acc[j].x = fmaf(wv.x, x, acc[j].x);
            acc[j].y = fmaf(wv.y, x, acc[j].y);
            acc[j].z = fmaf(wv.z, x, acc[j].z);
            acc[j].w = fmaf(wv.w, x, acc[j].w);
        }
    }
    __syncthreads();   // everyone done reading xs/sn before we overwrite them

    if (og < 32) {
        float4 b = ((const float4*)bnsS)[og];
#pragma unroll
        for (int j = 0; j < 8; j++) {
            int r = ng * 8 + j;
            float4 s = acc[j];
            s.x += b.x; s.y += b.y; s.z += b.z; s.w += b.w;
            s.x *= sigf(s.x); s.y *= sigf(s.y); s.z *= sigf(s.z); s.w *= sigf(s.w);
            if (og < 4) {
                gate[r * 16 + 4 * og + 0] = sigf(s.x);
                gate[r * 16 + 4 * og + 1] = sigf(s.y);
                gate[r * 16 + 4 * og + 2] = sigf(s.z);
                gate[r * 16 + 4 * og + 3] = sigf(s.w);
            }
            ((float4*)xs)[r * 32 + og] = s;
        }
    } else {
        float4 b = ((const float4*)brsS)[og - 32];
#pragma unroll
        for (int j = 0; j < 8; j++) {
            int r = ng * 8 + j;
            float4 s = acc[j];
            s.x += b.x; s.y += b.y; s.z += b.z; s.w += b.w;
            ((float4*)sn)[r * 32 + (og - 32)] = s;
        }
    }
    __syncthreads();

    // scalar output: silu(out_pre) + residual
    for (int i = tid; i < nN * 128; i += 256)
        out[(size_t)n0 * 128 + i] = xs[i] + sn[i];

    // vector output: (x_v @ wnv^T + bnv) * gate + (v_n @ wrv^T + brv)
    for (int p = tid; p < nN * 48; p += 256) {
        int r = p / 48, o = p % 48;
        const float* xvr = xv + r * 48;
        const float* vnr = vn + r * 48;
        float a = 0.f, bq = 0.f;
#pragma unroll 4
        for (int k = 0; k < 48; k++) {
            a  = fmaf(xvr[k], wVT[k * 96 + o],      a);
            bq = fmaf(vnr[k], wVT[k * 96 + 48 + o], bq);
        }
        float val = (a + bnvS[o]) * gate[r * 16 + o / 3] + bq + brvS[o];
        out[(size_t)Nn * 128 + (size_t)n0 * 48 + p] = val;
    }
}

// ---------------------------------------------------------------------------
extern "C" void kernel_launch(void* const* d_in, const int* in_sizes, int n_in,
                              void* d_out, int out_size)
{
    const float* node_s = (const float*)d_in[0];
    const float* node_v = (const float*)d_in[1];
    const int*   ei     = (const int*)  d_in[2];
    const float* edge_s = (const float*)d_in[3];
    const float* edge_v = (const float*)d_in[4];
    const float* ln_g   = (const float*)d_in[5];
    const float* ln_b   = (const float*)d_in[6];
    const float* wes    = (const float*)d_in[7];
    const float* bes    = (const float*)d_in[8];
    const float* wev    = (const float*)d_in[9];
    const float* bev    = (const float*)d_in[10];
    const float* wns    = (const float*)d_in[11];
    const float* bns    = (const float*)d_in[12];
    const float* wnv    = (const float*)d_in[13];
    const float* bnv    = (const float*)d_in[14];
    const float* wrs    = (const float*)d_in[15];
    const float* brs    = (const float*)d_in[16];
    const float* wrv    = (const float*)d_in[17];
    const float* brv    = (const float*)d_in[18];

    const int N = in_sizes[0] / 128;
    const int E = in_sizes[3] / 32;

    void* aggp; void* cntp;
    cudaGetSymbolAddress(&aggp, g_agg);
    cudaGetSymbolAddress(&cntp, g_cnti);
    cudaMemsetAsync(aggp, 0, (size_t)N * 176 * sizeof(float), 0);
    cudaMemsetAsync(cntp, 0, (size_t)N * sizeof(int), 0);

    cudaFuncSetAttribute(node_kernel, cudaFuncAttributeMaxDynamicSharedMemorySize,
                         NODE_SMEM_FLOATS * sizeof(float));

    prep_kernel<<<64, 256>>>(wes, wns, wrs, wnv, wrv);
    hist_kernel<<<(E + 255) / 256, 256>>>(ei, E);
    scan_kernel<<<1, 1024>>>(N);
    perm_kernel<<<(E + 255) / 256, 256>>>(ei, E);
    edge_kernel<<<(E + TE - 1) / TE, 256>>>(edge_s, edge_v, ei, bes, wev, bev, E);
    node_kernel<<<(N + 31) / 32, 256, NODE_SMEM_FLOATS * sizeof(float)>>>(
        node_s, node_v, ln_g, ln_b, bns, brs, bnv, brv, (float*)d_out, N);
}

// round 4
// speedup vs baseline: 1.0356x; 1.0356x over previous
#include <cuda_runtime.h>

// ---------------------------------------------------------------------------
// MultiGVPConvLayer fused, v4: CSR materialize-then-pull (zero float atomics).
//   prepA, prepB, hist, scan, slot, edge (captured by ncu), node
//   Output: concat( out_s [N,128], out_v [N,48] ) float32
// ---------------------------------------------------------------------------

#define NMAX 50000
#define EMAX 800000
#define TE 64

__device__ float g_ec[(size_t)EMAX * 176];    // edge GVP outputs, CSR-ordered by dst
__device__ int   g_slot[EMAX];                // CSR slot per edge
__device__ int   g_cnti[NMAX];                // in-degree
__device__ int   g_off[NMAX];                 // CSR offsets
__device__ int   g_cur[NMAX];                 // cursors
__device__ float g_wesT[32 * 128];            // wes transposed  [k][out]
__device__ float g_wST[128 * 256];            // [k][ wns_out | wrs_out ]
__device__ float g_wVT[48 * 96];              // [k][ wnv_out | wrv_out ]

__device__ __forceinline__ float sigf(float x) { return 1.f / (1.f + __expf(-x)); }
__device__ __forceinline__ void f4add(float4& a, const float4 b) {
    a.x += b.x; a.y += b.y; a.z += b.z; a.w += b.w;
}

// ---------------------------------------------------------------------------
__global__ void prepA_kernel(const float* __restrict__ wes, int Nn)
{
    int t = blockIdx.x * 256 + threadIdx.x;
    if (t < 128 * 32) { int o = t >> 5, k = t & 31; g_wesT[k * 128 + o] = wes[t]; }
    if (t < Nn) g_cnti[t] = 0;
}

__global__ void prepB_kernel(const float* __restrict__ wns, const float* __restrict__ wrs,
                             const float* __restrict__ wnv, const float* __restrict__ wrv)
{
    int t = blockIdx.x * 256 + threadIdx.x;
    if (t < 128 * 128){ int o = t >> 7, k = t & 127; g_wST[k * 256 + o] = wns[t];
                                                     g_wST[k * 256 + 128 + o] = wrs[t]; }
    if (t < 48 * 48)  { int o = t / 48, k = t % 48;  g_wVT[k * 96 + o] = wnv[t];
                                                     g_wVT[k * 96 + 48 + o] = wrv[t]; }
}

__global__ void hist_kernel(const int* __restrict__ ei, int E)
{
    int e = blockIdx.x * 256 + threadIdx.x;
    if (e < E) atomicAdd(&g_cnti[ei[E + e]], 1);
}

// single-block exclusive scan of g_cnti -> g_off, g_cur
__global__ __launch_bounds__(1024) void scan_kernel(int Nn)
{
    __shared__ int wsum[32];
    __shared__ int s_running;
    int t = threadIdx.x, lane = t & 31, wid = t >> 5;
    if (t == 0) s_running = 0;
    __syncthreads();

    for (int base = 0; base < Nn; base += 4096) {
        int idx = base + t * 4;
        int v[4];
#pragma unroll
        for (int i = 0; i < 4; i++) v[i] = (idx + i < Nn) ? g_cnti[idx + i] : 0;
        int tot = v[0] + v[1] + v[2] + v[3];
        int x = tot;
#pragma unroll
        for (int o = 1; o < 32; o <<= 1) {
            int y = __shfl_up_sync(0xffffffffu, x, o);
            if (lane >= o) x += y;
        }
        if (lane == 31) wsum[wid] = x;
        __syncthreads();
        if (wid == 0) {
            int w = wsum[lane];
            int xs = w;
#pragma unroll
            for (int o = 1; o < 32; o <<= 1) {
                int y = __shfl_up_sync(0xffffffffu, xs, o);
                if (lane >= o) xs += y;
            }
            wsum[lane] = xs - w;
        }
        __syncthreads();
        int excl = s_running + wsum[wid] + (x - tot);
        int run = excl;
#pragma unroll
        for (int i = 0; i < 4; i++) {
            if (idx + i < Nn) { g_off[idx + i] = run; g_cur[idx + i] = run; }
            run += v[i];
        }
        __syncthreads();
        if (t == 1023) s_running = excl + tot;
        __syncthreads();
    }
}

__global__ void slot_kernel(const int* __restrict__ ei, int E)
{
    int e = blockIdx.x * 256 + threadIdx.x;
    if (e < E) g_slot[e] = atomicAdd(&g_cur[ei[E + e]], 1);
}

// ---------------------------------------------------------------------------
// Edge kernel: v1 streaming GEMV, results stored to g_ec[slot] (no atomics).
// 64 edges / 256 threads per block; warp handles 8 edges, lane = 4 outputs.
// ---------------------------------------------------------------------------
__global__ __launch_bounds__(256) void edge_kernel(
    const float* __restrict__ edge_s, const float* __restrict__ edge_v,
    const float* __restrict__ bes, const float* __restrict__ wev,
    const float* __restrict__ bev, int E)
{
    __shared__ float4 wsh[32 * 32];        // wesT as float4 [k][32]
    __shared__ float  es_sh[TE * 32];
    __shared__ float  ev_sh[TE * 3];
    __shared__ int    slot_sh[TE];
    __shared__ float  gate_sh[TE * 16];
    __shared__ float  bes_sh[128];
    __shared__ float  wev_sh[144];
    __shared__ float  bev_sh[48];

    const int tid = threadIdx.x;
    const int e0  = blockIdx.x * TE;
    const int nE  = min(TE, E - e0);

    {
        const float4* w4 = (const float4*)g_wesT;
        for (int i = tid; i < 1024; i += 256) wsh[i] = w4[i];
    }
    {
        const float4* s4 = (const float4*)(edge_s + (size_t)e0 * 32);
        float4* d4 = (float4*)es_sh;
        for (int i = tid; i < TE * 8; i += 256)
            if ((i >> 3) < nE) d4[i] = s4[i];
    }
    if (tid < TE * 3) { int e = tid / 3; ev_sh[tid] = (e < nE) ? edge_v[(size_t)e0 * 3 + tid] : 0.f; }
    if (tid < TE)     slot_sh[tid] = (tid < nE) ? g_slot[e0 + tid] : -1;
    if (tid < 128)    bes_sh[tid] = bes[tid];
    if (tid < 144)    wev_sh[tid] = wev[tid];
    if (tid < 48)     bev_sh[tid] = bev[tid];
    __syncthreads();

    const int tx = tid & 31;
    const int wg = tid >> 5;

    float4 acc[8];
#pragma unroll
    for (int j = 0; j < 8; j++) acc[j] = make_float4(0.f, 0.f, 0.f, 0.f);

#pragma unroll 4
    for (int k = 0; k < 32; k++) {
        float4 w = wsh[k * 32 + tx];
#pragma unroll
        for (int j = 0; j < 8; j++) {
            float e = es_sh[(wg * 8 + j) * 32 + k];    // warp-uniform broadcast
            acc[j].x = fmaf(w.x, e, acc[j].x);
            acc[j].y = fmaf(w.y, e, acc[j].y);
            acc[j].z = fmaf(w.z, e, acc[j].z);
            acc[j].w = fmaf(w.w, e, acc[j].w);
        }
    }

    const float4 bb = ((const float4*)bes_sh)[tx];
#pragma unroll
    for (int j = 0; j < 8; j++) {
        int el = wg * 8 + j;
        if (el >= nE) break;
        int slot = slot_sh[el];
        float4 s;
        s.x = acc[j].x + bb.x; s.y = acc[j].y + bb.y;
        s.z = acc[j].z + bb.z; s.w = acc[j].w + bb.w;
        s.x *= sigf(s.x); s.y *= sigf(s.y); s.z *= sigf(s.z); s.w *= sigf(s.w); // silu
        if (tx < 4) {  // gate = sigmoid(silu(out)[:16])
            gate_sh[el * 16 + 4 * tx + 0] = sigf(s.x);
            gate_sh[el * 16 + 4 * tx + 1] = sigf(s.y);
            gate_sh[el * 16 + 4 * tx + 2] = sigf(s.z);
            gate_sh[el * 16 + 4 * tx + 3] = sigf(s.w);
        }
        *(float4*)(g_ec + (size_t)slot * 176 + 4 * tx) = s;   // coalesced 512B
    }
    __syncthreads();

    // vector part: 12 float4-quads per edge (48 outputs)
    for (int p = tid; p < TE * 12; p += 256) {
        int el = p / 12;
        if (el >= nE) continue;
        int q = p % 12;
        int slot = slot_sh[el];
        float e0v = ev_sh[el * 3 + 0], e1v = ev_sh[el * 3 + 1], e2v = ev_sh[el * 3 + 2];
        float4 v; float* vp = (float*)&v;
#pragma unroll
        for (int i = 0; i < 4; i++) {
            int o = 4 * q + i;
            float val = fmaf(wev_sh[o * 3 + 0], e0v,
                        fmaf(wev_sh[o * 3 + 1], e1v,
                        fmaf(wev_sh[o * 3 + 2], e2v, bev_sh[o])));
            vp[i] = val * gate_sh[el * 16 + o / 3];
        }
        *(float4*)(g_ec + (size_t)slot * 176 + 128 + 4 * q) = v;
    }
}

// ---------------------------------------------------------------------------
// Node kernel: CSR pull-aggregation + LN + vnorm + node GVP + residuals.
// ---------------------------------------------------------------------------
#define NODE_SMEM_FLOATS 50400

__global__ __launch_bounds__(256) void node_kernel(
    const float* __restrict__ node_s, const float* __restrict__ node_v,
    const float* __restrict__ ln_g, const float* __restrict__ ln_b,
    const float* __restrict__ bns, const float* __restrict__ brs,
    const float* __restrict__ bnv, const float* __restrict__ brv,
    float* __restrict__ out, int Nn)
{
    extern __shared__ float smf[];
    float* wST  = smf;                // 32768
    float* wVT  = wST + 32768;        // 4608
    float* sn   = wVT + 4608;         // 4096
    float* xs   = sn + 4096;          // 4096  (agg -> x_s -> silu(out_pre))
    float* vn   = xs + 4096;          // 1536
    float* xv   = vn + 1536;          // 1536  (agg -> x_v)
    float* gate = xv + 1536;          // 512
    float* lng  = gate + 512;
    float* lnb  = lng + 128;
    float* bnsS = lnb + 128;
    float* brsS = bnsS + 128;
    float* bnvS = brsS + 128;
    float* brvS = bnvS + 48;

    const int tid = threadIdx.x;
    const int n0  = blockIdx.x * 32;
    const int nN  = min(32, Nn - n0);

    {
        float4* d = (float4*)wST; const float4* s = (const float4*)g_wST;
        for (int i = tid; i < 8192; i += 256) d[i] = s[i];
    }
    for (int i = tid; i < 4608; i += 256) wVT[i] = g_wVT[i];
    if (tid < 128) { lng[tid] = ln_g[tid]; lnb[tid] = ln_b[tid];
                     bnsS[tid] = bns[tid]; brsS[tid] = brs[tid]; }
    if (tid < 48)  { bnvS[tid] = bnv[tid]; brvS[tid] = brv[tid]; }
    for (int i = tid; i < 4096; i += 256)
        sn[i] = (i < nN * 128) ? node_s[(size_t)n0 * 128 + i] : 0.f;
    for (int i = tid; i < 1536; i += 256)
        vn[i] = (i < nN * 48) ? node_v[(size_t)n0 * 48 + i] : 0.f;
    __syncthreads();

    // --- per warp: 4 nodes. CSR pull-aggregate, then LN/vnorm/combine.
    const int lane = tid & 31, w = tid >> 5;
    const float4 zf4 = make_float4(0.f, 0.f, 0.f, 0.f);
    for (int q = 0; q < 4; q++) {
        int r = w * 4 + q;
        int n = n0 + r;

        // ---- aggregation: sum deg rows of 44 float4 each (streaming reads)
        int off = 0, deg = 0;
        if (r < nN) { off = g_off[n]; deg = g_cnti[n]; }
        {
            const float4* base = ((const float4*)g_ec) + (size_t)off * 44;
            float4 a0 = zf4, a1 = zf4, c0 = zf4, c1 = zf4;
            int e = 0;
            for (; e + 4 <= deg; e += 4) {
                const float4* r0 = base + (size_t)e * 44;
                float4 p0 = r0[lane];
                float4 p1 = r0[44 + lane];
                float4 p2 = r0[88 + lane];
                float4 p3 = r0[132 + lane];
                f4add(a0, p0); f4add(c0, p1); f4add(a0, p2); f4add(c0, p3);
                if (lane < 12) {
                    float4 q0 = r0[32 + lane];
                    float4 q1 = r0[76 + lane];
                    float4 q2 = r0[120 + lane];
                    float4 q3 = r0[164 + lane];
                    f4add(a1, q0); f4add(c1, q1); f4add(a1, q2); f4add(c1, q3);
                }
            }
            for (; e < deg; e++) {
                const float4* r0 = base + (size_t)e * 44;
                f4add(a0, r0[lane]);
                if (lane < 12) f4add(a1, r0[32 + lane]);
            }
            f4add(a0, c0); f4add(a1, c1);
            if (r < nN) {
                ((float4*)(xs + r * 128))[lane] = a0;          // stage agg_s
                if (lane < 12) ((float4*)(xv + r * 48))[lane] = a1;  // stage agg_v
            }
        }
        __syncwarp();

        // ---- LayerNorm + vector norm + combine
        const float* row = sn + r * 128;
        float a = row[lane] + row[lane + 32] + row[lane + 64] + row[lane + 96];
#pragma unroll
        for (int o = 16; o; o >>= 1) a += __shfl_xor_sync(0xffffffffu, a, o);
        float mu = a * (1.f / 128.f);
        float d0 = row[lane] - mu, d1 = row[lane + 32] - mu;
        float d2 = row[lane + 64] - mu, d3 = row[lane + 96] - mu;
        float vv = d0 * d0 + d1 * d1 + d2 * d2 + d3 * d3;
#pragma unroll
        for (int o = 16; o; o >>= 1) vv += __shfl_xor_sync(0xffffffffu, vv, o);
        float rs = rsqrtf(vv * (1.f / 128.f) + 1e-5f);

        const float* vrow = vn + r * 48;
        float x0 = vrow[lane];
        float x1 = (lane < 16) ? vrow[32 + lane] : 0.f;
        float sq = x0 * x0 + x1 * x1;
#pragma unroll
        for (int o = 16; o; o >>= 1) sq += __shfl_xor_sync(0xffffffffu, sq, o);
        float vr = rsqrtf(sq * (1.f / 16.f) + 1e-8f);

        float invden = (r < nN) ? 1.f / fmaxf((float)deg, 1.f) : 0.f;

#pragma unroll
        for (int jj = 0; jj < 4; jj++) {
            int c = lane + 32 * jj;
            float x = (row[c] - mu) * rs * lng[c] + lnb[c];
            float xa = x;
            if (r < nN) xa = x + xs[r * 128 + c] * invden;
            sn[r * 128 + c] = x;
            xs[r * 128 + c] = xa;
        }
        {
            float x = x0 * vr;
            float xa = x;
            if (r < nN) xa = x + xv[r * 48 + lane] * invden;
            vn[r * 48 + lane] = x;
            xv[r * 48 + lane] = xa;
            if (lane < 16) {
                float y = x1 * vr;
                float ya = y;
                if (r < nN) ya = y + xv[r * 48 + 32 + lane] * invden;
                vn[r * 48 + 32 + lane] = y;
                xv[r * 48 + 32 + lane] = ya;
            }
        }
    }
    __syncthreads();

    // --- dual GEMM: [32,128] x [128,256]. og<32 -> wns(x_s), og>=32 -> wrs(s_n)
    const int og = tid & 63;
    const int ng = tid >> 6;
    const float* xin = (og < 32) ? xs : sn;
    const float4* w4 = (const float4*)wST;
    float4 acc[8];
#pragma unroll
    for (int j = 0; j < 8; j++) acc[j] = make_float4(0.f, 0.f, 0.f, 0.f);

#pragma unroll 4
    for (int k = 0; k < 128; k++) {
        float4 wv = w4[k * 64 + og];
#pragma unroll
        for (int j = 0; j < 8; j++) {
            float x = xin[(ng * 8 + j) * 128 + k];
            acc[j].x = fmaf(wv.x, x, acc[j].x);
            acc[j].y = fmaf(wv.y, x, acc[j].y);
            acc[j].z = fmaf(wv.z, x, acc[j].z);
            acc[j].w = fmaf(wv.w, x, acc[j].w);
        }
    }
    __syncthreads();

    if (og < 32) {
        float4 b = ((const float4*)bnsS)[og];
#pragma unroll
        for (int j = 0; j < 8; j++) {
            int r = ng * 8 + j;
            float4 s = acc[j];
            s.x += b.x; s.y += b.y; s.z += b.z; s.w += b.w;
            s.x *= sigf(s.x); s.y *= sigf(s.y); s.z *= sigf(s.z); s.w *= sigf(s.w);
            if (og < 4) {
                gate[r * 16 + 4 * og + 0] = sigf(s.x);
                gate[r * 16 + 4 * og + 1] = sigf(s.y);
                gate[r * 16 + 4 * og + 2] = sigf(s.z);
                gate[r * 16 + 4 * og + 3] = sigf(s.w);
            }
            ((float4*)xs)[r * 32 + og] = s;
        }
    } else {
        float4 b = ((const float4*)brsS)[og - 32];
#pragma unroll
        for (int j = 0; j < 8; j++) {
            int r = ng * 8 + j;
            float4 s = acc[j];
            s.x += b.x; s.y += b.y; s.z += b.z; s.w += b.w;
            ((float4*)sn)[r * 32 + (og - 32)] = s;
        }
    }
    __syncthreads();

    for (int i = tid; i < nN * 128; i += 256)
        out[(size_t)n0 * 128 + i] = xs[i] + sn[i];

    for (int p = tid; p < nN * 48; p += 256) {
        int r = p / 48, o = p % 48;
        const float* xvr = xv + r * 48;
        const float* vnr = vn + r * 48;
        float a = 0.f, bq = 0.f;
#pragma unroll 4
        for (int k = 0; k < 48; k++) {
            a  = fmaf(xvr[k], wVT[k * 96 + o],      a);
            bq = fmaf(vnr[k], wVT[k * 96 + 48 + o], bq);
        }
        float val = (a + bnvS[o]) * gate[r * 16 + o / 3] + bq + brvS[o];
        out[(size_t)Nn * 128 + (size_t)n0 * 48 + p] = val;
    }
}

// ---------------------------------------------------------------------------
extern "C" void kernel_launch(void* const* d_in, const int* in_sizes, int n_in,
                              void* d_out, int out_size)
{
    const float* node_s = (const float*)d_in[0];
    const float* node_v = (const float*)d_in[1];
    const int*   ei     = (const int*)  d_in[2];
    const float* edge_s = (const float*)d_in[3];
    const float* edge_v = (const float*)d_in[4];
    const float* ln_g   = (const float*)d_in[5];
    const float* ln_b   = (const float*)d_in[6];
    const float* wes    = (const float*)d_in[7];
    const float* bes    = (const float*)d_in[8];
    const float* wev    = (const float*)d_in[9];
    const float* bev    = (const float*)d_in[10];
    const float* wns    = (const float*)d_in[11];
    const float* bns    = (const float*)d_in[12];
    const float* wnv    = (const float*)d_in[13];
    const float* bnv    = (const float*)d_in[14];
    const float* wrs    = (const float*)d_in[15];
    const float* brs    = (const float*)d_in[16];
    const float* wrv    = (const float*)d_in[17];
    const float* brv    = (const float*)d_in[18];

    const int N = in_sizes[0] / 128;
    const int E = in_sizes[3] / 32;

    cudaFuncSetAttribute(node_kernel, cudaFuncAttributeMaxDynamicSharedMemorySize,
                         NODE_SMEM_FLOATS * sizeof(float));

    prepA_kernel<<<(N + 255) / 256, 256>>>(wes, N);               // also zeroes g_cnti
    prepB_kernel<<<64, 256>>>(wns, wrs, wnv, wrv);
    hist_kernel<<<(E + 255) / 256, 256>>>(ei, E);
    scan_kernel<<<1, 1024>>>(N);
    slot_kernel<<<(E + 255) / 256, 256>>>(ei, E);
    edge_kernel<<<(E + TE - 1) / TE, 256>>>(edge_s, edge_v, bes, wev, bev, E);
    node_kernel<<<(N + 31) / 32, 256, NODE_SMEM_FLOATS * sizeof(float)>>>(
        node_s, node_v, ln_g, ln_b, bns, brs, bnv, brv, (float*)d_out, N);
}

// round 5
// speedup vs baseline: 1.1786x; 1.1381x over previous
#include <cuda_runtime.h>

// ---------------------------------------------------------------------------
// MultiGVPConvLayer fused, v5: CSR-ordered edge processing with run-
// accumulated scatter (few atomics), v1 mainloop, parallel 3-kernel scan.
//   Output: concat( out_s [N,128], out_v [N,48] ) float32
// ---------------------------------------------------------------------------

#define NMAX 50000
#define EMAX 800000
#define TE 64

__device__ float g_agg[(size_t)NMAX * 176];   // per-node [128 scalar | 48 vector] SUMS
__device__ int   g_cnti[NMAX];                // in-degree
__device__ int   g_off[NMAX];                 // CSR offsets
__device__ int   g_cur[NMAX];                 // cursors
__device__ int   g_perm[EMAX];                // edge ids sorted by dst
__device__ int   g_bsum[256];                 // scan block sums
__device__ float g_wesT[32 * 128];            // wes transposed  [k][out]
__device__ float g_wST[128 * 256];            // [k][ wns_out | wrs_out ]
__device__ float g_wVT[48 * 96];              // [k][ wnv_out | wrv_out ]

__device__ __forceinline__ float sigf(float x) { return 1.f / (1.f + __expf(-x)); }

__device__ __forceinline__ void red4(float* p, float4 v) {
    asm volatile("red.global.add.v4.f32 [%0], {%1,%2,%3,%4};"
                 :: "l"(p), "f"(v.x), "f"(v.y), "f"(v.z), "f"(v.w) : "memory");
}

// ---------------------------------------------------------------------------
__global__ void prepW_kernel(const float* __restrict__ wes,
                             const float* __restrict__ wns, const float* __restrict__ wrs,
                             const float* __restrict__ wnv, const float* __restrict__ wrv,
                             int Nn)
{
    int t = blockIdx.x * 256 + threadIdx.x;
    if (t < 128 * 32) { int o = t >> 5, k = t & 31;  g_wesT[k * 128 + o] = wes[t]; }
    if (t < 128 * 128){ int o = t >> 7, k = t & 127; g_wST[k * 256 + o] = wns[t];
                                                     g_wST[k * 256 + 128 + o] = wrs[t]; }
    if (t < 48 * 48)  { int o = t / 48, k = t % 48;  g_wVT[k * 96 + o] = wnv[t];
                                                     g_wVT[k * 96 + 48 + o] = wrv[t]; }
    if (t < Nn) g_cnti[t] = 0;
}

__global__ void hist_kernel(const int* __restrict__ ei, int E)
{
    int e = blockIdx.x * 256 + threadIdx.x;
    if (e < E) atomicAdd(&g_cnti[ei[E + e]], 1);
}

// scan1: per-block sums of 256 counts
__global__ __launch_bounds__(256) void scan1_kernel(int Nn)
{
    __shared__ int ws[8];
    int tid = threadIdx.x, lane = tid & 31, w = tid >> 5;
    int i = blockIdx.x * 256 + tid;
    int v = (i < Nn) ? g_cnti[i] : 0;
    int s = v;
#pragma unroll
    for (int o = 16; o; o >>= 1) s += __shfl_xor_sync(0xffffffffu, s, o);
    if (lane == 0) ws[w] = s;
    __syncthreads();
    if (tid == 0) {
        int t = 0;
#pragma unroll
        for (int k = 0; k < 8; k++) t += ws[k];
        g_bsum[blockIdx.x] = t;
    }
}

// scan2: exclusive scan of block sums (<=256 blocks), single block
__global__ __launch_bounds__(256) void scan2_kernel(int nb)
{
    __shared__ int ws[8];
    int tid = threadIdx.x, lane = tid & 31, w = tid >> 5;
    int v = (tid < nb) ? g_bsum[tid] : 0;
    int x = v;
#pragma unroll
    for (int o = 1; o < 32; o <<= 1) {
        int y = __shfl_up_sync(0xffffffffu, x, o);
        if (lane >= o) x += y;
    }
    if (lane == 31) ws[w] = x;
    __syncthreads();
    int base = 0;
    for (int k = 0; k < w; k++) base += ws[k];
    if (tid < nb) g_bsum[tid] = base + x - v;   // exclusive prefix
}

// scan3: intra-block exclusive scan + base -> g_off, g_cur
__global__ __launch_bounds__(256) void scan3_kernel(int Nn)
{
    __shared__ int ws[8];
    int tid = threadIdx.x, lane = tid & 31, w = tid >> 5;
    int i = blockIdx.x * 256 + tid;
    int v = (i < Nn) ? g_cnti[i] : 0;
    int x = v;
#pragma unroll
    for (int o = 1; o < 32; o <<= 1) {
        int y = __shfl_up_sync(0xffffffffu, x, o);
        if (lane >= o) x += y;
    }
    if (lane == 31) ws[w] = x;
    __syncthreads();
    int wbase = 0;
    for (int k = 0; k < w; k++) wbase += ws[k];
    int excl = g_bsum[blockIdx.x] + wbase + (x - v);
    if (i < Nn) { g_off[i] = excl; g_cur[i] = excl; }
}

__global__ void perm_kernel(const int* __restrict__ ei, int E)
{
    int e = blockIdx.x * 256 + threadIdx.x;
    if (e < E) {
        int slot = atomicAdd(&g_cur[ei[E + e]], 1);
        g_perm[slot] = e;
    }
}

// ---------------------------------------------------------------------------
// Edge kernel: v1 mainloop on CSR-ordered edges, run-accumulated scatter.
// 64 edges / 256 threads; warp handles 8 consecutive CSR slots.
// ---------------------------------------------------------------------------
__global__ __launch_bounds__(256) void edge_kernel(
    const float* __restrict__ edge_s, const float* __restrict__ edge_v,
    const int* __restrict__ edge_index,
    const float* __restrict__ bes, const float* __restrict__ wev,
    const float* __restrict__ bev, int E)
{
    __shared__ float4 wsh[32 * 32];        // wesT as float4 [k][32]
    __shared__ float  es_sh[TE * 32];
    __shared__ float  ev_sh[TE * 3];
    __shared__ int    eid_sh[TE];
    __shared__ int    dst_sh[TE];
    __shared__ float  gate_sh[TE * 16];
    __shared__ float  bes_sh[128];
    __shared__ float  wev_sh[144];
    __shared__ float  bev_sh[48];

    const int tid = threadIdx.x;
    const int e0  = blockIdx.x * TE;
    const int nE  = min(TE, E - e0);

    if (tid < TE) {
        int e = (tid < nE) ? g_perm[e0 + tid] : -1;
        eid_sh[tid] = e;
        dst_sh[tid] = (e >= 0) ? edge_index[E + e] : -1;
    }
    {
        const float4* w4 = (const float4*)g_wesT;
        for (int i = tid; i < 1024; i += 256) wsh[i] = w4[i];
    }
    if (tid < 128)    bes_sh[tid] = bes[tid];
    if (tid < 144)    wev_sh[tid] = wev[tid];
    if (tid < 48)     bev_sh[tid] = bev[tid];
    __syncthreads();

    // gather edge features (each edge_s row = one 128B line)
    {
        const float4* s4 = (const float4*)edge_s;
        float4* d4 = (float4*)es_sh;
        for (int i = tid; i < TE * 8; i += 256) {
            int e = eid_sh[i >> 3];
            d4[i] = (e >= 0) ? s4[(size_t)e * 8 + (i & 7)]
                             : make_float4(0.f, 0.f, 0.f, 0.f);
        }
    }
    if (tid < TE * 3) {
        int e = eid_sh[tid / 3];
        ev_sh[tid] = (e >= 0) ? edge_v[(size_t)e * 3 + tid % 3] : 0.f;
    }
    __syncthreads();

    const int tx = tid & 31;
    const int wg = tid >> 5;

    float4 acc[8];
#pragma unroll
    for (int j = 0; j < 8; j++) acc[j] = make_float4(0.f, 0.f, 0.f, 0.f);

#pragma unroll 4
    for (int k = 0; k < 32; k++) {
        float4 w = wsh[k * 32 + tx];
#pragma unroll
        for (int j = 0; j < 8; j++) {
            float e = es_sh[(wg * 8 + j) * 32 + k];    // warp-uniform broadcast
            acc[j].x = fmaf(w.x, e, acc[j].x);
            acc[j].y = fmaf(w.y, e, acc[j].y);
            acc[j].z = fmaf(w.z, e, acc[j].z);
            acc[j].w = fmaf(w.w, e, acc[j].w);
        }
    }

    // scalar epilogue: silu + gate + run-accumulated scatter (slots dst-sorted)
    {
        const float4 bb = ((const float4*)bes_sh)[tx];
        float4 racc = make_float4(0.f, 0.f, 0.f, 0.f);
        int cur = -1;
#pragma unroll
        for (int j = 0; j < 8; j++) {
            int el = wg * 8 + j;
            int node = dst_sh[el];
            if (node != cur) {
                if (cur >= 0) red4(g_agg + (size_t)cur * 176 + 4 * tx, racc);
                racc = make_float4(0.f, 0.f, 0.f, 0.f);
                cur = node;
            }
            if (node >= 0) {
                float4 s = acc[j];
                s.x += bb.x; s.y += bb.y; s.z += bb.z; s.w += bb.w;
                s.x *= sigf(s.x); s.y *= sigf(s.y);
                s.z *= sigf(s.z); s.w *= sigf(s.w);       // silu
                if (tx < 4) {
                    gate_sh[el * 16 + 4 * tx + 0] = sigf(s.x);
                    gate_sh[el * 16 + 4 * tx + 1] = sigf(s.y);
                    gate_sh[el * 16 + 4 * tx + 2] = sigf(s.z);
                    gate_sh[el * 16 + 4 * tx + 3] = sigf(s.w);
                }
                racc.x += s.x; racc.y += s.y; racc.z += s.z; racc.w += s.w;
            }
        }
        if (cur >= 0) red4(g_agg + (size_t)cur * 176 + 4 * tx, racc);
    }
    __syncthreads();

    // vector part: thread (q, range) -> quad q over 8 consecutive slots
    if (tid < 96) {
        const int q   = tid >> 3;           // 0..11 -> outputs 4q..4q+3
        const int el0 = (tid & 7) * 8;      // 8 consecutive slots
        float w0[4], w1[4], w2[4], bq[4];
#pragma unroll
        for (int i = 0; i < 4; i++) {
            int o = 4 * q + i;
            w0[i] = wev_sh[o * 3 + 0]; w1[i] = wev_sh[o * 3 + 1];
            w2[i] = wev_sh[o * 3 + 2]; bq[i] = bev_sh[o];
        }
        float4 racc = make_float4(0.f, 0.f, 0.f, 0.f);
        int cur = -1;
#pragma unroll
        for (int j = 0; j < 8; j++) {
            int el = el0 + j;
            int node = dst_sh[el];
            if (node != cur) {
                if (cur >= 0) red4(g_agg + (size_t)cur * 176 + 128 + 4 * q, racc);
                racc = make_float4(0.f, 0.f, 0.f, 0.f);
                cur = node;
            }
            if (node >= 0) {
                float e0v = ev_sh[el * 3 + 0], e1v = ev_sh[el * 3 + 1], e2v = ev_sh[el * 3 + 2];
                float* rp = (float*)&racc;
#pragma unroll
                for (int i = 0; i < 4; i++) {
                    float val = fmaf(w0[i], e0v, fmaf(w1[i], e1v, fmaf(w2[i], e2v, bq[i])));
                    rp[i] += val * gate_sh[el * 16 + (4 * q + i) / 3];
                }
            }
        }
        if (cur >= 0) red4(g_agg + (size_t)cur * 176 + 128 + 4 * q, racc);
    }
}

// ---------------------------------------------------------------------------
// Node kernel (v1, with int degree)
// ---------------------------------------------------------------------------
#define NODE_SMEM_FLOATS 50400

__global__ __launch_bounds__(256) void node_kernel(
    const float* __restrict__ node_s, const float* __restrict__ node_v,
    const float* __restrict__ ln_g, const float* __restrict__ ln_b,
    const float* __restrict__ bns, const float* __restrict__ brs,
    const float* __restrict__ bnv, const float* __restrict__ brv,
    float* __restrict__ out, int Nn)
{
    extern __shared__ float smf[];
    float* wST  = smf;
    float* wVT  = wST + 32768;
    float* sn   = wVT + 4608;
    float* xs   = sn + 4096;
    float* vn   = xs + 4096;
    float* xv   = vn + 1536;
    float* gate = xv + 1536;
    float* lng  = gate + 512;
    float* lnb  = lng + 128;
    float* bnsS = lnb + 128;
    float* brsS = bnsS + 128;
    float* bnvS = brsS + 128;
    float* brvS = bnvS + 48;

    const int tid = threadIdx.x;
    const int n0  = blockIdx.x * 32;
    const int nN  = min(32, Nn - n0);

    {
        float4* d = (float4*)wST; const float4* s = (const float4*)g_wST;
        for (int i = tid; i < 8192; i += 256) d[i] = s[i];
    }
    for (int i = tid; i < 4608; i += 256) wVT[i] = g_wVT[i];
    if (tid < 128) { lng[tid] = ln_g[tid]; lnb[tid] = ln_b[tid];
                     bnsS[tid] = bns[tid]; brsS[tid] = brs[tid]; }
    if (tid < 48)  { bnvS[tid] = bnv[tid]; brvS[tid] = brv[tid]; }
    for (int i = tid; i < 4096; i += 256)
        sn[i] = (i < nN * 128) ? node_s[(size_t)n0 * 128 + i] : 0.f;
    for (int i = tid; i < 1536; i += 256)
        vn[i] = (i < nN * 48) ? node_v[(size_t)n0 * 48 + i] : 0.f;
    __syncthreads();

    const int lane = tid & 31, w = tid >> 5;
    for (int q = 0; q < 4; q++) {
        int r = w * 4 + q;
        int n = n0 + r;
        const float* row = sn + r * 128;
        float a = row[lane] + row[lane + 32] + row[lane + 64] + row[lane + 96];
#pragma unroll
        for (int o = 16; o; o >>= 1) a += __shfl_xor_sync(0xffffffffu, a, o);
        float mu = a * (1.f / 128.f);
        float d0 = row[lane] - mu, d1 = row[lane + 32] - mu;
        float d2 = row[lane + 64] - mu, d3 = row[lane + 96] - mu;
        float vv = d0 * d0 + d1 * d1 + d2 * d2 + d3 * d3;
#pragma unroll
        for (int o = 16; o; o >>= 1) vv += __shfl_xor_sync(0xffffffffu, vv, o);
        float rs = rsqrtf(vv * (1.f / 128.f) + 1e-5f);

        const float* vrow = vn + r * 48;
        float x0 = vrow[lane];
        float x1 = (lane < 16) ? vrow[32 + lane] : 0.f;
        float sq = x0 * x0 + x1 * x1;
#pragma unroll
        for (int o = 16; o; o >>= 1) sq += __shfl_xor_sync(0xffffffffu, sq, o);
        float vr = rsqrtf(sq * (1.f / 16.f) + 1e-8f);

        float invden = 0.f;
        const float* aggr = g_agg + (size_t)n * 176;
        if (r < nN) invden = 1.f / fmaxf((float)g_cnti[n], 1.f);

#pragma unroll
        for (int jj = 0; jj < 4; jj++) {
            int c = lane + 32 * jj;
            float x = (row[c] - mu) * rs * lng[c] + lnb[c];
            sn[r * 128 + c] = x;
            float xa = x;
            if (r < nN) xa = x + aggr[c] * invden;
            xs[r * 128 + c] = xa;
        }
        {
            float x = x0 * vr;
            vn[r * 48 + lane] = x;
            float xa = x;
            if (r < nN) xa = x + aggr[128 + lane] * invden;
            xv[r * 48 + lane] = xa;
            if (lane < 16) {
                float y = x1 * vr;
                vn[r * 48 + 32 + lane] = y;
                float ya = y;
                if (r < nN) ya = y + aggr[128 + 32 + lane] * invden;
                xv[r * 48 + 32 + lane] = ya;
            }
        }
    }
    __syncthreads();

    const int og = tid & 63;
    const int ng = tid >> 6;
    const float* xin = (og < 32) ? xs : sn;
    const float4* w4 = (const float4*)wST;
    float4 acc[8];
#pragma unroll
    for (int j = 0; j < 8; j++) acc[j] = make_float4(0.f, 0.f, 0.f, 0.f);

#pragma unroll 4
    for (int k = 0; k < 128; k++) {
        float4 wv = w4[k * 64 + og];
#pragma unroll
        for (int j = 0; j < 8; j++) {
            float x = xin[(ng * 8 + j) * 128 + k];
            acc[j].x = fmaf(wv.x, x, acc[j].x);
            acc[j].y = fmaf(wv.y, x, acc[j].y);
            acc[j].z = fmaf(wv.z, x, acc[j].z);
            acc[j].w = fmaf(wv.w, x, acc[j].w);
        }
    }
    __syncthreads();

    if (og < 32) {
        float4 b = ((const float4*)bnsS)[og];
#pragma unroll
        for (int j = 0; j < 8; j++) {
            int r = ng * 8 + j;
            float4 s = acc[j];
            s.x += b.x; s.y += b.y; s.z += b.z; s.w += b.w;
            s.x *= sigf(s.x); s.y *= sigf(s.y); s.z *= sigf(s.z); s.w *= sigf(s.w);
            if (og < 4) {
                gate[r * 16 + 4 * og + 0] = sigf(s.x);
                gate[r * 16 + 4 * og + 1] = sigf(s.y);
                gate[r * 16 + 4 * og + 2] = sigf(s.z);
                gate[r * 16 + 4 * og + 3] = sigf(s.w);
            }
            ((float4*)xs)[r * 32 + og] = s;
        }
    } else {
        float4 b = ((const float4*)brsS)[og - 32];
#pragma unroll
        for (int j = 0; j < 8; j++) {
            int r = ng * 8 + j;
            float4 s = acc[j];
            s.x += b.x; s.y += b.y; s.z += b.z; s.w += b.w;
            ((float4*)sn)[r * 32 + (og - 32)] = s;
        }
    }
    __syncthreads();

    for (int i = tid; i < nN * 128; i += 256)
        out[(size_t)n0 * 128 + i] = xs[i] + sn[i];

    for (int p = tid; p < nN * 48; p += 256) {
        int r = p / 48, o = p % 48;
        const float* xvr = xv + r * 48;
        const float* vnr = vn + r * 48;
        float a = 0.f, bq = 0.f;
#pragma unroll 4
        for (int k = 0; k < 48; k++) {
            a  = fmaf(xvr[k], wVT[k * 96 + o],      a);
            bq = fmaf(vnr[k], wVT[k * 96 + 48 + o], bq);
        }
        float val = (a + bnvS[o]) * gate[r * 16 + o / 3] + bq + brvS[o];
        out[(size_t)Nn * 128 + (size_t)n0 * 48 + p] = val;
    }
}

// ---------------------------------------------------------------------------
extern "C" void kernel_launch(void* const* d_in, const int* in_sizes, int n_in,
                              void* d_out, int out_size)
{
    const float* node_s = (const float*)d_in[0];
    const float* node_v = (const float*)d_in[1];
    const int*   ei     = (const int*)  d_in[2];
    const float* edge_s = (const float*)d_in[3];
    const float* edge_v = (const float*)d_in[4];
    const float* ln_g   = (const float*)d_in[5];
    const float* ln_b   = (const float*)d_in[6];
    const float* wes    = (const float*)d_in[7];
    const float* bes    = (const float*)d_in[8];
    const float* wev    = (const float*)d_in[9];
    const float* bev    = (const float*)d_in[10];
    const float* wns    = (const float*)d_in[11];
    const float* bns    = (const float*)d_in[12];
    const float* wnv    = (const float*)d_in[13];
    const float* bnv    = (const float*)d_in[14];
    const float* wrs    = (const float*)d_in[15];
    const float* brs    = (const float*)d_in[16];
    const float* wrv    = (const float*)d_in[17];
    const float* brv    = (const float*)d_in[18];

    const int N = in_sizes[0] / 128;
    const int E = in_sizes[3] / 32;
    const int nb = (N + 255) / 256;

    void* aggp;
    cudaGetSymbolAddress(&aggp, g_agg);
    cudaMemsetAsync(aggp, 0, (size_t)N * 176 * sizeof(float), 0);

    cudaFuncSetAttribute(node_kernel, cudaFuncAttributeMaxDynamicSharedMemorySize,
                         NODE_SMEM_FLOATS * sizeof(float));

    prepW_kernel<<<nb, 256>>>(wes, wns, wrs, wnv, wrv, N);   // also zeroes g_cnti
    hist_kernel<<<(E + 255) / 256, 256>>>(ei, E);
    scan1_kernel<<<nb, 256>>>(N);
    scan2_kernel<<<1, 256>>>(nb);
    scan3_kernel<<<nb, 256>>>(N);
    perm_kernel<<<(E + 255) / 256, 256>>>(ei, E);
    edge_kernel<<<(E + TE - 1) / TE, 256>>>(edge_s, edge_v, ei, bes, wev, bev, E);
    node_kernel<<<(N + 31) / 32, 256, NODE_SMEM_FLOATS * sizeof(float)>>>(
        node_s, node_v, ln_g, ln_b, bns, brs, bnv, brv, (float*)d_out, N);
}

// round 6
// speedup vs baseline: 1.4260x; 1.2099x over previous
#include <cuda_runtime.h>

// ---------------------------------------------------------------------------
// MultiGVPConvLayer fused, v6: v1 structure (streaming edges + red4 atomics)
// with f32x2 packed-FMA edge mainloop. Launch order puts edge 4th (ncu slot).
//   Output: concat( out_s [N,128], out_v [N,48] ) float32
// ---------------------------------------------------------------------------

#define NMAX 50000
#define TE 64

__device__ float g_agg[(size_t)NMAX * 176];   // per-node [128 scalar | 48 vector] sums
__device__ float g_cnt[NMAX];                 // in-degree counts
__device__ float g_wesT[32 * 128];            // wes transposed  [k][out]
__device__ float g_wST[128 * 256];            // [k][ wns_out(128) | wrs_out(128) ]
__device__ float g_wVT[48 * 96];              // [k][ wnv_out(48) | wrv_out(48) ]

__device__ __forceinline__ float sigf(float x) { return 1.f / (1.f + __expf(-x)); }

__device__ __forceinline__ void red4(float* p, float4 v) {
    asm volatile("red.global.add.v4.f32 [%0], {%1,%2,%3,%4};"
                 :: "l"(p), "f"(v.x), "f"(v.y), "f"(v.z), "f"(v.w) : "memory");
}

// packed dual-fp32 FMA: d += a * b  (per 32-bit lane)
#define FMA2(d, a, b) \
    asm("fma.rn.f32x2 %0, %1, %2, %0;" : "+l"(d) : "l"(a), "l"(b))

// ---------------------------------------------------------------------------
__global__ void zero_kernel(int Nn)                    // launch #1
{
    size_t t = (size_t)blockIdx.x * 256 + threadIdx.x;
    size_t tot = (size_t)Nn * 44;                      // float4 count of g_agg
    if (t < tot) ((float4*)g_agg)[t] = make_float4(0.f, 0.f, 0.f, 0.f);
    if (t < (size_t)Nn) g_cnt[t] = 0.f;
}

__global__ void prepA_kernel(const float* __restrict__ wes)   // launch #2
{
    int t = blockIdx.x * 256 + threadIdx.x;
    if (t < 128 * 32) { int o = t >> 5, k = t & 31; g_wesT[k * 128 + o] = wes[t]; }
}

__global__ void prepB_kernel(const float* __restrict__ wns, const float* __restrict__ wrs,
                             const float* __restrict__ wnv, const float* __restrict__ wrv)
{                                                             // launch #3
    int t = blockIdx.x * 256 + threadIdx.x;
    if (t < 128 * 128){ int o = t >> 7, k = t & 127; g_wST[k * 256 + o] = wns[t];
                                                     g_wST[k * 256 + 128 + o] = wrs[t]; }
    if (t < 48 * 48)  { int o = t / 48, k = t % 48;  g_wVT[k * 96 + o] = wnv[t];
                                                     g_wVT[k * 96 + 48 + o] = wrv[t]; }
}

// ---------------------------------------------------------------------------
// Edge kernel (launch #4 -> ncu). 64 edges / 256 threads.
// Warp handles 8 edges; lane tx covers outputs 4tx..4tx+3 as 2 f32x2 pairs.
// ---------------------------------------------------------------------------
__global__ __launch_bounds__(256) void edge_kernel(
    const float* __restrict__ edge_s, const float* __restrict__ edge_v,
    const int* __restrict__ edge_index,
    const float* __restrict__ bes, const float* __restrict__ wev,
    const float* __restrict__ bev, int E)
{
    __shared__ float4 wsh[32 * 32];            // wesT float4  [k][32]   16KB
    __shared__ unsigned long long esd[TE * 32];// dup pairs    [e][k]    16KB
    __shared__ float  ev_sh[TE * 3];
    __shared__ int    dst_sh[TE];
    __shared__ float  gate_sh[TE * 16];
    __shared__ float  bes_sh[128];
    __shared__ float  wev_sh[144];
    __shared__ float  bev_sh[48];

    const int tid = threadIdx.x;
    const int e0  = blockIdx.x * TE;
    const int nE  = min(TE, E - e0);

    {
        const float4* w4 = (const float4*)g_wesT;
        for (int i = tid; i < 1024; i += 256) wsh[i] = w4[i];
    }
    {   // gather edge_s rows and store duplicated-transposed: esd[e][k] = (x,x)
        const float4* s4 = (const float4*)(edge_s + (size_t)e0 * 32);
        for (int i = tid; i < TE * 8; i += 256) {
            int e = i >> 3, c = i & 7;
            float4 v = (e < nE) ? s4[i] : make_float4(0.f, 0.f, 0.f, 0.f);
            float2* d = (float2*)&esd[e * 32 + 4 * c];
            d[0] = make_float2(v.x, v.x);
            d[1] = make_float2(v.y, v.y);
            d[2] = make_float2(v.z, v.z);
            d[3] = make_float2(v.w, v.w);
        }
    }
    if (tid < TE * 3) { int e = tid / 3; ev_sh[tid] = (e < nE) ? edge_v[(size_t)e0 * 3 + tid] : 0.f; }
    if (tid < TE) {
        int d = -1;
        if (tid < nE) { d = edge_index[E + e0 + tid]; atomicAdd(&g_cnt[d], 1.f); }
        dst_sh[tid] = d;
    }
    if (tid < 128)    bes_sh[tid] = bes[tid];
    if (tid < 144)    wev_sh[tid] = wev[tid];
    if (tid < 48)     bev_sh[tid] = bev[tid];
    __syncthreads();

    const int tx = tid & 31;
    const int wg = tid >> 5;

    // mainloop: acc2[2j]   = outputs (4tx,4tx+1) for edge wg*8+j
    //           acc2[2j+1] = outputs (4tx+2,4tx+3)
    unsigned long long acc2[16];
#pragma unroll
    for (int i = 0; i < 16; i++) acc2[i] = 0ull;

    const ulonglong2* wp = (const ulonglong2*)wsh;     // [k*32 + tx]
    const ulonglong2* ep = (const ulonglong2*)esd;     // [e*16 + k2]

#pragma unroll
    for (int k2 = 0; k2 < 16; k2++) {
        ulonglong2 w0 = wp[(2 * k2)     * 32 + tx];    // k = 2*k2
        ulonglong2 w1 = wp[(2 * k2 + 1) * 32 + tx];    // k = 2*k2+1
#pragma unroll
        for (int j = 0; j < 8; j++) {
            ulonglong2 ee = ep[(wg * 8 + j) * 16 + k2];  // (e dup @k, e dup @k+1)
            FMA2(acc2[2 * j],     w0.x, ee.x);
            FMA2(acc2[2 * j + 1], w0.y, ee.x);
            FMA2(acc2[2 * j],     w1.x, ee.y);
            FMA2(acc2[2 * j + 1], w1.y, ee.y);
        }
    }

    // epilogue: silu + gate + atomic scatter (v1 scheme)
    const float4 bb = ((const float4*)bes_sh)[tx];
#pragma unroll
    for (int j = 0; j < 8; j++) {
        int el = wg * 8 + j;
        if (el >= nE) break;
        float2 lo = *reinterpret_cast<float2*>(&acc2[2 * j]);
        float2 hi = *reinterpret_cast<float2*>(&acc2[2 * j + 1]);
        float4 s;
        s.x = lo.x + bb.x; s.y = lo.y + bb.y;
        s.z = hi.x + bb.z; s.w = hi.y + bb.w;
        s.x *= sigf(s.x); s.y *= sigf(s.y); s.z *= sigf(s.z); s.w *= sigf(s.w); // silu
        if (tx < 4) {  // gate = sigmoid(silu(out)[:16])
            gate_sh[el * 16 + 4 * tx + 0] = sigf(s.x);
            gate_sh[el * 16 + 4 * tx + 1] = sigf(s.y);
            gate_sh[el * 16 + 4 * tx + 2] = sigf(s.z);
            gate_sh[el * 16 + 4 * tx + 3] = sigf(s.w);
        }
        red4(g_agg + (size_t)dst_sh[el] * 176 + 4 * tx, s);
    }
    __syncthreads();

    // vector part: 12 float4-quads per edge (48 outputs)
    for (int p = tid; p < TE * 12; p += 256) {
        int el = p / 12;
        if (el >= nE) continue;
        int q = p % 12;
        float e0v = ev_sh[el * 3 + 0], e1v = ev_sh[el * 3 + 1], e2v = ev_sh[el * 3 + 2];
        float4 v; float* vp = (float*)&v;
#pragma unroll
        for (int i = 0; i < 4; i++) {
            int o = 4 * q + i;
            float val = fmaf(wev_sh[o * 3 + 0], e0v,
                        fmaf(wev_sh[o * 3 + 1], e1v,
                        fmaf(wev_sh[o * 3 + 2], e2v, bev_sh[o])));
            vp[i] = val * gate_sh[el * 16 + o / 3];
        }
        red4(g_agg + (size_t)dst_sh[el] * 176 + 128 + 4 * q, v);
    }
}

// ---------------------------------------------------------------------------
// Node kernel (launch #5; unchanged v1)
// ---------------------------------------------------------------------------
#define NODE_SMEM_FLOATS 50400

__global__ __launch_bounds__(256) void node_kernel(
    const float* __restrict__ node_s, const float* __restrict__ node_v,
    const float* __restrict__ ln_g, const float* __restrict__ ln_b,
    const float* __restrict__ bns, const float* __restrict__ brs,
    const float* __restrict__ bnv, const float* __restrict__ brv,
    float* __restrict__ out, int Nn)
{
    extern __shared__ float smf[];
    float* wST  = smf;
    float* wVT  = wST + 32768;
    float* sn   = wVT + 4608;
    float* xs   = sn + 4096;
    float* vn   = xs + 4096;
    float* xv   = vn + 1536;
    float* gate = xv + 1536;
    float* lng  = gate + 512;
    float* lnb  = lng + 128;
    float* bnsS = lnb + 128;
    float* brsS = bnsS + 128;
    float* bnvS = brsS + 128;
    float* brvS = bnvS + 48;

    const int tid = threadIdx.x;
    const int n0  = blockIdx.x * 32;
    const int nN  = min(32, Nn - n0);

    {
        float4* d = (float4*)wST; const float4* s = (const float4*)g_wST;
        for (int i = tid; i < 8192; i += 256) d[i] = s[i];
    }
    for (int i = tid; i < 4608; i += 256) wVT[i] = g_wVT[i];
    if (tid < 128) { lng[tid] = ln_g[tid]; lnb[tid] = ln_b[tid];
                     bnsS[tid] = bns[tid]; brsS[tid] = brs[tid]; }
    if (tid < 48)  { bnvS[tid] = bnv[tid]; brvS[tid] = brv[tid]; }
    for (int i = tid; i < 4096; i += 256)
        sn[i] = (i < nN * 128) ? node_s[(size_t)n0 * 128 + i] : 0.f;
    for (int i = tid; i < 1536; i += 256)
        vn[i] = (i < nN * 48) ? node_v[(size_t)n0 * 48 + i] : 0.f;
    __syncthreads();

    const int lane = tid & 31, w = tid >> 5;
    for (int q = 0; q < 4; q++) {
        int r = w * 4 + q;
        int n = n0 + r;
        const float* row = sn + r * 128;
        float a = row[lane] + row[lane + 32] + row[lane + 64] + row[lane + 96];
#pragma unroll
        for (int o = 16; o; o >>= 1) a += __shfl_xor_sync(0xffffffffu, a, o);
        float mu = a * (1.f / 128.f);
        float d0 = row[lane] - mu, d1 = row[lane + 32] - mu;
        float d2 = row[lane + 64] - mu, d3 = row[lane + 96] - mu;
        float vv = d0 * d0 + d1 * d1 + d2 * d2 + d3 * d3;
#pragma unroll
        for (int o = 16; o; o >>= 1) vv += __shfl_xor_sync(0xffffffffu, vv, o);
        float rs = rsqrtf(vv * (1.f / 128.f) + 1e-5f);

        const float* vrow = vn + r * 48;
        float x0 = vrow[lane];
        float x1 = (lane < 16) ? vrow[32 + lane] : 0.f;
        float sq = x0 * x0 + x1 * x1;
#pragma unroll
        for (int o = 16; o; o >>= 1) sq += __shfl_xor_sync(0xffffffffu, sq, o);
        float vr = rsqrtf(sq * (1.f / 16.f) + 1e-8f);

        float invden = 0.f;
        const float* aggr = g_agg + (size_t)n * 176;
        if (r < nN) invden = 1.f / fmaxf(g_cnt[n], 1.f);

#pragma unroll
        for (int jj = 0; jj < 4; jj++) {
            int c = lane + 32 * jj;
            float x = (row[c] - mu) * rs * lng[c] + lnb[c];
            sn[r * 128 + c] = x;
            float xa = x;
            if (r < nN) xa = x + aggr[c] * invden;
            xs[r * 128 + c] = xa;
        }
        {
            float x = x0 * vr;
            vn[r * 48 + lane] = x;
            float xa = x;
            if (r < nN) xa = x + aggr[128 + lane] * invden;
            xv[r * 48 + lane] = xa;
            if (lane < 16) {
                float y = x1 * vr;
                vn[r * 48 + 32 + lane] = y;
                float ya = y;
                if (r < nN) ya = y + aggr[128 + 32 + lane] * invden;
                xv[r * 48 + 32 + lane] = ya;
            }
        }
    }
    __syncthreads();

    const int og = tid & 63;
    const int ng = tid >> 6;
    const float* xin = (og < 32) ? xs : sn;
    const float4* w4 = (const float4*)wST;
    float4 acc[8];
#pragma unroll
    for (int j = 0; j < 8; j++) acc[j] = make_float4(0.f, 0.f, 0.f, 0.f);

#pragma unroll 4
    for (int k = 0; k < 128; k++) {
        float4 wv = w4[k * 64 + og];
#pragma unroll
        for (int j = 0; j < 8; j++) {
            float x = xin[(ng * 8 + j) * 128 + k];
            acc[j].x = fmaf(wv.x, x, acc[j].x);
            acc[j].y = fmaf(wv.y, x, acc[j].y);
            acc[j].z = fmaf(wv.z, x, acc[j].z);
            acc[j].w = fmaf(wv.w, x, acc[j].w);
        }
    }
    __syncthreads();

    if (og < 32) {
        float4 b = ((const float4*)bnsS)[og];
#pragma unroll
        for (int j = 0; j < 8; j++) {
            int r = ng * 8 + j;
            float4 s = acc[j];
            s.x += b.x; s.y += b.y; s.z += b.z; s.w += b.w;
            s.x *= sigf(s.x); s.y *= sigf(s.y); s.z *= sigf(s.z); s.w *= sigf(s.w);
            if (og < 4) {
                gate[r * 16 + 4 * og + 0] = sigf(s.x);
                gate[r * 16 + 4 * og + 1] = sigf(s.y);
                gate[r * 16 + 4 * og + 2] = sigf(s.z);
                gate[r * 16 + 4 * og + 3] = sigf(s.w);
            }
            ((float4*)xs)[r * 32 + og] = s;
        }
    } else {
        float4 b = ((const float4*)brsS)[og - 32];
#pragma unroll
        for (int j = 0; j < 8; j++) {
            int r = ng * 8 + j;
            float4 s = acc[j];
            s.x += b.x; s.y += b.y; s.z += b.z; s.w += b.w;
            ((float4*)sn)[r * 32 + (og - 32)] = s;
        }
    }
    __syncthreads();

    for (int i = tid; i < nN * 128; i += 256)
        out[(size_t)n0 * 128 + i] = xs[i] + sn[i];

    for (int p = tid; p < nN * 48; p += 256) {
        int r = p / 48, o = p % 48;
        const float* xvr = xv + r * 48;
        const float* vnr = vn + r * 48;
        float a = 0.f, bq = 0.f;
#pragma unroll 4
        for (int k = 0; k < 48; k++) {
            a  = fmaf(xvr[k], wVT[k * 96 + o],      a);
            bq = fmaf(vnr[k], wVT[k * 96 + 48 + o], bq);
        }
        float val = (a + bnvS[o]) * gate[r * 16 + o / 3] + bq + brvS[o];
        out[(size_t)Nn * 128 + (size_t)n0 * 48 + p] = val;
    }
}

// ---------------------------------------------------------------------------
extern "C" void kernel_launch(void* const* d_in, const int* in_sizes, int n_in,
                              void* d_out, int out_size)
{
    const float* node_s = (const float*)d_in[0];
    const float* node_v = (const float*)d_in[1];
    const int*   ei     = (const int*)  d_in[2];
    const float* edge_s = (const float*)d_in[3];
    const float* edge_v = (const float*)d_in[4];
    const float* ln_g   = (const float*)d_in[5];
    const float* ln_b   = (const float*)d_in[6];
    const float* wes    = (const float*)d_in[7];
    const float* bes    = (const float*)d_in[8];
    const float* wev    = (const float*)d_in[9];
    const float* bev    = (const float*)d_in[10];
    const float* wns    = (const float*)d_in[11];
    const float* bns    = (const float*)d_in[12];
    const float* wnv    = (const float*)d_in[13];
    const float* bnv    = (const float*)d_in[14];
    const float* wrs    = (const float*)d_in[15];
    const float* brs    = (const float*)d_in[16];
    const float* wrv    = (const float*)d_in[17];
    const float* brv    = (const float*)d_in[18];

    const int N = in_sizes[0] / 128;
    const int E = in_sizes[3] / 32;

    cudaFuncSetAttribute(node_kernel, cudaFuncAttributeMaxDynamicSharedMemorySize,
                         NODE_SMEM_FLOATS * sizeof(float));

    zero_kernel<<<(N * 44 + 255) / 256, 256>>>(N);                 // #1
    prepA_kernel<<<16, 256>>>(wes);                                // #2
    prepB_kernel<<<64, 256>>>(wns, wrs, wnv, wrv);                 // #3
    edge_kernel<<<(E + TE - 1) / TE, 256>>>(edge_s, edge_v, ei,    // #4 (ncu)
                                            bes, wev, bev, E);
    node_kernel<<<(N + 31) / 32, 256, NODE_SMEM_FLOATS * sizeof(float)>>>(
        node_s, node_v, ln_g, ln_b, bns, brs, bnv, brv, (float*)d_out, N);
}

// round 7
// speedup vs baseline: 1.9253x; 1.3501x over previous
#include <cuda_runtime.h>

// ---------------------------------------------------------------------------
// MultiGVPConvLayer fused, v7: v6 edge kernel (FFMA2 GEMV + red4 scatter),
// node kernel rebuilt: persistent blocks, 512 threads, f32x2 GEMM.
//   Launch order: zero, prep, edge, node (#4 -> ncu capture slot)
//   Output: concat( out_s [N,128], out_v [N,48] ) float32
// ---------------------------------------------------------------------------

#define NMAX 50000
#define TE 64

__device__ float g_agg[(size_t)NMAX * 176];   // per-node [128 scalar | 48 vector] sums
__device__ float g_cnt[NMAX];                 // in-degree counts
__device__ float g_wesT[32 * 128];            // wes transposed  [k][out]
__device__ float g_wST[128 * 256];            // [k][ wns_out(128) | wrs_out(128) ]
__device__ float g_wVT[48 * 96];              // [k][ wnv_out(48) | wrv_out(48) ]

__device__ __forceinline__ float sigf(float x) { return 1.f / (1.f + __expf(-x)); }

__device__ __forceinline__ void red4(float* p, float4 v) {
    asm volatile("red.global.add.v4.f32 [%0], {%1,%2,%3,%4};"
                 :: "l"(p), "f"(v.x), "f"(v.y), "f"(v.z), "f"(v.w) : "memory");
}

// packed dual-fp32 FMA: d += a * b  (per 32-bit lane)
#define FMA2(d, a, b) \
    asm("fma.rn.f32x2 %0, %1, %2, %0;" : "+l"(d) : "l"(a), "l"(b))

__device__ __forceinline__ unsigned long long dup2(float x) {
    unsigned long long d;
    asm("mov.b64 %0, {%1, %1};" : "=l"(d) : "f"(x));
    return d;
}

// ---------------------------------------------------------------------------
__global__ void zero_kernel(int Nn)                    // launch #1
{
    size_t t = (size_t)blockIdx.x * 256 + threadIdx.x;
    size_t tot = (size_t)Nn * 44;                      // float4 count of g_agg
    if (t < tot) ((float4*)g_agg)[t] = make_float4(0.f, 0.f, 0.f, 0.f);
    if (t < (size_t)Nn) g_cnt[t] = 0.f;
}

__global__ void prep_kernel(const float* __restrict__ wes,     // launch #2
                            const float* __restrict__ wns, const float* __restrict__ wrs,
                            const float* __restrict__ wnv, const float* __restrict__ wrv)
{
    int t = blockIdx.x * 256 + threadIdx.x;
    if (t < 128 * 32) { int o = t >> 5, k = t & 31;  g_wesT[k * 128 + o] = wes[t]; }
    if (t < 128 * 128){ int o = t >> 7, k = t & 127; g_wST[k * 256 + o] = wns[t];
                                                     g_wST[k * 256 + 128 + o] = wrs[t]; }
    if (t < 48 * 48)  { int o = t / 48, k = t % 48;  g_wVT[k * 96 + o] = wnv[t];
                                                     g_wVT[k * 96 + 48 + o] = wrv[t]; }
}

// ---------------------------------------------------------------------------
// Edge kernel (launch #3). 64 edges / 256 threads; FFMA2 mainloop (v6).
// ---------------------------------------------------------------------------
__global__ __launch_bounds__(256) void edge_kernel(
    const float* __restrict__ edge_s, const float* __restrict__ edge_v,
    const int* __restrict__ edge_index,
    const float* __restrict__ bes, const float* __restrict__ wev,
    const float* __restrict__ bev, int E)
{
    __shared__ float4 wsh[32 * 32];            // wesT float4  [k][32]   16KB
    __shared__ unsigned long long esd[TE * 32];// dup pairs    [e][k]    16KB
    __shared__ float  ev_sh[TE * 3];
    __shared__ int    dst_sh[TE];
    __shared__ float  gate_sh[TE * 16];
    __shared__ float  bes_sh[128];
    __shared__ float  wev_sh[144];
    __shared__ float  bev_sh[48];

    const int tid = threadIdx.x;
    const int e0  = blockIdx.x * TE;
    const int nE  = min(TE, E - e0);

    {
        const float4* w4 = (const float4*)g_wesT;
        for (int i = tid; i < 1024; i += 256) wsh[i] = w4[i];
    }
    {   // gather edge_s rows, store duplicated: esd[e][k] = (x,x)
        const float4* s4 = (const float4*)(edge_s + (size_t)e0 * 32);
        for (int i = tid; i < TE * 8; i += 256) {
            int e = i >> 3, c = i & 7;
            float4 v = (e < nE) ? s4[i] : make_float4(0.f, 0.f, 0.f, 0.f);
            float2* d = (float2*)&esd[e * 32 + 4 * c];
            d[0] = make_float2(v.x, v.x);
            d[1] = make_float2(v.y, v.y);
            d[2] = make_float2(v.z, v.z);
            d[3] = make_float2(v.w, v.w);
        }
    }
    if (tid < TE * 3) { int e = tid / 3; ev_sh[tid] = (e < nE) ? edge_v[(size_t)e0 * 3 + tid] : 0.f; }
    if (tid < TE) {
        int d = -1;
        if (tid < nE) { d = edge_index[E + e0 + tid]; atomicAdd(&g_cnt[d], 1.f); }
        dst_sh[tid] = d;
    }
    if (tid < 128)    bes_sh[tid] = bes[tid];
    if (tid < 144)    wev_sh[tid] = wev[tid];
    if (tid < 48)     bev_sh[tid] = bev[tid];
    __syncthreads();

    const int tx = tid & 31;
    const int wg = tid >> 5;

    unsigned long long acc2[16];
#pragma unroll
    for (int i = 0; i < 16; i++) acc2[i] = 0ull;

    const ulonglong2* wp = (const ulonglong2*)wsh;     // [k*32 + tx]
    const ulonglong2* ep = (const ulonglong2*)esd;     // [e*16 + k2]

#pragma unroll
    for (int k2 = 0; k2 < 16; k2++) {
        ulonglong2 w0 = wp[(2 * k2)     * 32 + tx];
        ulonglong2 w1 = wp[(2 * k2 + 1) * 32 + tx];
#pragma unroll
        for (int j = 0; j < 8; j++) {
            ulonglong2 ee = ep[(wg * 8 + j) * 16 + k2];
            FMA2(acc2[2 * j],     w0.x, ee.x);
            FMA2(acc2[2 * j + 1], w0.y, ee.x);
            FMA2(acc2[2 * j],     w1.x, ee.y);
            FMA2(acc2[2 * j + 1], w1.y, ee.y);
        }
    }

    const float4 bb = ((const float4*)bes_sh)[tx];
#pragma unroll
    for (int j = 0; j < 8; j++) {
        int el = wg * 8 + j;
        if (el >= nE) break;
        float2 lo = *reinterpret_cast<float2*>(&acc2[2 * j]);
        float2 hi = *reinterpret_cast<float2*>(&acc2[2 * j + 1]);
        float4 s;
        s.x = lo.x + bb.x; s.y = lo.y + bb.y;
        s.z = hi.x + bb.z; s.w = hi.y + bb.w;
        s.x *= sigf(s.x); s.y *= sigf(s.y); s.z *= sigf(s.z); s.w *= sigf(s.w); // silu
        if (tx < 4) {
            gate_sh[el * 16 + 4 * tx + 0] = sigf(s.x);
            gate_sh[el * 16 + 4 * tx + 1] = sigf(s.y);
            gate_sh[el * 16 + 4 * tx + 2] = sigf(s.z);
            gate_sh[el * 16 + 4 * tx + 3] = sigf(s.w);
        }
        red4(g_agg + (size_t)dst_sh[el] * 176 + 4 * tx, s);
    }
    __syncthreads();

    for (int p = tid; p < TE * 12; p += 256) {
        int el = p / 12;
        if (el >= nE) continue;
        int q = p % 12;
        float e0v = ev_sh[el * 3 + 0], e1v = ev_sh[el * 3 + 1], e2v = ev_sh[el * 3 + 2];
        float4 v; float* vp = (float*)&v;
#pragma unroll
        for (int i = 0; i < 4; i++) {
            int o = 4 * q + i;
            float val = fmaf(wev_sh[o * 3 + 0], e0v,
                        fmaf(wev_sh[o * 3 + 1], e1v,
                        fmaf(wev_sh[o * 3 + 2], e2v, bev_sh[o])));
            vp[i] = val * gate_sh[el * 16 + o / 3];
        }
        red4(g_agg + (size_t)dst_sh[el] * 176 + 128 + 4 * q, v);
    }
}

// ---------------------------------------------------------------------------
// Node kernel (launch #4 -> ncu): persistent, 512 threads, weights loaded once.
// Tile = 32 nodes. GEMM: thread = (og 0..63 -> 4 outputs, ng 0..7 -> 4 nodes).
// ---------------------------------------------------------------------------
#define NODE_SMEM_FLOATS 50400

__global__ __launch_bounds__(512) void node_kernel(
    const float* __restrict__ node_s, const float* __restrict__ node_v,
    const float* __restrict__ ln_g, const float* __restrict__ ln_b,
    const float* __restrict__ bns, const float* __restrict__ brs,
    const float* __restrict__ bnv, const float* __restrict__ brv,
    float* __restrict__ out, int Nn)
{
    extern __shared__ float smf[];
    float* wST  = smf;                // 32768
    float* wVT  = wST + 32768;        // 4608
    float* sn   = wVT + 4608;         // 4096
    float* xs   = sn + 4096;          // 4096
    float* vn   = xs + 4096;          // 1536
    float* xv   = vn + 1536;          // 1536
    float* gate = xv + 1536;          // 512
    float* lng  = gate + 512;
    float* lnb  = lng + 128;
    float* bnsS = lnb + 128;
    float* brsS = bnsS + 128;
    float* bnvS = brsS + 128;
    float* brvS = bnvS + 48;

    const int tid  = threadIdx.x;
    const int lane = tid & 31;
    const int w    = tid >> 5;        // 0..15

    // ---- one-time: weights + params into smem
    {
        float4* d = (float4*)wST; const float4* s = (const float4*)g_wST;
        for (int i = tid; i < 8192; i += 512) d[i] = s[i];
    }
    for (int i = tid; i < 4608; i += 512) wVT[i] = g_wVT[i];
    if (tid < 128) { lng[tid] = ln_g[tid]; lnb[tid] = ln_b[tid];
                     bnsS[tid] = bns[tid]; brsS[tid] = brs[tid]; }
    if (tid < 48)  { bnvS[tid] = bnv[tid]; brvS[tid] = brv[tid]; }

    const int ntiles = (Nn + 31) / 32;
    for (int tile = blockIdx.x; tile < ntiles; tile += gridDim.x) {
        const int n0 = tile * 32;
        const int nN = min(32, Nn - n0);
        __syncthreads();   // buffers free (covers one-time loads on first iter)

        for (int i = tid; i < 4096; i += 512)
            sn[i] = (i < nN * 128) ? node_s[(size_t)n0 * 128 + i] : 0.f;
        for (int i = tid; i < 1536; i += 512)
            vn[i] = (i < nN * 48) ? node_v[(size_t)n0 * 48 + i] : 0.f;
        __syncthreads();

        // ---- LN + vnorm + agg consume: warp w -> nodes 2w, 2w+1
        for (int q = 0; q < 2; q++) {
            int r = w * 2 + q;
            int n = n0 + r;
            const float* row = sn + r * 128;
            float a = row[lane] + row[lane + 32] + row[lane + 64] + row[lane + 96];
#pragma unroll
            for (int o = 16; o; o >>= 1) a += __shfl_xor_sync(0xffffffffu, a, o);
            float mu = a * (1.f / 128.f);
            float d0 = row[lane] - mu, d1 = row[lane + 32] - mu;
            float d2 = row[lane + 64] - mu, d3 = row[lane + 96] - mu;
            float vv = d0 * d0 + d1 * d1 + d2 * d2 + d3 * d3;
#pragma unroll
            for (int o = 16; o; o >>= 1) vv += __shfl_xor_sync(0xffffffffu, vv, o);
            float rs = rsqrtf(vv * (1.f / 128.f) + 1e-5f);

            const float* vrow = vn + r * 48;
            float x0 = vrow[lane];
            float x1 = (lane < 16) ? vrow[32 + lane] : 0.f;
            float sq = x0 * x0 + x1 * x1;
#pragma unroll
            for (int o = 16; o; o >>= 1) sq += __shfl_xor_sync(0xffffffffu, sq, o);
            float vr = rsqrtf(sq * (1.f / 16.f) + 1e-8f);

            float invden = 0.f;
            const float* aggr = g_agg + (size_t)n * 176;
            if (r < nN) invden = 1.f / fmaxf(g_cnt[n], 1.f);

#pragma unroll
            for (int jj = 0; jj < 4; jj++) {
                int c = lane + 32 * jj;
                float x = (row[c] - mu) * rs * lng[c] + lnb[c];
                sn[r * 128 + c] = x;
                float xa = x;
                if (r < nN) xa = x + aggr[c] * invden;
                xs[r * 128 + c] = xa;
            }
            {
                float x = x0 * vr;
                vn[r * 48 + lane] = x;
                float xa = x;
                if (r < nN) xa = x + aggr[128 + lane] * invden;
                xv[r * 48 + lane] = xa;
                if (lane < 16) {
                    float y = x1 * vr;
                    vn[r * 48 + 32 + lane] = y;
                    float ya = y;
                    if (r < nN) ya = y + aggr[128 + 32 + lane] * invden;
                    xv[r * 48 + 32 + lane] = ya;
                }
            }
        }
        __syncthreads();

        // ---- dual GEMM [32,128]x[128,256], f32x2 packed
        const int og = tid & 63;
        const int ng = tid >> 6;            // 0..7 -> nodes 4ng..4ng+3
        const float* xin = (og < 32) ? xs : sn;
        const ulonglong2* wp = (const ulonglong2*)wST;   // [k*64 + og]
        unsigned long long acc2[8];
#pragma unroll
        for (int i = 0; i < 8; i++) acc2[i] = 0ull;

#pragma unroll 4
        for (int k = 0; k < 128; k++) {
            ulonglong2 wv = wp[k * 64 + og];
#pragma unroll
            for (int j = 0; j < 4; j++) {
                unsigned long long xd = dup2(xin[(ng * 4 + j) * 128 + k]);
                FMA2(acc2[2 * j],     wv.x, xd);
                FMA2(acc2[2 * j + 1], wv.y, xd);
            }
        }
        __syncthreads();   // done reading xs/sn

        if (og < 32) {
            float4 b = ((const float4*)bnsS)[og];
#pragma unroll
            for (int j = 0; j < 4; j++) {
                int r = ng * 4 + j;
                float2 lo = *reinterpret_cast<float2*>(&acc2[2 * j]);
                float2 hi = *reinterpret_cast<float2*>(&acc2[2 * j + 1]);
                float4 s;
                s.x = lo.x + b.x; s.y = lo.y + b.y;
                s.z = hi.x + b.z; s.w = hi.y + b.w;
                s.x *= sigf(s.x); s.y *= sigf(s.y); s.z *= sigf(s.z); s.w *= sigf(s.w);
                if (og < 4) {
                    gate[r * 16 + 4 * og + 0] = sigf(s.x);
                    gate[r * 16 + 4 * og + 1] = sigf(s.y);
                    gate[r * 16 + 4 * og + 2] = sigf(s.z);
                    gate[r * 16 + 4 * og + 3] = sigf(s.w);
                }
                ((float4*)xs)[r * 32 + og] = s;
            }
        } else {
            float4 b = ((const float4*)brsS)[og - 32];
#pragma unroll
            for (int j = 0; j < 4; j++) {
                int r = ng * 4 + j;
                float2 lo = *reinterpret_cast<float2*>(&acc2[2 * j]);
                float2 hi = *reinterpret_cast<float2*>(&acc2[2 * j + 1]);
                float4 s;
                s.x = lo.x + b.x; s.y = lo.y + b.y;
                s.z = hi.x + b.z; s.w = hi.y + b.w;
                ((float4*)sn)[r * 32 + (og - 32)] = s;
            }
        }
        __syncthreads();

        // scalar output: silu(out_pre) + residual
        for (int i = tid; i < nN * 128; i += 512)
            out[(size_t)n0 * 128 + i] = xs[i] + sn[i];

        // vector output
        for (int p = tid; p < nN * 48; p += 512) {
            int r = p / 48, o = p % 48;
            const float* xvr = xv + r * 48;
            const float* vnr = vn + r * 48;
            float a = 0.f, bq = 0.f;
#pragma unroll 4
            for (int k = 0; k < 48; k++) {
                a  = fmaf(xvr[k], wVT[k * 96 + o],      a);
                bq = fmaf(vnr[k], wVT[k * 96 + 48 + o], bq);
            }
            float val = (a + bnvS[o]) * gate[r * 16 + o / 3] + bq + brvS[o];
            out[(size_t)Nn * 128 + (size_t)n0 * 48 + p] = val;
        }
    }
}

// ---------------------------------------------------------------------------
extern "C" void kernel_launch(void* const* d_in, const int* in_sizes, int n_in,
                              void* d_out, int out_size)
{
    const float* node_s = (const float*)d_in[0];
    const float* node_v = (const float*)d_in[1];
    const int*   ei     = (const int*)  d_in[2];
    const float* edge_s = (const float*)d_in[3];
    const float* edge_v = (const float*)d_in[4];
    const float* ln_g   = (const float*)d_in[5];
    const float* ln_b   = (const float*)d_in[6];
    const float* wes    = (const float*)d_in[7];
    const float* bes    = (const float*)d_in[8];
    const float* wev    = (const float*)d_in[9];
    const float* bev    = (const float*)d_in[10];
    const float* wns    = (const float*)d_in[11];
    const float* bns    = (const float*)d_in[12];
    const float* wnv    = (const float*)d_in[13];
    const float* bnv    = (const float*)d_in[14];
    const float* wrs    = (const float*)d_in[15];
    const float* brs    = (const float*)d_in[16];
    const float* wrv    = (const float*)d_in[17];
    const float* brv    = (const float*)d_in[18];

    const int N = in_sizes[0] / 128;
    const int E = in_sizes[3] / 32;

    cudaFuncSetAttribute(node_kernel, cudaFuncAttributeMaxDynamicSharedMemorySize,
                         NODE_SMEM_FLOATS * sizeof(float));

    zero_kernel<<<(N * 44 + 255) / 256, 256>>>(N);                 // #1
    prep_kernel<<<64, 256>>>(wes, wns, wrs, wnv, wrv);             // #2
    edge_kernel<<<(E + TE - 1) / TE, 256>>>(edge_s, edge_v, ei,    // #3
                                            bes, wev, bev, E);
    node_kernel<<<152, 512, NODE_SMEM_FLOATS * sizeof(float)>>>(   // #4 (ncu)
        node_s, node_v, ln_g, ln_b, bns, brs, bnv, brv, (float*)d_out, N);
}

// round 8
// speedup vs baseline: 1.9391x; 1.0072x over previous
#include <cuda_runtime.h>

// ---------------------------------------------------------------------------
// MultiGVPConvLayer fused, v7: v6 edge kernel (FFMA2 GEMV + red4 scatter),
// node kernel rebuilt: persistent blocks, 512 threads, f32x2 GEMM.
//   Launch order: zero, prep, edge, node (#4 -> ncu capture slot)
//   Output: concat( out_s [N,128], out_v [N,48] ) float32
// ---------------------------------------------------------------------------

#define NMAX 50000
#define TE 64

__device__ float g_agg[(size_t)NMAX * 176];   // per-node [128 scalar | 48 vector] sums
__device__ float g_cnt[NMAX];                 // in-degree counts
__device__ float g_wesT[32 * 128];            // wes transposed  [k][out]
__device__ float g_wST[128 * 256];            // [k][ wns_out(128) | wrs_out(128) ]
__device__ float g_wVT[48 * 96];              // [k][ wnv_out(48) | wrv_out(48) ]

__device__ __forceinline__ float sigf(float x) { return 1.f / (1.f + __expf(-x)); }

__device__ __forceinline__ void red4(float* p, float4 v) {
    asm volatile("red.global.add.v4.f32 [%0], {%1,%2,%3,%4};"
                 :: "l"(p), "f"(v.x), "f"(v.y), "f"(v.z), "f"(v.w) : "memory");
}

// packed dual-fp32 FMA: d += a * b  (per 32-bit lane)
#define FMA2(d, a, b) \
    asm("fma.rn.f32x2 %0, %1, %2, %0;" : "+l"(d) : "l"(a), "l"(b))

__device__ __forceinline__ unsigned long long dup2(float x) {
    unsigned long long d;
    asm("mov.b64 %0, {%1, %1};" : "=l"(d) : "f"(x));
    return d;
}

// ---------------------------------------------------------------------------
__global__ void zero_kernel(int Nn)                    // launch #1
{
    size_t t = (size_t)blockIdx.x * 256 + threadIdx.x;
    size_t tot = (size_t)Nn * 44;                      // float4 count of g_agg
    if (t < tot) ((float4*)g_agg)[t] = make_float4(0.f, 0.f, 0.f, 0.f);
    if (t < (size_t)Nn) g_cnt[t] = 0.f;
}

__global__ void prep_kernel(const float* __restrict__ wes,     // launch #2
                            const float* __restrict__ wns, const float* __restrict__ wrs,
                            const float* __restrict__ wnv, const float* __restrict__ wrv)
{
    int t = blockIdx.x * 256 + threadIdx.x;
    if (t < 128 * 32) { int o = t >> 5, k = t & 31;  g_wesT[k * 128 + o] = wes[t]; }
    if (t < 128 * 128){ int o = t >> 7, k = t & 127; g_wST[k * 256 + o] = wns[t];
                                                     g_wST[k * 256 + 128 + o] = wrs[t]; }
    if (t < 48 * 48)  { int o = t / 48, k = t % 48;  g_wVT[k * 96 + o] = wnv[t];
                                                     g_wVT[k * 96 + 48 + o] = wrv[t]; }
}

// ---------------------------------------------------------------------------
// Edge kernel (launch #3). 64 edges / 256 threads; FFMA2 mainloop (v6).
// ---------------------------------------------------------------------------
__global__ __launch_bounds__(256) void edge_kernel(
    const float* __restrict__ edge_s, const float* __restrict__ edge_v,
    const int* __restrict__ edge_index,
    const float* __restrict__ bes, const float* __restrict__ wev,
    const float* __restrict__ bev, int E)
{
    __shared__ float4 wsh[32 * 32];            // wesT float4  [k][32]   16KB
    __shared__ unsigned long long esd[TE * 32];// dup pairs    [e][k]    16KB
    __shared__ float  ev_sh[TE * 3];
    __shared__ int    dst_sh[TE];
    __shared__ float  gate_sh[TE * 16];
    __shared__ float  bes_sh[128];
    __shared__ float  wev_sh[144];
    __shared__ float  bev_sh[48];

    const int tid = threadIdx.x;
    const int e0  = blockIdx.x * TE;
    const int nE  = min(TE, E - e0);

    {
        const float4* w4 = (const float4*)g_wesT;
        for (int i = tid; i < 1024; i += 256) wsh[i] = w4[i];
    }
    {   // gather edge_s rows, store duplicated: esd[e][k] = (x,x)
        const float4* s4 = (const float4*)(edge_s + (size_t)e0 * 32);
        for (int i = tid; i < TE * 8; i += 256) {
            int e = i >> 3, c = i & 7;
            float4 v = (e < nE) ? s4[i] : make_float4(0.f, 0.f, 0.f, 0.f);
            float2* d = (float2*)&esd[e * 32 + 4 * c];
            d[0] = make_float2(v.x, v.x);
            d[1] = make_float2(v.y, v.y);
            d[2] = make_float2(v.z, v.z);
            d[3] = make_float2(v.w, v.w);
        }
    }
    if (tid < TE * 3) { int e = tid / 3; ev_sh[tid] = (e < nE) ? edge_v[(size_t)e0 * 3 + tid] : 0.f; }
    if (tid < TE) {
        int d = -1;
        if (tid < nE) { d = edge_index[E + e0 + tid]; atomicAdd(&g_cnt[d], 1.f); }
        dst_sh[tid] = d;
    }
    if (tid < 128)    bes_sh[tid] = bes[tid];
    if (tid < 144)    wev_sh[tid] = wev[tid];
    if (tid < 48)     bev_sh[tid] = bev[tid];
    __syncthreads();

    const int tx = tid & 31;
    const int wg = tid >> 5;

    unsigned long long acc2[16];
#pragma unroll
    for (int i = 0; i < 16; i++) acc2[i] = 0ull;

    const ulonglong2* wp = (const ulonglong2*)wsh;     // [k*32 + tx]
    const ulonglong2* ep = (const ulonglong2*)esd;     // [e*16 + k2]

#pragma unroll
    for (int k2 = 0; k2 < 16; k2++) {
        ulonglong2 w0 = wp[(2 * k2)     * 32 + tx];
        ulonglong2 w1 = wp[(2 * k2 + 1) * 32 + tx];
#pragma unroll
        for (int j = 0; j < 8; j++) {
            ulonglong2 ee = ep[(wg * 8 + j) * 16 + k2];
            FMA2(acc2[2 * j],     w0.x, ee.x);
            FMA2(acc2[2 * j + 1], w0.y, ee.x);
            FMA2(acc2[2 * j],     w1.x, ee.y);
            FMA2(acc2[2 * j + 1], w1.y, ee.y);
        }
    }

    const float4 bb = ((const float4*)bes_sh)[tx];
#pragma unroll
    for (int j = 0; j < 8; j++) {
        int el = wg * 8 + j;
        if (el >= nE) break;
        float2 lo = *reinterpret_cast<float2*>(&acc2[2 * j]);
        float2 hi = *reinterpret_cast<float2*>(&acc2[2 * j + 1]);
        float4 s;
        s.x = lo.x + bb.x; s.y = lo.y + bb.y;
        s.z = hi.x + bb.z; s.w = hi.y + bb.w;
        s.x *= sigf(s.x); s.y *= sigf(s.y); s.z *= sigf(s.z); s.w *= sigf(s.w); // silu
        if (tx < 4) {
            gate_sh[el * 16 + 4 * tx + 0] = sigf(s.x);
            gate_sh[el * 16 + 4 * tx + 1] = sigf(s.y);
            gate_sh[el * 16 + 4 * tx + 2] = sigf(s.z);
            gate_sh[el * 16 + 4 * tx + 3] = sigf(s.w);
        }
        red4(g_agg + (size_t)dst_sh[el] * 176 + 4 * tx, s);
    }
    __syncthreads();

    for (int p = tid; p < TE * 12; p += 256) {
        int el = p / 12;
        if (el >= nE) continue;
        int q = p % 12;
        float e0v = ev_sh[el * 3 + 0], e1v = ev_sh[el * 3 + 1], e2v = ev_sh[el * 3 + 2];
        float4 v; float* vp = (float*)&v;
#pragma unroll
        for (int i = 0; i < 4; i++) {
            int o = 4 * q + i;
            float val = fmaf(wev_sh[o * 3 + 0], e0v,
                        fmaf(wev_sh[o * 3 + 1], e1v,
                        fmaf(wev_sh[o * 3 + 2], e2v, bev_sh[o])));
            vp[i] = val * gate_sh[el * 16 + o / 3];
        }
        red4(g_agg + (size_t)dst_sh[el] * 176 + 128 + 4 * q, v);
    }
}

// ---------------------------------------------------------------------------
// Node kernel (launch #4 -> ncu): persistent, 512 threads, weights loaded once.
// Tile = 32 nodes. GEMM: thread = (og 0..63 -> 4 outputs, ng 0..7 -> 4 nodes).
// ---------------------------------------------------------------------------
#define NODE_SMEM_FLOATS 50400

__global__ __launch_bounds__(512) void node_kernel(
    const float* __restrict__ node_s, const float* __restrict__ node_v,
    const float* __restrict__ ln_g, const float* __restrict__ ln_b,
    const float* __restrict__ bns, const float* __restrict__ brs,
    const float* __restrict__ bnv, const float* __restrict__ brv,
    float* __restrict__ out, int Nn)
{
    extern __shared__ float smf[];
    float* wST  = smf;                // 32768
    float* wVT  = wST + 32768;        // 4608
    float* sn   = wVT + 4608;         // 4096
    float* xs   = sn + 4096;          // 4096
    float* vn   = xs + 4096;          // 1536
    float* xv   = vn + 1536;          // 1536
    float* gate = xv + 1536;          // 512
    float* lng  = gate + 512;
    float* lnb  = lng + 128;
    float* bnsS = lnb + 128;
    float* brsS = bnsS + 128;
    float* bnvS = brsS + 128;
    float* brvS = bnvS + 48;

    const int tid  = threadIdx.x;
    const int lane = tid & 31;
    const int w    = tid >> 5;        // 0..15

    // ---- one-time: weights + params into smem
    {
        float4* d = (float4*)wST; const float4* s = (const float4*)g_wST;
        for (int i = tid; i < 8192; i += 512) d[i] = s[i];
    }
    for (int i = tid; i < 4608; i += 512) wVT[i] = g_wVT[i];
    if (tid < 128) { lng[tid] = ln_g[tid]; lnb[tid] = ln_b[tid];
                     bnsS[tid] = bns[tid]; brsS[tid] = brs[tid]; }
    if (tid < 48)  { bnvS[tid] = bnv[tid]; brvS[tid] = brv[tid]; }

    const int ntiles = (Nn + 31) / 32;
    for (int tile = blockIdx.x; tile < ntiles; tile += gridDim.x) {
        const int n0 = tile * 32;
        const int nN = min(32, Nn - n0);
        __syncthreads();   // buffers free (covers one-time loads on first iter)

        for (int i = tid; i < 4096; i += 512)
            sn[i] = (i < nN * 128) ? node_s[(size_t)n0 * 128 + i] : 0.f;
        for (int i = tid; i < 1536; i += 512)
            vn[i] = (i < nN * 48) ? node_v[(size_t)n0 * 48 + i] : 0.f;
        __syncthreads();

        // ---- LN + vnorm + agg consume: warp w -> nodes 2w, 2w+1
        for (int q = 0; q < 2; q++) {
            int r = w * 2 + q;
            int n = n0 + r;
            const float* row = sn + r * 128;
            float a = row[lane] + row[lane + 32] + row[lane + 64] + row[lane + 96];
#pragma unroll
            for (int o = 16; o; o >>= 1) a += __shfl_xor_sync(0xffffffffu, a, o);
            float mu = a * (1.f / 128.f);
            float d0 = row[lane] - mu, d1 = row[lane + 32] - mu;
            float d2 = row[lane + 64] - mu, d3 = row[lane + 96] - mu;
            float vv = d0 * d0 + d1 * d1 + d2 * d2 + d3 * d3;
#pragma unroll
            for (int o = 16; o; o >>= 1) vv += __shfl_xor_sync(0xffffffffu, vv, o);
            float rs = rsqrtf(vv * (1.f / 128.f) + 1e-5f);

            const float* vrow = vn + r * 48;
            float x0 = vrow[lane];
            float x1 = (lane < 16) ? vrow[32 + lane] : 0.f;
            float sq = x0 * x0 + x1 * x1;
#pragma unroll
            for (int o = 16; o; o >>= 1) sq += __shfl_xor_sync(0xffffffffu, sq, o);
            float vr = rsqrtf(sq * (1.f / 16.f) + 1e-8f);

            float invden = 0.f;
            const float* aggr = g_agg + (size_t)n * 176;
            if (r < nN) invden = 1.f / fmaxf(g_cnt[n], 1.f);

#pragma unroll
            for (int jj = 0; jj < 4; jj++) {
                int c = lane + 32 * jj;
                float x = (row[c] - mu) * rs * lng[c] + lnb[c];
                sn[r * 128 + c] = x;
                float xa = x;
                if (r < nN) xa = x + aggr[c] * invden;
                xs[r * 128 + c] = xa;
            }
            {
                float x = x0 * vr;
                vn[r * 48 + lane] = x;
                float xa = x;
                if (r < nN) xa = x + aggr[128 + lane] * invden;
                xv[r * 48 + lane] = xa;
                if (lane < 16) {
                    float y = x1 * vr;
                    vn[r * 48 + 32 + lane] = y;
                    float ya = y;
                    if (r < nN) ya = y + aggr[128 + 32 + lane] * invden;
                    xv[r * 48 + 32 + lane] = ya;
                }
            }
        }
        __syncthreads();

        // ---- dual GEMM [32,128]x[128,256], f32x2 packed
        const int og = tid & 63;
        const int ng = tid >> 6;            // 0..7 -> nodes 4ng..4ng+3
        const float* xin = (og < 32) ? xs : sn;
        const ulonglong2* wp = (const ulonglong2*)wST;   // [k*64 + og]
        unsigned long long acc2[8];
#pragma unroll
        for (int i = 0; i < 8; i++) acc2[i] = 0ull;

#pragma unroll 4
        for (int k = 0; k < 128; k++) {
            ulonglong2 wv = wp[k * 64 + og];
#pragma unroll
            for (int j = 0; j < 4; j++) {
                unsigned long long xd = dup2(xin[(ng * 4 + j) * 128 + k]);
                FMA2(acc2[2 * j],     wv.x, xd);
                FMA2(acc2[2 * j + 1], wv.y, xd);
            }
        }
        __syncthreads();   // done reading xs/sn

        if (og < 32) {
            float4 b = ((const float4*)bnsS)[og];
#pragma unroll
            for (int j = 0; j < 4; j++) {
                int r = ng * 4 + j;
                float2 lo = *reinterpret_cast<float2*>(&acc2[2 * j]);
                float2 hi = *reinterpret_cast<float2*>(&acc2[2 * j + 1]);
                float4 s;
                s.x = lo.x + b.x; s.y = lo.y + b.y;
                s.z = hi.x + b.z; s.w = hi.y + b.w;
                s.x *= sigf(s.x); s.y *= sigf(s.y); s.z *= sigf(s.z); s.w *= sigf(s.w);
                if (og < 4) {
                    gate[r * 16 + 4 * og + 0] = sigf(s.x);
                    gate[r * 16 + 4 * og + 1] = sigf(s.y);
                    gate[r * 16 + 4 * og + 2] = sigf(s.z);
                    gate[r * 16 + 4 * og + 3] = sigf(s.w);
                }
                ((float4*)xs)[r * 32 + og] = s;
            }
        } else {
            float4 b = ((const float4*)brsS)[og - 32];
#pragma unroll
            for (int j = 0; j < 4; j++) {
                int r = ng * 4 + j;
                float2 lo = *reinterpret_cast<float2*>(&acc2[2 * j]);
                float2 hi = *reinterpret_cast<float2*>(&acc2[2 * j + 1]);
                float4 s;
                s.x = lo.x + b.x; s.y = lo.y + b.y;
                s.z = hi.x + b.z; s.w = hi.y + b.w;
                ((float4*)sn)[r * 32 + (og - 32)] = s;
            }
        }
        __syncthreads();

        // scalar output: silu(out_pre) + residual
        for (int i = tid; i < nN * 128; i += 512)
            out[(size_t)n0 * 128 + i] = xs[i] + sn[i];

        // vector output
        for (int p = tid; p < nN * 48; p += 512) {
            int r = p / 48, o = p % 48;
            const float* xvr = xv + r * 48;
            const float* vnr = vn + r * 48;
            float a = 0.f, bq = 0.f;
#pragma unroll 4
            for (int k = 0; k < 48; k++) {
                a  = fmaf(xvr[k], wVT[k * 96 + o],      a);
                bq = fmaf(vnr[k], wVT[k * 96 + 48 + o], bq);
            }
            float val = (a + bnvS[o]) * gate[r * 16 + o / 3] + bq + brvS[o];
            out[(size_t)Nn * 128 + (size_t)n0 * 48 + p] = val;
        }
    }
}

// ---------------------------------------------------------------------------
extern "C" void kernel_launch(void* const* d_in, const int* in_sizes, int n_in,
                              void* d_out, int out_size)
{
    const float* node_s = (const float*)d_in[0];
    const float* node_v = (const float*)d_in[1];
    const int*   ei     = (const int*)  d_in[2];
    const float* edge_s = (const float*)d_in[3];
    const float* edge_v = (const float*)d_in[4];
    const float* ln_g   = (const float*)d_in[5];
    const float* ln_b   = (const float*)d_in[6];
    const float* wes    = (const float*)d_in[7];
    const float* bes    = (const float*)d_in[8];
    const float* wev    = (const float*)d_in[9];
    const float* bev    = (const float*)d_in[10];
    const float* wns    = (const float*)d_in[11];
    const float* bns    = (const float*)d_in[12];
    const float* wnv    = (const float*)d_in[13];
    const float* bnv    = (const float*)d_in[14];
    const float* wrs    = (const float*)d_in[15];
    const float* brs    = (const float*)d_in[16];
    const float* wrv    = (const float*)d_in[17];
    const float* brv    = (const float*)d_in[18];

    const int N = in_sizes[0] / 128;
    const int E = in_sizes[3] / 32;

    cudaFuncSetAttribute(node_kernel, cudaFuncAttributeMaxDynamicSharedMemorySize,
                         NODE_SMEM_FLOATS * sizeof(float));

    zero_kernel<<<(N * 44 + 255) / 256, 256>>>(N);                 // #1
    prep_kernel<<<64, 256>>>(wes, wns, wrs, wnv, wrv);             // #2
    edge_kernel<<<(E + TE - 1) / TE, 256>>>(edge_s, edge_v, ei,    // #3
                                            bes, wev, bev, E);
    node_kernel<<<152, 512, NODE_SMEM_FLOATS * sizeof(float)>>>(   // #4 (ncu)
        node_s, node_v, ln_g, ln_b, bns, brs, bnv, brv, (float*)d_out, N);
}

// round 9
// speedup vs baseline: 2.0908x; 1.0782x over previous
#include <cuda_runtime.h>

// ---------------------------------------------------------------------------
// MultiGVPConvLayer fused, v8: v6/v7 edge kernel (FFMA2 + red4) unchanged;
// node kernel GEMM moved to mma.sync m16n8k8 tf32 (x hi/lo split, weights
// single tf32). Persistent node blocks, 512 threads.
//   Launch order: zero, prep, edge, node (#4 -> ncu capture slot)
//   Output: concat( out_s [N,128], out_v [N,48] ) float32
// ---------------------------------------------------------------------------

#define NMAX 50000
#define TE 64

__device__ float  g_agg[(size_t)NMAX * 176];  // per-node [128 scalar | 48 vector] sums
__device__ float  g_cnt[NMAX];                // in-degree counts
__device__ float  g_wesT[32 * 128];           // wes transposed [k][out] (edge GEMV)
__device__ float2 g_wB[16384];                // node B-frags: [kt16][ntg32][lane32] (b0,b1) tf32
__device__ float  g_wVT[48 * 96];             // [k][ wnv_out(48) | wrv_out(48) ]

__device__ __forceinline__ float sigf(float x) { return 1.f / (1.f + __expf(-x)); }

__device__ __forceinline__ void red4(float* p, float4 v) {
    asm volatile("red.global.add.v4.f32 [%0], {%1,%2,%3,%4};"
                 :: "l"(p), "f"(v.x), "f"(v.y), "f"(v.z), "f"(v.w) : "memory");
}

// packed dual-fp32 FMA: d += a * b  (per 32-bit lane)
#define FMA2(d, a, b) \
    asm("fma.rn.f32x2 %0, %1, %2, %0;" : "+l"(d) : "l"(a), "l"(b))

// tf32 round (rna) -> fp32-bit-pattern with low mantissa zeroed
__device__ __forceinline__ unsigned tf32u(float f) {
    unsigned u;
    asm("cvt.rna.tf32.f32 %0, %1;" : "=r"(u) : "f"(f));
    return u;
}
__device__ __forceinline__ float tf32f(float f) { return __uint_as_float(tf32u(f)); }

__device__ __forceinline__ void mma_tf32(float* d, const unsigned* a, const unsigned* b) {
    asm volatile(
        "mma.sync.aligned.m16n8k8.row.col.f32.tf32.tf32.f32 "
        "{%0,%1,%2,%3}, {%4,%5,%6,%7}, {%8,%9}, {%0,%1,%2,%3};"
        : "+f"(d[0]), "+f"(d[1]), "+f"(d[2]), "+f"(d[3])
        : "r"(a[0]), "r"(a[1]), "r"(a[2]), "r"(a[3]), "r"(b[0]), "r"(b[1]));
}

// ---------------------------------------------------------------------------
__global__ void zero_kernel(int Nn)                    // launch #1
{
    size_t t = (size_t)blockIdx.x * 256 + threadIdx.x;
    size_t tot = (size_t)Nn * 44;
    if (t < tot) ((float4*)g_agg)[t] = make_float4(0.f, 0.f, 0.f, 0.f);
    if (t < (size_t)Nn) g_cnt[t] = 0.f;
}

__global__ void prep_kernel(const float* __restrict__ wes,     // launch #2
                            const float* __restrict__ wns, const float* __restrict__ wrs,
                            const float* __restrict__ wnv, const float* __restrict__ wrv)
{
    int t = blockIdx.x * 256 + threadIdx.x;
    if (t < 16384) {            // node B fragments, tf32-rounded
        int lane = t & 31, ntg = (t >> 5) & 31, kt = t >> 10;
        int g = lane >> 2, tig = lane & 3;
        int k = kt * 8 + tig;
        int n = ntg * 8 + g;
        const float* srow = (n < 128) ? (wns + n * 128) : (wrs + (n - 128) * 128);
        g_wB[t] = make_float2(tf32f(srow[k]), tf32f(srow[k + 4]));
    }
    if (t < 128 * 32) { int o = t >> 5, k = t & 31; g_wesT[k * 128 + o] = wes[t]; }
    if (t < 48 * 48)  { int o = t / 48, k = t % 48; g_wVT[k * 96 + o] = wnv[t];
                                                    g_wVT[k * 96 + 48 + o] = wrv[t]; }
}

// ---------------------------------------------------------------------------
// Edge kernel (launch #3). 64 edges / 256 threads; FFMA2 mainloop (v6, proven).
// ---------------------------------------------------------------------------
__global__ __launch_bounds__(256) void edge_kernel(
    const float* __restrict__ edge_s, const float* __restrict__ edge_v,
    const int* __restrict__ edge_index,
    const float* __restrict__ bes, const float* __restrict__ wev,
    const float* __restrict__ bev, int E)
{
    __shared__ float4 wsh[32 * 32];
    __shared__ unsigned long long esd[TE * 32];
    __shared__ float  ev_sh[TE * 3];
    __shared__ int    dst_sh[TE];
    __shared__ float  gate_sh[TE * 16];
    __shared__ float  bes_sh[128];
    __shared__ float  wev_sh[144];
    __shared__ float  bev_sh[48];

    const int tid = threadIdx.x;
    const int e0  = blockIdx.x * TE;
    const int nE  = min(TE, E - e0);

    {
        const float4* w4 = (const float4*)g_wesT;
        for (int i = tid; i < 1024; i += 256) wsh[i] = w4[i];
    }
    {
        const float4* s4 = (const float4*)(edge_s + (size_t)e0 * 32);
        for (int i = tid; i < TE * 8; i += 256) {
            int e = i >> 3, c = i & 7;
            float4 v = (e < nE) ? s4[i] : make_float4(0.f, 0.f, 0.f, 0.f);
            float2* d = (float2*)&esd[e * 32 + 4 * c];
            d[0] = make_float2(v.x, v.x);
            d[1] = make_float2(v.y, v.y);
            d[2] = make_float2(v.z, v.z);
            d[3] = make_float2(v.w, v.w);
        }
    }
    if (tid < TE * 3) { int e = tid / 3; ev_sh[tid] = (e < nE) ? edge_v[(size_t)e0 * 3 + tid] : 0.f; }
    if (tid < TE) {
        int d = -1;
        if (tid < nE) { d = edge_index[E + e0 + tid]; atomicAdd(&g_cnt[d], 1.f); }
        dst_sh[tid] = d;
    }
    if (tid < 128)    bes_sh[tid] = bes[tid];
    if (tid < 144)    wev_sh[tid] = wev[tid];
    if (tid < 48)     bev_sh[tid] = bev[tid];
    __syncthreads();

    const int tx = tid & 31;
    const int wg = tid >> 5;

    unsigned long long acc2[16];
#pragma unroll
    for (int i = 0; i < 16; i++) acc2[i] = 0ull;

    const ulonglong2* wp = (const ulonglong2*)wsh;
    const ulonglong2* ep = (const ulonglong2*)esd;

#pragma unroll
    for (int k2 = 0; k2 < 16; k2++) {
        ulonglong2 w0 = wp[(2 * k2)     * 32 + tx];
        ulonglong2 w1 = wp[(2 * k2 + 1) * 32 + tx];
#pragma unroll
        for (int j = 0; j < 8; j++) {
            ulonglong2 ee = ep[(wg * 8 + j) * 16 + k2];
            FMA2(acc2[2 * j],     w0.x, ee.x);
            FMA2(acc2[2 * j + 1], w0.y, ee.x);
            FMA2(acc2[2 * j],     w1.x, ee.y);
            FMA2(acc2[2 * j + 1], w1.y, ee.y);
        }
    }

    const float4 bb = ((const float4*)bes_sh)[tx];
#pragma unroll
    for (int j = 0; j < 8; j++) {
        int el = wg * 8 + j;
        if (el >= nE) break;
        float2 lo = *reinterpret_cast<float2*>(&acc2[2 * j]);
        float2 hi = *reinterpret_cast<float2*>(&acc2[2 * j + 1]);
        float4 s;
        s.x = lo.x + bb.x; s.y = lo.y + bb.y;
        s.z = hi.x + bb.z; s.w = hi.y + bb.w;
        s.x *= sigf(s.x); s.y *= sigf(s.y); s.z *= sigf(s.z); s.w *= sigf(s.w);
        if (tx < 4) {
            gate_sh[el * 16 + 4 * tx + 0] = sigf(s.x);
            gate_sh[el * 16 + 4 * tx + 1] = sigf(s.y);
            gate_sh[el * 16 + 4 * tx + 2] = sigf(s.z);
            gate_sh[el * 16 + 4 * tx + 3] = sigf(s.w);
        }
        red4(g_agg + (size_t)dst_sh[el] * 176 + 4 * tx, s);
    }
    __syncthreads();

    for (int p = tid; p < TE * 12; p += 256) {
        int el = p / 12;
        if (el >= nE) continue;
        int q = p % 12;
        float e0v = ev_sh[el * 3 + 0], e1v = ev_sh[el * 3 + 1], e2v = ev_sh[el * 3 + 2];
        float4 v; float* vp = (float*)&v;
#pragma unroll
        for (int i = 0; i < 4; i++) {
            int o = 4 * q + i;
            float val = fmaf(wev_sh[o * 3 + 0], e0v,
                        fmaf(wev_sh[o * 3 + 1], e1v,
                        fmaf(wev_sh[o * 3 + 2], e2v, bev_sh[o])));
            vp[i] = val * gate_sh[el * 16 + o / 3];
        }
        red4(g_agg + (size_t)dst_sh[el] * 176 + 128 + 4 * q, v);
    }
}

// ---------------------------------------------------------------------------
// Node kernel (launch #4 -> ncu): persistent, 512 threads, tf32 mma GEMM.
// Tile = 32 nodes x 256 outputs. Warp w: mstrip=w>>3 (16 nodes), nstrip=w&7
// (32 outputs = 4 n-tiles). Outputs 0..127: wns on xs (hi/lo split, 2 mma);
// 128..255: wrs on s_n (single tf32, 1 mma). X rows padded to 132 floats
// (conflict-free A-frag LDS: bank = 4g+tig).
// ---------------------------------------------------------------------------
#define XPAD 132
#define NODE_SMEM_FLOATS 54240

__global__ __launch_bounds__(512) void node_kernel(
    const float* __restrict__ node_s, const float* __restrict__ node_v,
    const float* __restrict__ ln_g, const float* __restrict__ ln_b,
    const float* __restrict__ bns, const float* __restrict__ brs,
    const float* __restrict__ bnv, const float* __restrict__ brv,
    float* __restrict__ out, int Nn)
{
    extern __shared__ float smf[];
    float* wB   = smf;                 // 32768 (float2 frags)
    float* wVT  = wB + 32768;          // 4608
    float* xh   = wVT + 4608;          // 4224  (xs hi  -> bufA: silu out)
    float* xl   = xh + 4224;           // 4224  (xs lo  -> bufB: res out)
    float* sh   = xl + 4224;           // 4224  (raw node_s -> s_n tf32)
    float* vn   = sh + 4224;           // 1536
    float* xv   = vn + 1536;           // 1536
    float* gate = xv + 1536;           // 512
    float* lng  = gate + 512;
    float* lnb  = lng + 128;
    float* bnsS = lnb + 128;
    float* brsS = bnsS + 128;
    float* bnvS = brsS + 128;
    float* brvS = bnvS + 48;

    const int tid  = threadIdx.x;
    const int lane = tid & 31;
    const int w    = tid >> 5;          // 0..15
    const int g    = lane >> 2;         // 0..7
    const int tig  = lane & 3;          // 0..3

    // one-time loads
    {
        float4* d = (float4*)wB; const float4* s = (const float4*)g_wB;
        for (int i = tid; i < 8192; i += 512) d[i] = s[i];
    }
    for (int i = tid; i < 4608; i += 512) wVT[i] = g_wVT[i];
    if (tid < 128) { lng[tid] = ln_g[tid]; lnb[tid] = ln_b[tid];
                     bnsS[tid] = bns[tid]; brsS[tid] = brs[tid]; }
    if (tid < 48)  { bnvS[tid] = bnv[tid]; brvS[tid] = brv[tid]; }

    const int mstrip = w >> 3;          // 0..1
    const int nstrip = w & 7;           // 0..7
    const int m0     = mstrip * 16;
    const bool wnsP  = (nstrip < 4);

    const int ntiles = (Nn + 31) / 32;
    for (int tile = blockIdx.x; tile < ntiles; tile += gridDim.x) {
        const int n0t = tile * 32;
        const int nN  = min(32, Nn - n0t);
        __syncthreads();   // previous tile fully consumed (covers one-time loads)

        for (int i = tid; i < 4096; i += 512) {
            int r = i >> 7, c = i & 127;
            sh[r * XPAD + c] = (i < nN * 128) ? node_s[(size_t)n0t * 128 + i] : 0.f;
        }
        for (int i = tid; i < 1536; i += 512)
            vn[i] = (i < nN * 48) ? node_v[(size_t)n0t * 48 + i] : 0.f;
        __syncthreads();

        // ---- LN + vnorm + agg consume: warp w -> nodes 2w, 2w+1
        for (int q = 0; q < 2; q++) {
            int r = w * 2 + q;
            int n = n0t + r;
            const float* row = sh + r * XPAD;
            float a = row[lane] + row[lane + 32] + row[lane + 64] + row[lane + 96];
#pragma unroll
            for (int o = 16; o; o >>= 1) a += __shfl_xor_sync(0xffffffffu, a, o);
            float mu = a * (1.f / 128.f);
            float d0 = row[lane] - mu, d1 = row[lane + 32] - mu;
            float d2 = row[lane + 64] - mu, d3 = row[lane + 96] - mu;
            float vv = d0 * d0 + d1 * d1 + d2 * d2 + d3 * d3;
#pragma unroll
            for (int o = 16; o; o >>= 1) vv += __shfl_xor_sync(0xffffffffu, vv, o);
            float rs = rsqrtf(vv * (1.f / 128.f) + 1e-5f);

            const float* vrow = vn + r * 48;
            float x0 = vrow[lane];
            float x1 = (lane < 16) ? vrow[32 + lane] : 0.f;
            float sq = x0 * x0 + x1 * x1;
#pragma unroll
            for (int o = 16; o; o >>= 1) sq += __shfl_xor_sync(0xffffffffu, sq, o);
            float vr = rsqrtf(sq * (1.f / 16.f) + 1e-8f);

            float invden = 0.f;
            const float* aggr = g_agg + (size_t)n * 176;
            if (r < nN) invden = 1.f / fmaxf(g_cnt[n], 1.f);

#pragma unroll
            for (int jj = 0; jj < 4; jj++) {
                int c = lane + 32 * jj;
                float x = (row[c] - mu) * rs * lng[c] + lnb[c];
                float xa = x;
                if (r < nN) xa = x + aggr[c] * invden;
                float hf = tf32f(xa);
                sh[r * XPAD + c] = tf32f(x);           // s_n (tf32, residual path)
                xh[r * XPAD + c] = hf;                 // xs hi
                xl[r * XPAD + c] = tf32f(xa - hf);     // xs lo
            }
            {
                float x = x0 * vr;
                float xa = x;
                if (r < nN) xa = x + aggr[128 + lane] * invden;
                vn[r * 48 + lane] = x;
                xv[r * 48 + lane] = xa;
                if (lane < 16) {
                    float y = x1 * vr;
                    float ya = y;
                    if (r < nN) ya = y + aggr[128 + 32 + lane] * invden;
                    vn[r * 48 + 32 + lane] = y;
                    xv[r * 48 + 32 + lane] = ya;
                }
            }
        }
        __syncthreads();

        // ---- mma GEMM: 16 k-tiles
        float acc[4][4];
#pragma unroll
        for (int nt = 0; nt < 4; nt++)
#pragma unroll
            for (int i = 0; i < 4; i++) acc[nt][i] = 0.f;

        {
            const int arow = (m0 + g) * XPAD + tig;
            const float2* Bb = ((const float2*)wB) + (nstrip * 4) * 32 + lane;
#pragma unroll 4
            for (int kt = 0; kt < 16; kt++) {
                const int ko = kt * 8;
                unsigned a0[4], a1[4];
                if (wnsP) {
                    a0[0] = __float_as_uint(xh[arow + ko]);
                    a0[1] = __float_as_uint(xh[arow + 8 * XPAD + ko]);
                    a0[2] = __float_as_uint(xh[arow + ko + 4]);
                    a0[3] = __float_as_uint(xh[arow + 8 * XPAD + ko + 4]);
                    a1[0] = __float_as_uint(xl[arow + ko]);
                    a1[1] = __float_as_uint(xl[arow + 8 * XPAD + ko]);
                    a1[2] = __float_as_uint(xl[arow + ko + 4]);
                    a1[3] = __float_as_uint(xl[arow + 8 * XPAD + ko + 4]);
                } else {
                    a0[0] = __float_as_uint(sh[arow + ko]);
                    a0[1] = __float_as_uint(sh[arow + 8 * XPAD + ko]);
                    a0[2] = __float_as_uint(sh[arow + ko + 4]);
                    a0[3] = __float_as_uint(sh[arow + 8 * XPAD + ko + 4]);
                }
#pragma unroll
                for (int nt = 0; nt < 4; nt++) {
                    float2 bv = Bb[kt * 1024 + nt * 32];
                    unsigned b[2] = { __float_as_uint(bv.x), __float_as_uint(bv.y) };
                    mma_tf32(acc[nt], a0, b);
                    if (wnsP) mma_tf32(acc[nt], a1, b);
                }
            }
        }
        __syncthreads();   // all mma reads of xh/xl/sh complete

        // ---- epilogue: bias + silu/gate (wns) or bias (wrs); bufA=xh, bufB=xl
        {
            const int r0 = m0 + g, r1 = m0 + 8 + g;
#pragma unroll
            for (int nt = 0; nt < 4; nt++) {
                int o = nstrip * 32 + nt * 8 + tig * 2;   // global output col
                if (wnsP) {
                    float b0v = bnsS[o], b1v = bnsS[o + 1];
                    float v0 = acc[nt][0] + b0v, v1 = acc[nt][1] + b1v;
                    float v2 = acc[nt][2] + b0v, v3 = acc[nt][3] + b1v;
                    v0 *= sigf(v0); v1 *= sigf(v1); v2 *= sigf(v2); v3 *= sigf(v3);
                    xh[r0 * XPAD + o]     = v0;
                    xh[r0 * XPAD + o + 1] = v1;
                    xh[r1 * XPAD + o]     = v2;
                    xh[r1 * XPAD + o + 1] = v3;
                    if (o < 16) {
                        gate[r0 * 16 + o]     = sigf(v0);
                        gate[r0 * 16 + o + 1] = sigf(v1);
                        gate[r1 * 16 + o]     = sigf(v2);
                        gate[r1 * 16 + o + 1] = sigf(v3);
                    }
                } else {
                    int oc = o - 128;
                    float b0v = brsS[oc], b1v = brsS[oc + 1];
                    xl[r0 * XPAD + oc]     = acc[nt][0] + b0v;
                    xl[r0 * XPAD + oc + 1] = acc[nt][1] + b1v;
                    xl[r1 * XPAD + oc]     = acc[nt][2] + b0v;
                    xl[r1 * XPAD + oc + 1] = acc[nt][3] + b1v;
                }
            }
        }
        __syncthreads();

        // scalar output: silu(out_pre) + residual
        for (int i = tid; i < nN * 128; i += 512) {
            int r = i >> 7, c = i & 127;
            out[(size_t)n0t * 128 + i] = xh[r * XPAD + c] + xl[r * XPAD + c];
        }

        // vector output
        for (int p = tid; p < nN * 48; p += 512) {
            int r = p / 48, o = p % 48;
            const float* xvr = xv + r * 48;
            const float* vnr = vn + r * 48;
            float a = 0.f, bq = 0.f;
#pragma unroll 4
            for (int k = 0; k < 48; k++) {
                a  = fmaf(xvr[k], wVT[k * 96 + o],      a);
                bq = fmaf(vnr[k], wVT[k * 96 + 48 + o], bq);
            }
            float val = (a + bnvS[o]) * gate[r * 16 + o / 3] + bq + brvS[o];
            out[(size_t)Nn * 128 + (size_t)n0t * 48 + p] = val;
        }
    }
}

// ---------------------------------------------------------------------------
extern "C" void kernel_launch(void* const* d_in, const int* in_sizes, int n_in,
                              void* d_out, int out_size)
{
    const float* node_s = (const float*)d_in[0];
    const float* node_v = (const float*)d_in[1];
    const int*   ei     = (const int*)  d_in[2];
    const float* edge_s = (const float*)d_in[3];
    const float* edge_v = (const float*)d_in[4];
    const float* ln_g   = (const float*)d_in[5];
    const float* ln_b   = (const float*)d_in[6];
    const float* wes    = (const float*)d_in[7];
    const float* bes    = (const float*)d_in[8];
    const float* wev    = (const float*)d_in[9];
    const float* bev    = (const float*)d_in[10];
    const float* wns    = (const float*)d_in[11];
    const float* bns    = (const float*)d_in[12];
    const float* wnv    = (const float*)d_in[13];
    const float* bnv    = (const float*)d_in[14];
    const float* wrs    = (const float*)d_in[15];
    const float* brs    = (const float*)d_in[16];
    const float* wrv    = (const float*)d_in[17];
    const float* brv    = (const float*)d_in[18];

    const int N = in_sizes[0] / 128;
    const int E = in_sizes[3] / 32;

    cudaFuncSetAttribute(node_kernel, cudaFuncAttributeMaxDynamicSharedMemorySize,
                         NODE_SMEM_FLOATS * sizeof(float));

    zero_kernel<<<(N * 44 + 255) / 256, 256>>>(N);                 // #1
    prep_kernel<<<64, 256>>>(wes, wns, wrs, wnv, wrv);             // #2
    edge_kernel<<<(E + TE - 1) / TE, 256>>>(edge_s, edge_v, ei,    // #3
                                            bes, wev, bev, E);
    node_kernel<<<152, 512, NODE_SMEM_FLOATS * sizeof(float)>>>(   // #4 (ncu)
        node_s, node_v, ln_g, ln_b, bns, brs, bnv, brv, (float*)d_out, N);
}

// round 10
// speedup vs baseline: 2.3800x; 1.1383x over previous
#include <cuda_runtime.h>

// ---------------------------------------------------------------------------
// MultiGVPConvLayer fused, v9: BOTH GEMMs on tf32 mma.sync (m16n8k8).
//   edge: A = edges x 32k (hi/lo split), B = wes (single tf32)
//   node: v8 kernel unchanged (proven, 197us)
//   Launch order: prep, zero_agg, zero_cnt, edge (#4 -> ncu), node
//   Output: concat( out_s [N,128], out_v [N,48] ) float32
// ---------------------------------------------------------------------------

#define NMAX 50000
#define TE 64
#define EPAD 36
#define SPAD 132

__device__ float  g_agg[(size_t)NMAX * 176];  // per-node [128 s | 48 v] sums
__device__ float  g_cnt[NMAX];                // in-degree counts
__device__ float2 g_wesB[2048];               // edge B-frags [kt4][ntg16][lane32] tf32
__device__ float2 g_wB[16384];                // node B-frags [kt16][ntg32][lane32] tf32
__device__ float  g_wVT[48 * 96];             // [k][ wnv_out(48) | wrv_out(48) ]

__device__ __forceinline__ float sigf(float x) { return 1.f / (1.f + __expf(-x)); }

__device__ __forceinline__ void red4(float* p, float4 v) {
    asm volatile("red.global.add.v4.f32 [%0], {%1,%2,%3,%4};"
                 :: "l"(p), "f"(v.x), "f"(v.y), "f"(v.z), "f"(v.w) : "memory");
}

__device__ __forceinline__ unsigned tf32u(float f) {
    unsigned u;
    asm("cvt.rna.tf32.f32 %0, %1;" : "=r"(u) : "f"(f));
    return u;
}
__device__ __forceinline__ float tf32f(float f) { return __uint_as_float(tf32u(f)); }

__device__ __forceinline__ void mma_tf32(float* d, const unsigned* a, const unsigned* b) {
    asm volatile(
        "mma.sync.aligned.m16n8k8.row.col.f32.tf32.tf32.f32 "
        "{%0,%1,%2,%3}, {%4,%5,%6,%7}, {%8,%9}, {%0,%1,%2,%3};"
        : "+f"(d[0]), "+f"(d[1]), "+f"(d[2]), "+f"(d[3])
        : "r"(a[0]), "r"(a[1]), "r"(a[2]), "r"(a[3]), "r"(b[0]), "r"(b[1]));
}

// ---------------------------------------------------------------------------
__global__ void prep_kernel(const float* __restrict__ wes,     // launch #1
                            const float* __restrict__ wns, const float* __restrict__ wrs,
                            const float* __restrict__ wnv, const float* __restrict__ wrv)
{
    int t = blockIdx.x * 256 + threadIdx.x;
    if (t < 2048) {             // edge B frags (K=32 -> 4 kt, 16 ntg)
        int lane = t & 31, ntg = (t >> 5) & 15, kt = t >> 9;
        int g = lane >> 2, tig = lane & 3;
        int k = kt * 8 + tig;
        int n = ntg * 8 + g;
        g_wesB[t] = make_float2(tf32f(wes[n * 32 + k]), tf32f(wes[n * 32 + k + 4]));
    }
    if (t < 16384) {            // node B frags (K=128 -> 16 kt, 32 ntg)
        int lane = t & 31, ntg = (t >> 5) & 31, kt = t >> 10;
        int g = lane >> 2, tig = lane & 3;
        int k = kt * 8 + tig;
        int n = ntg * 8 + g;
        const float* srow = (n < 128) ? (wns + n * 128) : (wrs + (n - 128) * 128);
        g_wB[t] = make_float2(tf32f(srow[k]), tf32f(srow[k + 4]));
    }
    if (t < 48 * 48) { int o = t / 48, k = t % 48; g_wVT[k * 96 + o] = wnv[t];
                                                   g_wVT[k * 96 + 48 + o] = wrv[t]; }
}

__global__ void zero_agg_kernel(int Nn)                        // launch #2
{
    size_t t = (size_t)blockIdx.x * 256 + threadIdx.x;
    if (t < (size_t)Nn * 44) ((float4*)g_agg)[t] = make_float4(0.f, 0.f, 0.f, 0.f);
}
__global__ void zero_cnt_kernel(int Nn)                        // launch #3
{
    int t = blockIdx.x * 256 + threadIdx.x;
    if (t < Nn) g_cnt[t] = 0.f;
}

// ---------------------------------------------------------------------------
// Edge kernel (launch #4 -> ncu). 64 edges / 256 threads (8 warps).
// mma: warp w -> mstrip = w>>1 (16 edges), nhalf = w&1 (64 outputs, 8 ntiles).
// smem union: [ B frags | es_hi | es_lo ] overlaid by sout after mma.
// ---------------------------------------------------------------------------
__global__ __launch_bounds__(256) void edge_kernel(
    const float* __restrict__ edge_s, const float* __restrict__ edge_v,
    const int* __restrict__ edge_index,
    const float* __restrict__ bes, const float* __restrict__ wev,
    const float* __restrict__ bev, int E)
{
    __shared__ char  uni[34816];         // B 16384 | es_hi 9216 | es_lo 9216
    __shared__ float ev_sh[TE * 3];
    __shared__ int   dst_sh[TE];
    __shared__ float gate_sh[TE * 16];
    __shared__ float bes_sh[128];
    __shared__ float wev_sh[144];
    __shared__ float bev_sh[48];

    float2* wB   = (float2*)uni;                       // during mma
    float*  es_h = (float*)(uni + 16384);              // [64][36]
    float*  es_l = (float*)(uni + 16384 + 9216);       // [64][36]
    float*  sout = (float*)uni;                        // [64][132] after mma

    const int tid  = threadIdx.x;
    const int lane = tid & 31;
    const int w    = tid >> 5;
    const int e0   = blockIdx.x * TE;
    const int nE   = min(TE, E - e0);

    // ---- stage: B frags + edge_s hi/lo + small params
    {
        const float4* s = (const float4*)g_wesB;       // 1024 float4
        float4* d = (float4*)wB;
        for (int i = tid; i < 1024; i += 256) d[i] = s[i];
    }
    {
        const float4* s4 = (const float4*)(edge_s + (size_t)e0 * 32);
        for (int i = tid; i < TE * 8; i += 256) {
            int e = i >> 3, c = (i & 7) * 4;
            float4 v = (e < nE) ? s4[i] : make_float4(0.f, 0.f, 0.f, 0.f);
            float h;
            h = tf32f(v.x); es_h[e * EPAD + c + 0] = h; es_l[e * EPAD + c + 0] = tf32f(v.x - h);
            h = tf32f(v.y); es_h[e * EPAD + c + 1] = h; es_l[e * EPAD + c + 1] = tf32f(v.y - h);
            h = tf32f(v.z); es_h[e * EPAD + c + 2] = h; es_l[e * EPAD + c + 2] = tf32f(v.z - h);
            h = tf32f(v.w); es_h[e * EPAD + c + 3] = h; es_l[e * EPAD + c + 3] = tf32f(v.w - h);
        }
    }
    if (tid < TE * 3) { int e = tid / 3; ev_sh[tid] = (e < nE) ? edge_v[(size_t)e0 * 3 + tid] : 0.f; }
    if (tid < TE) {
        int d = -1;
        if (tid < nE) { d = edge_index[E + e0 + tid]; atomicAdd(&g_cnt[d], 1.f); }
        dst_sh[tid] = d;
    }
    if (tid < 128) bes_sh[tid] = bes[tid];
    if (tid < 144) wev_sh[tid] = wev[tid];
    if (tid < 48)  bev_sh[tid] = bev[tid];
    __syncthreads();

    // ---- mma mainloop
    const int g   = lane >> 2;
    const int tig = lane & 3;
    const int m0  = (w >> 1) * 16;
    const int nh  = w & 1;

    float acc[8][4];
#pragma unroll
    for (int nt = 0; nt < 8; nt++)
#pragma unroll
        for (int i = 0; i < 4; i++) acc[nt][i] = 0.f;

    {
        const float* Ah = es_h + (m0 + g) * EPAD + tig;
        const float* Al = es_l + (m0 + g) * EPAD + tig;
        const float2* Bb = wB + nh * 8 * 32 + lane;
#pragma unroll
        for (int kt = 0; kt < 4; kt++) {
            const int ko = kt * 8;
            unsigned a0[4], a1[4];
            a0[0] = __float_as_uint(Ah[ko]);
            a0[1] = __float_as_uint(Ah[8 * EPAD + ko]);
            a0[2] = __float_as_uint(Ah[ko + 4]);
            a0[3] = __float_as_uint(Ah[8 * EPAD + ko + 4]);
            a1[0] = __float_as_uint(Al[ko]);
            a1[1] = __float_as_uint(Al[8 * EPAD + ko]);
            a1[2] = __float_as_uint(Al[ko + 4]);
            a1[3] = __float_as_uint(Al[8 * EPAD + ko + 4]);
#pragma unroll
            for (int nt = 0; nt < 8; nt++) {
                float2 bv = Bb[kt * 512 + nt * 32];
                unsigned b[2] = { __float_as_uint(bv.x), __float_as_uint(bv.y) };
                mma_tf32(acc[nt], a0, b);
                mma_tf32(acc[nt], a1, b);
            }
        }
    }
    __syncthreads();   // all reads of wB/es done -> sout overlay safe

    // ---- epilogue: bias + silu + gate; stage to sout
    {
        const int r0 = m0 + g, r1 = m0 + 8 + g;
#pragma unroll
        for (int nt = 0; nt < 8; nt++) {
            int c0 = nh * 64 + nt * 8 + tig * 2;
            float b0 = bes_sh[c0], b1 = bes_sh[c0 + 1];
            float v0 = acc[nt][0] + b0, v1 = acc[nt][1] + b1;
            float v2 = acc[nt][2] + b0, v3 = acc[nt][3] + b1;
            v0 *= sigf(v0); v1 *= sigf(v1); v2 *= sigf(v2); v3 *= sigf(v3);
            *(float2*)(sout + r0 * SPAD + c0) = make_float2(v0, v1);
            *(float2*)(sout + r1 * SPAD + c0) = make_float2(v2, v3);
            if (nh == 0 && c0 < 16) {
                gate_sh[r0 * 16 + c0]     = sigf(v0);
                gate_sh[r0 * 16 + c0 + 1] = sigf(v1);
                gate_sh[r1 * 16 + c0]     = sigf(v2);
                gate_sh[r1 * 16 + c0 + 1] = sigf(v3);
            }
        }
    }
    __syncthreads();

    // ---- scalar scatter (v6 scheme): warp wg -> 8 edges, lane = 4 outputs
#pragma unroll
    for (int j = 0; j < 8; j++) {
        int el = w * 8 + j;
        if (el >= nE) break;
        float4 s = *(const float4*)(sout + el * SPAD + 4 * lane);
        red4(g_agg + (size_t)dst_sh[el] * 176 + 4 * lane, s);
    }

    // ---- vector part: 12 float4-quads per edge (48 outputs)
    for (int p = tid; p < TE * 12; p += 256) {
        int el = p / 12;
        if (el >= nE) continue;
        int q = p % 12;
        float e0v = ev_sh[el * 3 + 0], e1v = ev_sh[el * 3 + 1], e2v = ev_sh[el * 3 + 2];
        float4 v; float* vp = (float*)&v;
#pragma unroll
        for (int i = 0; i < 4; i++) {
            int o = 4 * q + i;
            float val = fmaf(wev_sh[o * 3 + 0], e0v,
                        fmaf(wev_sh[o * 3 + 1], e1v,
                        fmaf(wev_sh[o * 3 + 2], e2v, bev_sh[o])));
            vp[i] = val * gate_sh[el * 16 + o / 3];
        }
        red4(g_agg + (size_t)dst_sh[el] * 176 + 128 + 4 * q, v);
    }
}

// ---------------------------------------------------------------------------
// Node kernel (launch #5; v8 verbatim): persistent, 512 threads, tf32 mma.
// ---------------------------------------------------------------------------
#define XPAD 132
#define NODE_SMEM_FLOATS 54240

__global__ __launch_bounds__(512) void node_kernel(
    const float* __restrict__ node_s, const float* __restrict__ node_v,
    const float* __restrict__ ln_g, const float* __restrict__ ln_b,
    const float* __restrict__ bns, const float* __restrict__ brs,
    const float* __restrict__ bnv, const float* __restrict__ brv,
    float* __restrict__ out, int Nn)
{
    extern __shared__ float smf[];
    float* wB   = smf;                 // 32768 (float2 frags)
    float* wVT  = wB + 32768;          // 4608
    float* xh   = wVT + 4608;          // 4224
    float* xl   = xh + 4224;           // 4224
    float* sh   = xl + 4224;           // 4224
    float* vn   = sh + 4224;           // 1536
    float* xv   = vn + 1536;           // 1536
    float* gate = xv + 1536;           // 512
    float* lng  = gate + 512;
    float* lnb  = lng + 128;
    float* bnsS = lnb + 128;
    float* brsS = bnsS + 128;
    float* bnvS = brsS + 128;
    float* brvS = bnvS + 48;

    const int tid  = threadIdx.x;
    const int lane = tid & 31;
    const int w    = tid >> 5;
    const int g    = lane >> 2;
    const int tig  = lane & 3;

    {
        float4* d = (float4*)wB; const float4* s = (const float4*)g_wB;
        for (int i = tid; i < 8192; i += 512) d[i] = s[i];
    }
    for (int i = tid; i < 4608; i += 512) wVT[i] = g_wVT[i];
    if (tid < 128) { lng[tid] = ln_g[tid]; lnb[tid] = ln_b[tid];
                     bnsS[tid] = bns[tid]; brsS[tid] = brs[tid]; }
    if (tid < 48)  { bnvS[tid] = bnv[tid]; brvS[tid] = brv[tid]; }

    const int mstrip = w >> 3;
    const int nstrip = w & 7;
    const int m0     = mstrip * 16;
    const bool wnsP  = (nstrip < 4);

    const int ntiles = (Nn + 31) / 32;
    for (int tile = blockIdx.x; tile < ntiles; tile += gridDim.x) {
        const int n0t = tile * 32;
        const int nN  = min(32, Nn - n0t);
        __syncthreads();

        for (int i = tid; i < 4096; i += 512) {
            int r = i >> 7, c = i & 127;
            sh[r * XPAD + c] = (i < nN * 128) ? node_s[(size_t)n0t * 128 + i] : 0.f;
        }
        for (int i = tid; i < 1536; i += 512)
            vn[i] = (i < nN * 48) ? node_v[(size_t)n0t * 48 + i] : 0.f;
        __syncthreads();

        for (int q = 0; q < 2; q++) {
            int r = w * 2 + q;
            int n = n0t + r;
            const float* row = sh + r * XPAD;
            float a = row[lane] + row[lane + 32] + row[lane + 64] + row[lane + 96];
#pragma unroll
            for (int o = 16; o; o >>= 1) a += __shfl_xor_sync(0xffffffffu, a, o);
            float mu = a * (1.f / 128.f);
            float d0 = row[lane] - mu, d1 = row[lane + 32] - mu;
            float d2 = row[lane + 64] - mu, d3 = row[lane + 96] - mu;
            float vv = d0 * d0 + d1 * d1 + d2 * d2 + d3 * d3;
#pragma unroll
            for (int o = 16; o; o >>= 1) vv += __shfl_xor_sync(0xffffffffu, vv, o);
            float rs = rsqrtf(vv * (1.f / 128.f) + 1e-5f);

            const float* vrow = vn + r * 48;
            float x0 = vrow[lane];
            float x1 = (lane < 16) ? vrow[32 + lane] : 0.f;
            float sq = x0 * x0 + x1 * x1;
#pragma unroll
            for (int o = 16; o; o >>= 1) sq += __shfl_xor_sync(0xffffffffu, sq, o);
            float vr = rsqrtf(sq * (1.f / 16.f) + 1e-8f);

            float invden = 0.f;
            const float* aggr = g_agg + (size_t)n * 176;
            if (r < nN) invden = 1.f / fmaxf(g_cnt[n], 1.f);

#pragma unroll
            for (int jj = 0; jj < 4; jj++) {
                int c = lane + 32 * jj;
                float x = (row[c] - mu) * rs * lng[c] + lnb[c];
                float xa = x;
                if (r < nN) xa = x + aggr[c] * invden;
                float hf = tf32f(xa);
                sh[r * XPAD + c] = tf32f(x);
                xh[r * XPAD + c] = hf;
                xl[r * XPAD + c] = tf32f(xa - hf);
            }
            {
                float x = x0 * vr;
                float xa = x;
                if (r < nN) xa = x + aggr[128 + lane] * invden;
                vn[r * 48 + lane] = x;
                xv[r * 48 + lane] = xa;
                if (lane < 16) {
                    float y = x1 * vr;
                    float ya = y;
                    if (r < nN) ya = y + aggr[128 + 32 + lane] * invden;
                    vn[r * 48 + 32 + lane] = y;
                    xv[r * 48 + 32 + lane] = ya;
                }
            }
        }
        __syncthreads();

        float acc[4][4];
#pragma unroll
        for (int nt = 0; nt < 4; nt++)
#pragma unroll
            for (int i = 0; i < 4; i++) acc[nt][i] = 0.f;

        {
            const int arow = (m0 + g) * XPAD + tig;
            const float2* Bb = ((const float2*)wB) + (nstrip * 4) * 32 + lane;
#pragma unroll 4
            for (int kt = 0; kt < 16; kt++) {
                const int ko = kt * 8;
                unsigned a0[4], a1[4];
                if (wnsP) {
                    a0[0] = __float_as_uint(xh[arow + ko]);
                    a0[1] = __float_as_uint(xh[arow + 8 * XPAD + ko]);
                    a0[2] = __float_as_uint(xh[arow + ko + 4]);
                    a0[3] = __float_as_uint(xh[arow + 8 * XPAD + ko + 4]);
                    a1[0] = __float_as_uint(xl[arow + ko]);
                    a1[1] = __float_as_uint(xl[arow + 8 * XPAD + ko]);
                    a1[2] = __float_as_uint(xl[arow + ko + 4]);
                    a1[3] = __float_as_uint(xl[arow + 8 * XPAD + ko + 4]);
                } else {
                    a0[0] = __float_as_uint(sh[arow + ko]);
                    a0[1] = __float_as_uint(sh[arow + 8 * XPAD + ko]);
                    a0[2] = __float_as_uint(sh[arow + ko + 4]);
                    a0[3] = __float_as_uint(sh[arow + 8 * XPAD + ko + 4]);
                }
#pragma unroll
                for (int nt = 0; nt < 4; nt++) {
                    float2 bv = Bb[kt * 1024 + nt * 32];
                    unsigned b[2] = { __float_as_uint(bv.x), __float_as_uint(bv.y) };
                    mma_tf32(acc[nt], a0, b);
                    if (wnsP) mma_tf32(acc[nt], a1, b);
                }
            }
        }
        __syncthreads();

        {
            const int r0 = m0 + g, r1 = m0 + 8 + g;
#pragma unroll
            for (int nt = 0; nt < 4; nt++) {
                int o = nstrip * 32 + nt * 8 + tig * 2;
                if (wnsP) {
                    float b0v = bnsS[o], b1v = bnsS[o + 1];
                    float v0 = acc[nt][0] + b0v, v1 = acc[nt][1] + b1v;
                    float v2 = acc[nt][2] + b0v, v3 = acc[nt][3] + b1v;
                    v0 *= sigf(v0); v1 *= sigf(v1); v2 *= sigf(v2); v3 *= sigf(v3);
                    xh[r0 * XPAD + o]     = v0;
                    xh[r0 * XPAD + o + 1] = v1;
                    xh[r1 * XPAD + o]     = v2;
                    xh[r1 * XPAD + o + 1] = v3;
                    if (o < 16) {
                        gate[r0 * 16 + o]     = sigf(v0);
                        gate[r0 * 16 + o + 1] = sigf(v1);
                        gate[r1 * 16 + o]     = sigf(v2);
                        gate[r1 * 16 + o + 1] = sigf(v3);
                    }
                } else {
                    int oc = o - 128;
                    float b0v = brsS[oc], b1v = brsS[oc + 1];
                    xl[r0 * XPAD + oc]     = acc[nt][0] + b0v;
                    xl[r0 * XPAD + oc + 1] = acc[nt][1] + b1v;
                    xl[r1 * XPAD + oc]     = acc[nt][2] + b0v;
                    xl[r1 * XPAD + oc + 1] = acc[nt][3] + b1v;
                }
            }
        }
        __syncthreads();

        for (int i = tid; i < nN * 128; i += 512) {
            int r = i >> 7, c = i & 127;
            out[(size_t)n0t * 128 + i] = xh[r * XPAD + c] + xl[r * XPAD + c];
        }

        for (int p = tid; p < nN * 48; p += 512) {
            int r = p / 48, o = p % 48;
            const float* xvr = xv + r * 48;
            const float* vnr = vn + r * 48;
            float a = 0.f, bq = 0.f;
#pragma unroll 4
            for (int k = 0; k < 48; k++) {
                a  = fmaf(xvr[k], wVT[k * 96 + o],      a);
                bq = fmaf(vnr[k], wVT[k * 96 + 48 + o], bq);
            }
            float val = (a + bnvS[o]) * gate[r * 16 + o / 3] + bq + brvS[o];
            out[(size_t)Nn * 128 + (size_t)n0t * 48 + p] = val;
        }
    }
}

// ---------------------------------------------------------------------------
extern "C" void kernel_launch(void* const* d_in, const int* in_sizes, int n_in,
                              void* d_out, int out_size)
{
    const float* node_s = (const float*)d_in[0];
    const float* node_v = (const float*)d_in[1];
    const int*   ei     = (const int*)  d_in[2];
    const float* edge_s = (const float*)d_in[3];
    const float* edge_v = (const float*)d_in[4];
    const float* ln_g   = (const float*)d_in[5];
    const float* ln_b   = (const float*)d_in[6];
    const float* wes    = (const float*)d_in[7];
    const float* bes    = (const float*)d_in[8];
    const float* wev    = (const float*)d_in[9];
    const float* bev    = (const float*)d_in[10];
    const float* wns    = (const float*)d_in[11];
    const float* bns    = (const float*)d_in[12];
    const float* wnv    = (const float*)d_in[13];
    const float* bnv    = (const float*)d_in[14];
    const float* wrs    = (const float*)d_in[15];
    const float* brs    = (const float*)d_in[16];
    const float* wrv    = (const float*)d_in[17];
    const float* brv    = (const float*)d_in[18];

    const int N = in_sizes[0] / 128;
    const int E = in_sizes[3] / 32;

    cudaFuncSetAttribute(node_kernel, cudaFuncAttributeMaxDynamicSharedMemorySize,
                         NODE_SMEM_FLOATS * sizeof(float));

    prep_kernel<<<64, 256>>>(wes, wns, wrs, wnv, wrv);             // #1
    zero_agg_kernel<<<(N * 44 + 255) / 256, 256>>>(N);             // #2
    zero_cnt_kernel<<<(N + 255) / 256, 256>>>(N);                  // #3
    edge_kernel<<<(E + TE - 1) / TE, 256>>>(edge_s, edge_v, ei,    // #4 (ncu)
                                            bes, wev, bev, E);
    node_kernel<<<152, 512, NODE_SMEM_FLOATS * sizeof(float)>>>(   // #5
        node_s, node_v, ln_g, ln_b, bns, brs, bnv, brv, (float*)d_out, N);
}

// round 11
// speedup vs baseline: 2.4020x; 1.0093x over previous
#include <cuda_runtime.h>

// ---------------------------------------------------------------------------
// MultiGVPConvLayer fused, v10: edge mma slimmed (single-tf32 A, float4
// staging, div-free vector epilogue); node v8 kernel unchanged.
//   Launch order: prep, zero_agg, zero_cnt, edge (#4 -> ncu), node
//   Output: concat( out_s [N,128], out_v [N,48] ) float32
// ---------------------------------------------------------------------------

#define NMAX 50000
#define TE 64
#define EPAD 36
#define SPAD 132

__device__ float  g_agg[(size_t)NMAX * 176];  // per-node [128 s | 48 v] sums
__device__ float  g_cnt[NMAX];                // in-degree counts
__device__ float2 g_wesB[2048];               // edge B-frags [kt4][ntg16][lane32] tf32
__device__ float2 g_wB[16384];                // node B-frags [kt16][ntg32][lane32] tf32
__device__ float  g_wVT[48 * 96];             // [k][ wnv_out(48) | wrv_out(48) ]

__device__ __forceinline__ float sigf(float x) { return 1.f / (1.f + __expf(-x)); }

__device__ __forceinline__ void red4(float* p, float4 v) {
    asm volatile("red.global.add.v4.f32 [%0], {%1,%2,%3,%4};"
                 :: "l"(p), "f"(v.x), "f"(v.y), "f"(v.z), "f"(v.w) : "memory");
}

__device__ __forceinline__ unsigned tf32u(float f) {
    unsigned u;
    asm("cvt.rna.tf32.f32 %0, %1;" : "=r"(u) : "f"(f));
    return u;
}
__device__ __forceinline__ float tf32f(float f) { return __uint_as_float(tf32u(f)); }

__device__ __forceinline__ void mma_tf32(float* d, const unsigned* a, const unsigned* b) {
    asm volatile(
        "mma.sync.aligned.m16n8k8.row.col.f32.tf32.tf32.f32 "
        "{%0,%1,%2,%3}, {%4,%5,%6,%7}, {%8,%9}, {%0,%1,%2,%3};"
        : "+f"(d[0]), "+f"(d[1]), "+f"(d[2]), "+f"(d[3])
        : "r"(a[0]), "r"(a[1]), "r"(a[2]), "r"(a[3]), "r"(b[0]), "r"(b[1]));
}

// ---------------------------------------------------------------------------
__global__ void prep_kernel(const float* __restrict__ wes,     // launch #1
                            const float* __restrict__ wns, const float* __restrict__ wrs,
                            const float* __restrict__ wnv, const float* __restrict__ wrv)
{
    int t = blockIdx.x * 256 + threadIdx.x;
    if (t < 2048) {             // edge B frags (K=32 -> 4 kt, 16 ntg)
        int lane = t & 31, ntg = (t >> 5) & 15, kt = t >> 9;
        int g = lane >> 2, tig = lane & 3;
        int k = kt * 8 + tig;
        int n = ntg * 8 + g;
        g_wesB[t] = make_float2(tf32f(wes[n * 32 + k]), tf32f(wes[n * 32 + k + 4]));
    }
    if (t < 16384) {            // node B frags (K=128 -> 16 kt, 32 ntg)
        int lane = t & 31, ntg = (t >> 5) & 31, kt = t >> 10;
        int g = lane >> 2, tig = lane & 3;
        int k = kt * 8 + tig;
        int n = ntg * 8 + g;
        const float* srow = (n < 128) ? (wns + n * 128) : (wrs + (n - 128) * 128);
        g_wB[t] = make_float2(tf32f(srow[k]), tf32f(srow[k + 4]));
    }
    if (t < 48 * 48) { int o = t / 48, k = t % 48; g_wVT[k * 96 + o] = wnv[t];
                                                   g_wVT[k * 96 + 48 + o] = wrv[t]; }
}

__global__ void zero_agg_kernel(int Nn)                        // launch #2
{
    size_t t = (size_t)blockIdx.x * 256 + threadIdx.x;
    if (t < (size_t)Nn * 44) ((float4*)g_agg)[t] = make_float4(0.f, 0.f, 0.f, 0.f);
}
__global__ void zero_cnt_kernel(int Nn)                        // launch #3
{
    int t = blockIdx.x * 256 + threadIdx.x;
    if (t < Nn) g_cnt[t] = 0.f;
}

// ---------------------------------------------------------------------------
// Edge kernel (launch #4 -> ncu). 64 edges / 256 threads (8 warps).
// mma: warp w -> mstrip = w>>1 (16 edges), nhalf = w&1 (64 outputs, 8 ntiles).
// A single tf32 (no hi/lo). smem union: [B | es_h] overlaid by sout after mma.
// ---------------------------------------------------------------------------
__global__ __launch_bounds__(256) void edge_kernel(
    const float* __restrict__ edge_s, const float* __restrict__ edge_v,
    const int* __restrict__ edge_index,
    const float* __restrict__ bes, const float* __restrict__ wev,
    const float* __restrict__ bev, int E)
{
    __shared__ char  uni[33792];         // B 16384 | es_h 9216 | (sout 64x132x4)
    __shared__ float ev_sh[TE * 3];
    __shared__ int   dst_sh[TE];
    __shared__ float gate_sh[TE * 16];
    __shared__ float bes_sh[128];
    __shared__ float wev_sh[144];
    __shared__ float bev_sh[48];

    float2* wB   = (float2*)uni;                       // during mma
    float*  es_h = (float*)(uni + 16384);              // [64][36]
    float*  sout = (float*)uni;                        // [64][132] after mma

    const int tid  = threadIdx.x;
    const int lane = tid & 31;
    const int w    = tid >> 5;
    const int e0   = blockIdx.x * TE;
    const int nE   = min(TE, E - e0);

    // ---- stage: B frags + edge_s (single tf32, float4 stores) + params
    {
        const float4* s = (const float4*)g_wesB;       // 1024 float4
        float4* d = (float4*)wB;
        for (int i = tid; i < 1024; i += 256) d[i] = s[i];
    }
    {
        const float4* s4 = (const float4*)(edge_s + (size_t)e0 * 32);
        for (int i = tid; i < TE * 8; i += 256) {
            int e = i >> 3, c = (i & 7) * 4;
            float4 v = (e < nE) ? s4[i] : make_float4(0.f, 0.f, 0.f, 0.f);
            float4 h;
            h.x = tf32f(v.x); h.y = tf32f(v.y); h.z = tf32f(v.z); h.w = tf32f(v.w);
            *(float4*)(es_h + e * EPAD + c) = h;
        }
    }
    if (tid < TE * 3) { int e = tid / 3; ev_sh[tid] = (e < nE) ? edge_v[(size_t)e0 * 3 + tid] : 0.f; }
    if (tid < TE) {
        int d = -1;
        if (tid < nE) { d = edge_index[E + e0 + tid]; atomicAdd(&g_cnt[d], 1.f); }
        dst_sh[tid] = d;
    }
    if (tid < 128) bes_sh[tid] = bes[tid];
    if (tid < 144) wev_sh[tid] = wev[tid];
    if (tid < 48)  bev_sh[tid] = bev[tid];
    __syncthreads();

    // ---- mma mainloop (A single tf32)
    const int g   = lane >> 2;
    const int tig = lane & 3;
    const int m0  = (w >> 1) * 16;
    const int nh  = w & 1;

    float acc[8][4];
#pragma unroll
    for (int nt = 0; nt < 8; nt++)
#pragma unroll
        for (int i = 0; i < 4; i++) acc[nt][i] = 0.f;

    {
        const float* Ah = es_h + (m0 + g) * EPAD + tig;
        const float2* Bb = wB + nh * 8 * 32 + lane;
#pragma unroll
        for (int kt = 0; kt < 4; kt++) {
            const int ko = kt * 8;
            unsigned a0[4];
            a0[0] = __float_as_uint(Ah[ko]);
            a0[1] = __float_as_uint(Ah[8 * EPAD + ko]);
            a0[2] = __float_as_uint(Ah[ko + 4]);
            a0[3] = __float_as_uint(Ah[8 * EPAD + ko + 4]);
#pragma unroll
            for (int nt = 0; nt < 8; nt++) {
                float2 bv = Bb[kt * 512 + nt * 32];
                unsigned b[2] = { __float_as_uint(bv.x), __float_as_uint(bv.y) };
                mma_tf32(acc[nt], a0, b);
            }
        }
    }
    __syncthreads();   // all reads of wB/es_h done -> sout overlay safe

    // ---- epilogue: bias + silu + gate; stage to sout
    {
        const int r0 = m0 + g, r1 = m0 + 8 + g;
#pragma unroll
        for (int nt = 0; nt < 8; nt++) {
            int c0 = nh * 64 + nt * 8 + tig * 2;
            float b0 = bes_sh[c0], b1 = bes_sh[c0 + 1];
            float v0 = acc[nt][0] + b0, v1 = acc[nt][1] + b1;
            float v2 = acc[nt][2] + b0, v3 = acc[nt][3] + b1;
            v0 *= sigf(v0); v1 *= sigf(v1); v2 *= sigf(v2); v3 *= sigf(v3);
            *(float2*)(sout + r0 * SPAD + c0) = make_float2(v0, v1);
            *(float2*)(sout + r1 * SPAD + c0) = make_float2(v2, v3);
            if (nh == 0 && c0 < 16) {
                gate_sh[r0 * 16 + c0]     = sigf(v0);
                gate_sh[r0 * 16 + c0 + 1] = sigf(v1);
                gate_sh[r1 * 16 + c0]     = sigf(v2);
                gate_sh[r1 * 16 + c0 + 1] = sigf(v3);
            }
        }
    }
    __syncthreads();

    // ---- scalar scatter: warp w -> 8 edges, lane = 4 outputs
#pragma unroll
    for (int j = 0; j < 8; j++) {
        int el = w * 8 + j;
        if (el >= nE) break;
        float4 s = *(const float4*)(sout + el * SPAD + 4 * lane);
        red4(g_agg + (size_t)dst_sh[el] * 176 + 4 * lane, s);
    }

    // ---- vector part: 192 threads; thread = (q, sub) -> quad q over 4 edges
    if (tid < 192) {
        const int q   = tid >> 4;        // 0..11 -> outputs 4q..4q+3
        const int sub = tid & 15;        // edge stride 16
        float w0[4], w1[4], w2[4], bq[4];
        int   gi[4];
#pragma unroll
        for (int i = 0; i < 4; i++) {
            int o = 4 * q + i;
            w0[i] = wev_sh[o * 3 + 0]; w1[i] = wev_sh[o * 3 + 1];
            w2[i] = wev_sh[o * 3 + 2]; bq[i] = bev_sh[o];
            gi[i] = o / 3;               // constant-div, hoisted
        }
#pragma unroll
        for (int j = 0; j < 4; j++) {
            int el = sub + 16 * j;
            if (el >= nE) continue;
            float e0v = ev_sh[el * 3 + 0], e1v = ev_sh[el * 3 + 1], e2v = ev_sh[el * 3 + 2];
            float4 v; float* vp = (float*)&v;
#pragma unroll
            for (int i = 0; i < 4; i++) {
                float val = fmaf(w0[i], e0v, fmaf(w1[i], e1v, fmaf(w2[i], e2v, bq[i])));
                vp[i] = val * gate_sh[el * 16 + gi[i]];
            }
            red4(g_agg + (size_t)dst_sh[el] * 176 + 128 + 4 * q, v);
        }
    }
}

// ---------------------------------------------------------------------------
// Node kernel (launch #5; v8 verbatim): persistent, 512 threads, tf32 mma.
// ---------------------------------------------------------------------------
#define XPAD 132
#define NODE_SMEM_FLOATS 54240

__global__ __launch_bounds__(512) void node_kernel(
    const float* __restrict__ node_s, const float* __restrict__ node_v,
    const float* __restrict__ ln_g, const float* __restrict__ ln_b,
    const float* __restrict__ bns, const float* __restrict__ brs,
    const float* __restrict__ bnv, const float* __restrict__ brv,
    float* __restrict__ out, int Nn)
{
    extern __shared__ float smf[];
    float* wB   = smf;                 // 32768 (float2 frags)
    float* wVT  = wB + 32768;          // 4608
    float* xh   = wVT + 4608;          // 4224
    float* xl   = xh + 4224;           // 4224
    float* sh   = xl + 4224;           // 4224
    float* vn   = sh + 4224;           // 1536
    float* xv   = vn + 1536;           // 1536
    float* gate = xv + 1536;           // 512
    float* lng  = gate + 512;
    float* lnb  = lng + 128;
    float* bnsS = lnb + 128;
    float* brsS = bnsS + 128;
    float* bnvS = brsS + 128;
    float* brvS = bnvS + 48;

    const int tid  = threadIdx.x;
    const int lane = tid & 31;
    const int w    = tid >> 5;
    const int g    = lane >> 2;
    const int tig  = lane & 3;

    {
        float4* d = (float4*)wB; const float4* s = (const float4*)g_wB;
        for (int i = tid; i < 8192; i += 512) d[i] = s[i];
    }
    for (int i = tid; i < 4608; i += 512) wVT[i] = g_wVT[i];
    if (tid < 128) { lng[tid] = ln_g[tid]; lnb[tid] = ln_b[tid];
                     bnsS[tid] = bns[tid]; brsS[tid] = brs[tid]; }
    if (tid < 48)  { bnvS[tid] = bnv[tid]; brvS[tid] = brv[tid]; }

    const int mstrip = w >> 3;
    const int nstrip = w & 7;
    const int m0     = mstrip * 16;
    const bool wnsP  = (nstrip < 4);

    const int ntiles = (Nn + 31) / 32;
    for (int tile = blockIdx.x; tile < ntiles; tile += gridDim.x) {
        const int n0t = tile * 32;
        const int nN  = min(32, Nn - n0t);
        __syncthreads();

        for (int i = tid; i < 4096; i += 512) {
            int r = i >> 7, c = i & 127;
            sh[r * XPAD + c] = (i < nN * 128) ? node_s[(size_t)n0t * 128 + i] : 0.f;
        }
        for (int i = tid; i < 1536; i += 512)
            vn[i] = (i < nN * 48) ? node_v[(size_t)n0t * 48 + i] : 0.f;
        __syncthreads();

        for (int q = 0; q < 2; q++) {
            int r = w * 2 + q;
            int n = n0t + r;
            const float* row = sh + r * XPAD;
            float a = row[lane] + row[lane + 32] + row[lane + 64] + row[lane + 96];
#pragma unroll
            for (int o = 16; o; o >>= 1) a += __shfl_xor_sync(0xffffffffu, a, o);
            float mu = a * (1.f / 128.f);
            float d0 = row[lane] - mu, d1 = row[lane + 32] - mu;
            float d2 = row[lane + 64] - mu, d3 = row[lane + 96] - mu;
            float vv = d0 * d0 + d1 * d1 + d2 * d2 + d3 * d3;
#pragma unroll
            for (int o = 16; o; o >>= 1) vv += __shfl_xor_sync(0xffffffffu, vv, o);
            float rs = rsqrtf(vv * (1.f / 128.f) + 1e-5f);

            const float* vrow = vn + r * 48;
            float x0 = vrow[lane];
            float x1 = (lane < 16) ? vrow[32 + lane] : 0.f;
            float sq = x0 * x0 + x1 * x1;
#pragma unroll
            for (int o = 16; o; o >>= 1) sq += __shfl_xor_sync(0xffffffffu, sq, o);
            float vr = rsqrtf(sq * (1.f / 16.f) + 1e-8f);

            float invden = 0.f;
            const float* aggr = g_agg + (size_t)n * 176;
            if (r < nN) invden = 1.f / fmaxf(g_cnt[n], 1.f);

#pragma unroll
            for (int jj = 0; jj < 4; jj++) {
                int c = lane + 32 * jj;
                float x = (row[c] - mu) * rs * lng[c] + lnb[c];
                float xa = x;
                if (r < nN) xa = x + aggr[c] * invden;
                float hf = tf32f(xa);
                sh[r * XPAD + c] = tf32f(x);
                xh[r * XPAD + c] = hf;
                xl[r * XPAD + c] = tf32f(xa - hf);
            }
            {
                float x = x0 * vr;
                float xa = x;
                if (r < nN) xa = x + aggr[128 + lane] * invden;
                vn[r * 48 + lane] = x;
                xv[r * 48 + lane] = xa;
                if (lane < 16) {
                    float y = x1 * vr;
                    float ya = y;
                    if (r < nN) ya = y + aggr[128 + 32 + lane] * invden;
                    vn[r * 48 + 32 + lane] = y;
                    xv[r * 48 + 32 + lane] = ya;
                }
            }
        }
        __syncthreads();

        float acc[4][4];
#pragma unroll
        for (int nt = 0; nt < 4; nt++)
#pragma unroll
            for (int i = 0; i < 4; i++) acc[nt][i] = 0.f;

        {
            const int arow = (m0 + g) * XPAD + tig;
            const float2* Bb = ((const float2*)wB) + (nstrip * 4) * 32 + lane;
#pragma unroll 4
            for (int kt = 0; kt < 16; kt++) {
                const int ko = kt * 8;
                unsigned a0[4], a1[4];
                if (wnsP) {
                    a0[0] = __float_as_uint(xh[arow + ko]);
                    a0[1] = __float_as_uint(xh[arow + 8 * XPAD + ko]);
                    a0[2] = __float_as_uint(xh[arow + ko + 4]);
                    a0[3] = __float_as_uint(xh[arow + 8 * XPAD + ko + 4]);
                    a1[0] = __float_as_uint(xl[arow + ko]);
                    a1[1] = __float_as_uint(xl[arow + 8 * XPAD + ko]);
                    a1[2] = __float_as_uint(xl[arow + ko + 4]);
                    a1[3] = __float_as_uint(xl[arow + 8 * XPAD + ko + 4]);
                } else {
                    a0[0] = __float_as_uint(sh[arow + ko]);
                    a0[1] = __float_as_uint(sh[arow + 8 * XPAD + ko]);
                    a0[2] = __float_as_uint(sh[arow + ko + 4]);
                    a0[3] = __float_as_uint(sh[arow + 8 * XPAD + ko + 4]);
                }
#pragma unroll
                for (int nt = 0; nt < 4; nt++) {
                    float2 bv = Bb[kt * 1024 + nt * 32];
                    unsigned b[2] = { __float_as_uint(bv.x), __float_as_uint(bv.y) };
                    mma_tf32(acc[nt], a0, b);
                    if (wnsP) mma_tf32(acc[nt], a1, b);
                }
            }
        }
        __syncthreads();

        {
            const int r0 = m0 + g, r1 = m0 + 8 + g;
#pragma unroll
            for (int nt = 0; nt < 4; nt++) {
                int o = nstrip * 32 + nt * 8 + tig * 2;
                if (wnsP) {
                    float b0v = bnsS[o], b1v = bnsS[o + 1];
                    float v0 = acc[nt][0] + b0v, v1 = acc[nt][1] + b1v;
                    float v2 = acc[nt][2] + b0v, v3 = acc[nt][3] + b1v;
                    v0 *= sigf(v0); v1 *= sigf(v1); v2 *= sigf(v2); v3 *= sigf(v3);
                    xh[r0 * XPAD + o]     = v0;
                    xh[r0 * XPAD + o + 1] = v1;
                    xh[r1 * XPAD + o]     = v2;
                    xh[r1 * XPAD + o + 1] = v3;
                    if (o < 16) {
                        gate[r0 * 16 + o]     = sigf(v0);
                        gate[r0 * 16 + o + 1] = sigf(v1);
                        gate[r1 * 16 + o]     = sigf(v2);
                        gate[r1 * 16 + o + 1] = sigf(v3);
                    }
                } else {
                    int oc = o - 128;
                    float b0v = brsS[oc], b1v = brsS[oc + 1];
                    xl[r0 * XPAD + oc]     = acc[nt][0] + b0v;
                    xl[r0 * XPAD + oc + 1] = acc[nt][1] + b1v;
                    xl[r1 * XPAD + oc]     = acc[nt][2] + b0v;
                    xl[r1 * XPAD + oc + 1] = acc[nt][3] + b1v;
                }
            }
        }
        __syncthreads();

        for (int i = tid; i < nN * 128; i += 512) {
            int r = i >> 7, c = i & 127;
            out[(size_t)n0t * 128 + i] = xh[r * XPAD + c] + xl[r * XPAD + c];
        }

        for (int p = tid; p < nN * 48; p += 512) {
            int r = p / 48, o = p % 48;
            const float* xvr = xv + r * 48;
            const float* vnr = vn + r * 48;
            float a = 0.f, bq = 0.f;
#pragma unroll 4
            for (int k = 0; k < 48; k++) {
                a  = fmaf(xvr[k], wVT[k * 96 + o],      a);
                bq = fmaf(vnr[k], wVT[k * 96 + 48 + o], bq);
            }
            float val = (a + bnvS[o]) * gate[r * 16 + o / 3] + bq + brvS[o];
            out[(size_t)Nn * 128 + (size_t)n0t * 48 + p] = val;
        }
    }
}

// ---------------------------------------------------------------------------
extern "C" void kernel_launch(void* const* d_in, const int* in_sizes, int n_in,
                              void* d_out, int out_size)
{
    const float* node_s = (const float*)d_in[0];
    const float* node_v = (const float*)d_in[1];
    const int*   ei     = (const int*)  d_in[2];
    const float* edge_s = (const float*)d_in[3];
    const float* edge_v = (const float*)d_in[4];
    const float* ln_g   = (const float*)d_in[5];
    const float* ln_b   = (const float*)d_in[6];
    const float* wes    = (const float*)d_in[7];
    const float* bes    = (const float*)d_in[8];
    const float* wev    = (const float*)d_in[9];
    const float* bev    = (const float*)d_in[10];
    const float* wns    = (const float*)d_in[11];
    const float* bns    = (const float*)d_in[12];
    const float* wnv    = (const float*)d_in[13];
    const float* bnv    = (const float*)d_in[14];
    const float* wrs    = (const float*)d_in[15];
    const float* brs    = (const float*)d_in[16];
    const float* wrv    = (const float*)d_in[17];
    const float* brv    = (const float*)d_in[18];

    const int N = in_sizes[0] / 128;
    const int E = in_sizes[3] / 32;

    cudaFuncSetAttribute(node_kernel, cudaFuncAttributeMaxDynamicSharedMemorySize,
                         NODE_SMEM_FLOATS * sizeof(float));

    prep_kernel<<<64, 256>>>(wes, wns, wrs, wnv, wrv);             // #1
    zero_agg_kernel<<<(N * 44 + 255) / 256, 256>>>(N);             // #2
    zero_cnt_kernel<<<(N + 255) / 256, 256>>>(N);                  // #3
    edge_kernel<<<(E + TE - 1) / TE, 256>>>(edge_s, edge_v, ei,    // #4 (ncu)
                                            bes, wev, bev, E);
    node_kernel<<<152, 512, NODE_SMEM_FLOATS * sizeof(float)>>>(   // #5
        node_s, node_v, ln_g, ln_b, bns, brs, bnv, brv, (float*)d_out, N);
}

// round 12
// speedup vs baseline: 2.7746x; 1.1551x over previous
#include <cuda_runtime.h>

// ---------------------------------------------------------------------------
// MultiGVPConvLayer fused, v11: node weights moved smem -> L2 (__ldg), smem
// 212KB -> 86KB => 2 blocks/SM (occ 2x). Edge kernel = v10 verbatim.
//   Launch order: prep(+cnt), zero_agg, edge, node (#4 -> ncu)
//   Output: concat( out_s [N,128], out_v [N,48] ) float32
// ---------------------------------------------------------------------------

#define NMAX 50000
#define TE 64
#define EPAD 36
#define SPAD 132

__device__ float  g_agg[(size_t)NMAX * 176];  // per-node [128 s | 48 v] sums
__device__ float  g_cnt[NMAX];                // in-degree counts
__device__ float2 g_wesB[2048];               // edge B-frags [kt4][ntg16][lane32] tf32
__device__ float2 g_wB[16384];                // node B-frags [kt16][ntg32][lane32] tf32
__device__ float  g_wVT[48 * 96];             // [k][ wnv_out(48) | wrv_out(48) ]

__device__ __forceinline__ float sigf(float x) { return 1.f / (1.f + __expf(-x)); }

__device__ __forceinline__ void red4(float* p, float4 v) {
    asm volatile("red.global.add.v4.f32 [%0], {%1,%2,%3,%4};"
                 :: "l"(p), "f"(v.x), "f"(v.y), "f"(v.z), "f"(v.w) : "memory");
}

__device__ __forceinline__ unsigned tf32u(float f) {
    unsigned u;
    asm("cvt.rna.tf32.f32 %0, %1;" : "=r"(u) : "f"(f));
    return u;
}
__device__ __forceinline__ float tf32f(float f) { return __uint_as_float(tf32u(f)); }

__device__ __forceinline__ void mma_tf32(float* d, const unsigned* a, const unsigned* b) {
    asm volatile(
        "mma.sync.aligned.m16n8k8.row.col.f32.tf32.tf32.f32 "
        "{%0,%1,%2,%3}, {%4,%5,%6,%7}, {%8,%9}, {%0,%1,%2,%3};"
        : "+f"(d[0]), "+f"(d[1]), "+f"(d[2]), "+f"(d[3])
        : "r"(a[0]), "r"(a[1]), "r"(a[2]), "r"(a[3]), "r"(b[0]), "r"(b[1]));
}

// ---------------------------------------------------------------------------
__global__ void prep_kernel(const float* __restrict__ wes,     // launch #1
                            const float* __restrict__ wns, const float* __restrict__ wrs,
                            const float* __restrict__ wnv, const float* __restrict__ wrv,
                            int Nn)
{
    int t = blockIdx.x * 256 + threadIdx.x;
    if (t < 2048) {             // edge B frags (K=32 -> 4 kt, 16 ntg)
        int lane = t & 31, ntg = (t >> 5) & 15, kt = t >> 9;
        int g = lane >> 2, tig = lane & 3;
        int k = kt * 8 + tig;
        int n = ntg * 8 + g;
        g_wesB[t] = make_float2(tf32f(wes[n * 32 + k]), tf32f(wes[n * 32 + k + 4]));
    }
    if (t < 16384) {            // node B frags (K=128 -> 16 kt, 32 ntg)
        int lane = t & 31, ntg = (t >> 5) & 31, kt = t >> 10;
        int g = lane >> 2, tig = lane & 3;
        int k = kt * 8 + tig;
        int n = ntg * 8 + g;
        const float* srow = (n < 128) ? (wns + n * 128) : (wrs + (n - 128) * 128);
        g_wB[t] = make_float2(tf32f(srow[k]), tf32f(srow[k + 4]));
    }
    if (t < 48 * 48) { int o = t / 48, k = t % 48; g_wVT[k * 96 + o] = wnv[t];
                                                   g_wVT[k * 96 + 48 + o] = wrv[t]; }
    if (t < Nn) g_cnt[t] = 0.f;
}

__global__ void zero_agg_kernel(int Nn)                        // launch #2
{
    size_t t = (size_t)blockIdx.x * 256 + threadIdx.x;
    if (t < (size_t)Nn * 44) ((float4*)g_agg)[t] = make_float4(0.f, 0.f, 0.f, 0.f);
}

// ---------------------------------------------------------------------------
// Edge kernel (launch #3; v10 verbatim). 64 edges / 256 threads.
// ---------------------------------------------------------------------------
__global__ __launch_bounds__(256) void edge_kernel(
    const float* __restrict__ edge_s, const float* __restrict__ edge_v,
    const int* __restrict__ edge_index,
    const float* __restrict__ bes, const float* __restrict__ wev,
    const float* __restrict__ bev, int E)
{
    __shared__ char  uni[33792];         // B 16384 | es_h 9216 | (sout 64x132x4)
    __shared__ float ev_sh[TE * 3];
    __shared__ int   dst_sh[TE];
    __shared__ float gate_sh[TE * 16];
    __shared__ float bes_sh[128];
    __shared__ float wev_sh[144];
    __shared__ float bev_sh[48];

    float2* wB   = (float2*)uni;
    float*  es_h = (float*)(uni + 16384);
    float*  sout = (float*)uni;

    const int tid  = threadIdx.x;
    const int lane = tid & 31;
    const int w    = tid >> 5;
    const int e0   = blockIdx.x * TE;
    const int nE   = min(TE, E - e0);

    {
        const float4* s = (const float4*)g_wesB;
        float4* d = (float4*)wB;
        for (int i = tid; i < 1024; i += 256) d[i] = s[i];
    }
    {
        const float4* s4 = (const float4*)(edge_s + (size_t)e0 * 32);
        for (int i = tid; i < TE * 8; i += 256) {
            int e = i >> 3, c = (i & 7) * 4;
            float4 v = (e < nE) ? s4[i] : make_float4(0.f, 0.f, 0.f, 0.f);
            float4 h;
            h.x = tf32f(v.x); h.y = tf32f(v.y); h.z = tf32f(v.z); h.w = tf32f(v.w);
            *(float4*)(es_h + e * EPAD + c) = h;
        }
    }
    if (tid < TE * 3) { int e = tid / 3; ev_sh[tid] = (e < nE) ? edge_v[(size_t)e0 * 3 + tid] : 0.f; }
    if (tid < TE) {
        int d = -1;
        if (tid < nE) { d = edge_index[E + e0 + tid]; atomicAdd(&g_cnt[d], 1.f); }
        dst_sh[tid] = d;
    }
    if (tid < 128) bes_sh[tid] = bes[tid];
    if (tid < 144) wev_sh[tid] = wev[tid];
    if (tid < 48)  bev_sh[tid] = bev[tid];
    __syncthreads();

    const int g   = lane >> 2;
    const int tig = lane & 3;
    const int m0  = (w >> 1) * 16;
    const int nh  = w & 1;

    float acc[8][4];
#pragma unroll
    for (int nt = 0; nt < 8; nt++)
#pragma unroll
        for (int i = 0; i < 4; i++) acc[nt][i] = 0.f;

    {
        const float* Ah = es_h + (m0 + g) * EPAD + tig;
        const float2* Bb = wB + nh * 8 * 32 + lane;
#pragma unroll
        for (int kt = 0; kt < 4; kt++) {
            const int ko = kt * 8;
            unsigned a0[4];
            a0[0] = __float_as_uint(Ah[ko]);
            a0[1] = __float_as_uint(Ah[8 * EPAD + ko]);
            a0[2] = __float_as_uint(Ah[ko + 4]);
            a0[3] = __float_as_uint(Ah[8 * EPAD + ko + 4]);
#pragma unroll
            for (int nt = 0; nt < 8; nt++) {
                float2 bv = Bb[kt * 512 + nt * 32];
                unsigned b[2] = { __float_as_uint(bv.x), __float_as_uint(bv.y) };
                mma_tf32(acc[nt], a0, b);
            }
        }
    }
    __syncthreads();

    {
        const int r0 = m0 + g, r1 = m0 + 8 + g;
#pragma unroll
        for (int nt = 0; nt < 8; nt++) {
            int c0 = nh * 64 + nt * 8 + tig * 2;
            float b0 = bes_sh[c0], b1 = bes_sh[c0 + 1];
            float v0 = acc[nt][0] + b0, v1 = acc[nt][1] + b1;
            float v2 = acc[nt][2] + b0, v3 = acc[nt][3] + b1;
            v0 *= sigf(v0); v1 *= sigf(v1); v2 *= sigf(v2); v3 *= sigf(v3);
            *(float2*)(sout + r0 * SPAD + c0) = make_float2(v0, v1);
            *(float2*)(sout + r1 * SPAD + c0) = make_float2(v2, v3);
            if (nh == 0 && c0 < 16) {
                gate_sh[r0 * 16 + c0]     = sigf(v0);
                gate_sh[r0 * 16 + c0 + 1] = sigf(v1);
                gate_sh[r1 * 16 + c0]     = sigf(v2);
                gate_sh[r1 * 16 + c0 + 1] = sigf(v3);
            }
        }
    }
    __syncthreads();

#pragma unroll
    for (int j = 0; j < 8; j++) {
        int el = w * 8 + j;
        if (el >= nE) break;
        float4 s = *(const float4*)(sout + el * SPAD + 4 * lane);
        red4(g_agg + (size_t)dst_sh[el] * 176 + 4 * lane, s);
    }

    if (tid < 192) {
        const int q   = tid >> 4;
        const int sub = tid & 15;
        float w0[4], w1[4], w2[4], bq[4];
        int   gi[4];
#pragma unroll
        for (int i = 0; i < 4; i++) {
            int o = 4 * q + i;
            w0[i] = wev_sh[o * 3 + 0]; w1[i] = wev_sh[o * 3 + 1];
            w2[i] = wev_sh[o * 3 + 2]; bq[i] = bev_sh[o];
            gi[i] = o / 3;
        }
#pragma unroll
        for (int j = 0; j < 4; j++) {
            int el = sub + 16 * j;
            if (el >= nE) continue;
            float e0v = ev_sh[el * 3 + 0], e1v = ev_sh[el * 3 + 1], e2v = ev_sh[el * 3 + 2];
            float4 v; float* vp = (float*)&v;
#pragma unroll
            for (int i = 0; i < 4; i++) {
                float val = fmaf(w0[i], e0v, fmaf(w1[i], e1v, fmaf(w2[i], e2v, bq[i])));
                vp[i] = val * gate_sh[el * 16 + gi[i]];
            }
            red4(g_agg + (size_t)dst_sh[el] * 176 + 128 + 4 * q, v);
        }
    }
}

// ---------------------------------------------------------------------------
// Node kernel (launch #4 -> ncu): persistent, 512 threads, tf32 mma.
// B fragments read from GLOBAL (__ldg, L2-resident) -> smem 86KB -> 2 blk/SM.
// ---------------------------------------------------------------------------
#define XPAD 132
#define NODE_SMEM_FLOATS 21472

__global__ __launch_bounds__(512) void node_kernel(
    const float* __restrict__ node_s, const float* __restrict__ node_v,
    const float* __restrict__ ln_g, const float* __restrict__ ln_b,
    const float* __restrict__ bns, const float* __restrict__ brs,
    const float* __restrict__ bnv, const float* __restrict__ brv,
    float* __restrict__ out, int Nn)
{
    extern __shared__ float smf[];
    float* wVT  = smf;                 // 4608
    float* xh   = wVT + 4608;          // 4224
    float* xl   = xh + 4224;           // 4224
    float* sh   = xl + 4224;           // 4224
    float* vn   = sh + 4224;           // 1536
    float* xv   = vn + 1536;           // 1536
    float* gate = xv + 1536;           // 512
    float* lng  = gate + 512;
    float* lnb  = lng + 128;
    float* bnsS = lnb + 128;
    float* brsS = bnsS + 128;
    float* bnvS = brsS + 128;
    float* brvS = bnvS + 48;

    const int tid  = threadIdx.x;
    const int lane = tid & 31;
    const int w    = tid >> 5;
    const int g    = lane >> 2;
    const int tig  = lane & 3;

    for (int i = tid; i < 4608; i += 512) wVT[i] = g_wVT[i];
    if (tid < 128) { lng[tid] = ln_g[tid]; lnb[tid] = ln_b[tid];
                     bnsS[tid] = bns[tid]; brsS[tid] = brs[tid]; }
    if (tid < 48)  { bnvS[tid] = bnv[tid]; brvS[tid] = brv[tid]; }

    const int mstrip = w >> 3;
    const int nstrip = w & 7;
    const int m0     = mstrip * 16;
    const bool wnsP  = (nstrip < 4);
    const float2* Bb = g_wB + (nstrip * 4) * 32 + lane;   // global, L2-resident

    const int ntiles = (Nn + 31) / 32;
    for (int tile = blockIdx.x; tile < ntiles; tile += gridDim.x) {
        const int n0t = tile * 32;
        const int nN  = min(32, Nn - n0t);
        __syncthreads();

        for (int i = tid; i < 4096; i += 512) {
            int r = i >> 7, c = i & 127;
            sh[r * XPAD + c] = (i < nN * 128) ? node_s[(size_t)n0t * 128 + i] : 0.f;
        }
        for (int i = tid; i < 1536; i += 512)
            vn[i] = (i < nN * 48) ? node_v[(size_t)n0t * 48 + i] : 0.f;
        __syncthreads();

        for (int q = 0; q < 2; q++) {
            int r = w * 2 + q;
            int n = n0t + r;
            const float* row = sh + r * XPAD;
            float a = row[lane] + row[lane + 32] + row[lane + 64] + row[lane + 96];
#pragma unroll
            for (int o = 16; o; o >>= 1) a += __shfl_xor_sync(0xffffffffu, a, o);
            float mu = a * (1.f / 128.f);
            float d0 = row[lane] - mu, d1 = row[lane + 32] - mu;
            float d2 = row[lane + 64] - mu, d3 = row[lane + 96] - mu;
            float vv = d0 * d0 + d1 * d1 + d2 * d2 + d3 * d3;
#pragma unroll
            for (int o = 16; o; o >>= 1) vv += __shfl_xor_sync(0xffffffffu, vv, o);
            float rs = rsqrtf(vv * (1.f / 128.f) + 1e-5f);

            const float* vrow = vn + r * 48;
            float x0 = vrow[lane];
            float x1 = (lane < 16) ? vrow[32 + lane] : 0.f;
            float sq = x0 * x0 + x1 * x1;
#pragma unroll
            for (int o = 16; o; o >>= 1) sq += __shfl_xor_sync(0xffffffffu, sq, o);
            float vr = rsqrtf(sq * (1.f / 16.f) + 1e-8f);

            float invden = 0.f;
            const float* aggr = g_agg + (size_t)n * 176;
            if (r < nN) invden = 1.f / fmaxf(g_cnt[n], 1.f);

#pragma unroll
            for (int jj = 0; jj < 4; jj++) {
                int c = lane + 32 * jj;
                float x = (row[c] - mu) * rs * lng[c] + lnb[c];
                float xa = x;
                if (r < nN) xa = x + aggr[c] * invden;
                float hf = tf32f(xa);
                sh[r * XPAD + c] = tf32f(x);
                xh[r * XPAD + c] = hf;
                xl[r * XPAD + c] = tf32f(xa - hf);
            }
            {
                float x = x0 * vr;
                float xa = x;
                if (r < nN) xa = x + aggr[128 + lane] * invden;
                vn[r * 48 + lane] = x;
                xv[r * 48 + lane] = xa;
                if (lane < 16) {
                    float y = x1 * vr;
                    float ya = y;
                    if (r < nN) ya = y + aggr[128 + 32 + lane] * invden;
                    vn[r * 48 + 32 + lane] = y;
                    xv[r * 48 + 32 + lane] = ya;
                }
            }
        }
        __syncthreads();

        float acc[4][4];
#pragma unroll
        for (int nt = 0; nt < 4; nt++)
#pragma unroll
            for (int i = 0; i < 4; i++) acc[nt][i] = 0.f;

        {
            const int arow = (m0 + g) * XPAD + tig;
#pragma unroll 4
            for (int kt = 0; kt < 16; kt++) {
                const int ko = kt * 8;
                // prefetch B frags (global, L2 hit) ahead of A LDS
                float2 bv[4];
#pragma unroll
                for (int nt = 0; nt < 4; nt++) bv[nt] = __ldg(&Bb[kt * 1024 + nt * 32]);
                unsigned a0[4], a1[4];
                if (wnsP) {
                    a0[0] = __float_as_uint(xh[arow + ko]);
                    a0[1] = __float_as_uint(xh[arow + 8 * XPAD + ko]);
                    a0[2] = __float_as_uint(xh[arow + ko + 4]);
                    a0[3] = __float_as_uint(xh[arow + 8 * XPAD + ko + 4]);
                    a1[0] = __float_as_uint(xl[arow + ko]);
                    a1[1] = __float_as_uint(xl[arow + 8 * XPAD + ko]);
                    a1[2] = __float_as_uint(xl[arow + ko + 4]);
                    a1[3] = __float_as_uint(xl[arow + 8 * XPAD + ko + 4]);
                } else {
                    a0[0] = __float_as_uint(sh[arow + ko]);
                    a0[1] = __float_as_uint(sh[arow + 8 * XPAD + ko]);
                    a0[2] = __float_as_uint(sh[arow + ko + 4]);
                    a0[3] = __float_as_uint(sh[arow + 8 * XPAD + ko + 4]);
                }
#pragma unroll
                for (int nt = 0; nt < 4; nt++) {
                    unsigned b[2] = { __float_as_uint(bv[nt].x), __float_as_uint(bv[nt].y) };
                    mma_tf32(acc[nt], a0, b);
                    if (wnsP) mma_tf32(acc[nt], a1, b);
                }
            }
        }
        __syncthreads();

        {
            const int r0 = m0 + g, r1 = m0 + 8 + g;
#pragma unroll
            for (int nt = 0; nt < 4; nt++) {
                int o = nstrip * 32 + nt * 8 + tig * 2;
                if (wnsP) {
                    float b0v = bnsS[o], b1v = bnsS[o + 1];
                    float v0 = acc[nt][0] + b0v, v1 = acc[nt][1] + b1v;
                    float v2 = acc[nt][2] + b0v, v3 = acc[nt][3] + b1v;
                    v0 *= sigf(v0); v1 *= sigf(v1); v2 *= sigf(v2); v3 *= sigf(v3);
                    xh[r0 * XPAD + o]     = v0;
                    xh[r0 * XPAD + o + 1] = v1;
                    xh[r1 * XPAD + o]     = v2;
                    xh[r1 * XPAD + o + 1] = v3;
                    if (o < 16) {
                        gate[r0 * 16 + o]     = sigf(v0);
                        gate[r0 * 16 + o + 1] = sigf(v1);
                        gate[r1 * 16 + o]     = sigf(v2);
                        gate[r1 * 16 + o + 1] = sigf(v3);
                    }
                } else {
                    int oc = o - 128;
                    float b0v = brsS[oc], b1v = brsS[oc + 1];
                    xl[r0 * XPAD + oc]     = acc[nt][0] + b0v;
                    xl[r0 * XPAD + oc + 1] = acc[nt][1] + b1v;
                    xl[r1 * XPAD + oc]     = acc[nt][2] + b0v;
                    xl[r1 * XPAD + oc + 1] = acc[nt][3] + b1v;
                }
            }
        }
        __syncthreads();

        for (int i = tid; i < nN * 128; i += 512) {
            int r = i >> 7, c = i & 127;
            out[(size_t)n0t * 128 + i] = xh[r * XPAD + c] + xl[r * XPAD + c];
        }

        for (int p = tid; p < nN * 48; p += 512) {
            int r = p / 48, o = p % 48;
            const float* xvr = xv + r * 48;
            const float* vnr = vn + r * 48;
            float a = 0.f, bq = 0.f;
#pragma unroll 4
            for (int k = 0; k < 48; k++) {
                a  = fmaf(xvr[k], wVT[k * 96 + o],      a);
                bq = fmaf(vnr[k], wVT[k * 96 + 48 + o], bq);
            }
            float val = (a + bnvS[o]) * gate[r * 16 + o / 3] + bq + brvS[o];
            out[(size_t)Nn * 128 + (size_t)n0t * 48 + p] = val;
        }
    }
}

// ---------------------------------------------------------------------------
extern "C" void kernel_launch(void* const* d_in, const int* in_sizes, int n_in,
                              void* d_out, int out_size)
{
    const float* node_s = (const float*)d_in[0];
    const float* node_v = (const float*)d_in[1];
    const int*   ei     = (const int*)  d_in[2];
    const float* edge_s = (const float*)d_in[3];
    const float* edge_v = (const float*)d_in[4];
    const float* ln_g   = (const float*)d_in[5];
    const float* ln_b   = (const float*)d_in[6];
    const float* wes    = (const float*)d_in[7];
    const float* bes    = (const float*)d_in[8];
    const float* wev    = (const float*)d_in[9];
    const float* bev    = (const float*)d_in[10];
    const float* wns    = (const float*)d_in[11];
    const float* bns    = (const float*)d_in[12];
    const float* wnv    = (const float*)d_in[13];
    const float* bnv    = (const float*)d_in[14];
    const float* wrs    = (const float*)d_in[15];
    const float* brs    = (const float*)d_in[16];
    const float* wrv    = (const float*)d_in[17];
    const float* brv    = (const float*)d_in[18];

    const int N = in_sizes[0] / 128;
    const int E = in_sizes[3] / 32;

    cudaFuncSetAttribute(node_kernel, cudaFuncAttributeMaxDynamicSharedMemorySize,
                         NODE_SMEM_FLOATS * sizeof(float));

    prep_kernel<<<(N + 255) / 256, 256>>>(wes, wns, wrs, wnv, wrv, N);  // #1 (+cnt zero)
    zero_agg_kernel<<<(N * 44 + 255) / 256, 256>>>(N);                  // #2
    edge_kernel<<<(E + TE - 1) / TE, 256>>>(edge_s, edge_v, ei,         // #3
                                            bes, wev, bev, E);
    node_kernel<<<304, 512, NODE_SMEM_FLOATS * sizeof(float)>>>(        // #4 (ncu)
        node_s, node_v, ln_g, ln_b, bns, brs, bnv, brv, (float*)d_out, N);
}